// round 1
// baseline (speedup 1.0000x reference)
#include <cuda_runtime.h>
#include <cstdint>
#include <cstddef>

// ---------------- problem constants ----------------
#define NAT 131072      // atoms
#define NBO 262144      // bonds
#define NMO 4096        // molecules
#define DVV 72          // atom feat
#define DEE 14          // bond feat
#define DHH 300         // hidden
#define DHP 320         // padded hidden
#define DEM 256         // emb

// ---------------- scratch (device globals; no allocation) ----------------
__device__ float g_H0[(size_t)NBO * DHP];
__device__ float g_Ha[(size_t)NBO * DHP];
__device__ float g_Hb[(size_t)NBO * DHP];
__device__ float g_Mv[(size_t)NAT * DHP];
__device__ float g_Hv[(size_t)NAT * DHP];
__device__ float g_Z [(size_t)NMO * DHP];
__device__ float g_cnt[NMO];
__device__ float g_T [(size_t)NMO * DEM];
__device__ float g_Wi[(size_t)86  * DHP];
__device__ float g_Wh[(size_t)DHP * DHP];
__device__ float g_Wo[(size_t)392 * DHP];
__device__ float g_bo[DHP];
__device__ float g_W1[(size_t)DHP * DEM];

// ---------------- packed fp32x2 FMA (sm_10x) ----------------
__device__ __forceinline__ void fma2(unsigned long long &d,
                                     unsigned long long a,
                                     unsigned long long b) {
    asm("fma.rn.f32x2 %0, %1, %2, %0;" : "+l"(d) : "l"(a), "l"(b));
}

// ---------------- weight padding ----------------
__global__ void pad_k(const float* __restrict__ in, float* __restrict__ out,
                      int IR, int IC, int OR, int OC) {
    int idx = blockIdx.x * blockDim.x + threadIdx.x;
    if (idx >= OR * OC) return;
    int r = idx / OC, c = idx - r * OC;
    out[idx] = (r < IR && c < IC) ? in[r * IC + c] : 0.f;
}

// ---------------- GEMM ----------------
// C[M,N] = A[M,K] @ B[K,N]  (B row-major, ldb = N)
// AMODE: 0 plain A1 (lda1)
//        1 concat-gather: k<K1 ? A1[idx1[r]*lda1+k] : A2[r*lda2+(k-K1)]   (H0)
//        2 message:       A1[idx1[r]*lda1+k] - A2[idx2[r]*lda2+k]          (Mv[src]-H[rev])
//        3 concat-plain:  k<K1 ? A1[r*lda1+k] : A2[r*lda2+(k-K1)]          (V | Mv)
// EPI:   0 C=acc ; 1 C=relu(acc+aux[c]) ; 2 C=relu(acc+aux[r*N+c]) ;
//        3 C=acc, C2=relu(acc) ; 4 C=acc+aux[c]
// Tiles: BM=128, BN=160, BK=8, 256 threads, per-thread 8x10 via f32x2.
// Requires M % 128 == 0 (true for all call sites).
template<int AMODE, int EPI>
__global__ void __launch_bounds__(256)
gemm_k(const float* __restrict__ A1, const float* __restrict__ A2,
       const int* __restrict__ idx1, const int* __restrict__ idx2,
       int K1, int lda1, int lda2,
       const float* __restrict__ B,
       const float* __restrict__ aux,
       float* __restrict__ C, float* __restrict__ C2,
       int M, int N, int K) {
    __shared__ __align__(16) float2 As[8][128];   // duplicated A values
    __shared__ __align__(16) float  Bs[8][160];

    const int tid = threadIdx.x;
    const int bm = blockIdx.y * 128;
    const int bn = blockIdx.x * 160;

    // A load mapping: one row per thread-pair, 4 k's each
    const int a_row = tid >> 1;
    const int a_k0  = (tid & 1) * 4;
    const int grow  = bm + a_row;                 // always < M
    int gi1 = 0, gi2 = 0;
    if (AMODE == 1 || AMODE == 2) gi1 = idx1[grow];
    if (AMODE == 2)               gi2 = idx2[grow];

    const int ty = tid >> 4;   // 0..15 -> rows ty*8..+7
    const int tx = tid & 15;   // 0..15 -> cols tx*10..+9 (5 pairs)

    unsigned long long acc[8][5];
#pragma unroll
    for (int i = 0; i < 8; i++)
#pragma unroll
        for (int j = 0; j < 5; j++) acc[i][j] = 0ull;

    for (int k0 = 0; k0 < K; k0 += 8) {
        // ---- load A tile (duplicated for f32x2) ----
#pragma unroll
        for (int j = 0; j < 4; j++) {
            int kk = a_k0 + j;
            int gk = k0 + kk;
            float v = 0.f;
            if (gk < K) {
                if (AMODE == 0)      v = A1[(size_t)grow * lda1 + gk];
                else if (AMODE == 1) v = (gk < K1) ? A1[(size_t)gi1 * lda1 + gk]
                                                   : A2[(size_t)grow * lda2 + (gk - K1)];
                else if (AMODE == 2) v = A1[(size_t)gi1 * lda1 + gk]
                                       - A2[(size_t)gi2 * lda2 + gk];
                else                 v = (gk < K1) ? A1[(size_t)grow * lda1 + gk]
                                                   : A2[(size_t)grow * lda2 + (gk - K1)];
            }
            As[kk][a_row] = make_float2(v, v);
        }
        // ---- load B tile: 1280 elems, 5 per thread ----
#pragma unroll
        for (int j = 0; j < 5; j++) {
            int l   = tid + j * 256;
            int kk  = l / 160;
            int col = l - kk * 160;
            int gk = k0 + kk, gn = bn + col;
            Bs[kk][col] = (gk < K && gn < N) ? B[(size_t)gk * N + gn] : 0.f;
        }
        __syncthreads();

#pragma unroll
        for (int kk = 0; kk < 8; kk++) {
            unsigned long long a[8], b[5];
            const unsigned long long* ap =
                reinterpret_cast<const unsigned long long*>(&As[kk][ty * 8]);
#pragma unroll
            for (int i = 0; i < 8; i++) a[i] = ap[i];
            const unsigned long long* bp =
                reinterpret_cast<const unsigned long long*>(&Bs[kk][tx * 10]);
#pragma unroll
            for (int j = 0; j < 5; j++) b[j] = bp[j];
#pragma unroll
            for (int i = 0; i < 8; i++)
#pragma unroll
                for (int j = 0; j < 5; j++) fma2(acc[i][j], a[i], b[j]);
        }
        __syncthreads();
    }

    // ---- epilogue ----
#pragma unroll
    for (int i = 0; i < 8; i++) {
        int r = bm + ty * 8 + i;
        if (r >= M) continue;
#pragma unroll
        for (int j = 0; j < 5; j++) {
            float2 v2 = *reinterpret_cast<float2*>(&acc[i][j]);
            float vv[2] = {v2.x, v2.y};
#pragma unroll
            for (int h = 0; h < 2; h++) {
                int c = bn + tx * 10 + 2 * j + h;
                if (c >= N) continue;
                size_t o = (size_t)r * N + c;
                float v = vv[h];
                if (EPI == 0)      C[o] = v;
                else if (EPI == 1) C[o] = fmaxf(v + aux[c], 0.f);
                else if (EPI == 2) C[o] = fmaxf(v + aux[o], 0.f);
                else if (EPI == 3) { C[o] = v; C2[o] = fmaxf(v, 0.f); }
                else if (EPI == 4) C[o] = v + aux[c];
            }
        }
    }
}

// ---------------- scatter / pool / misc ----------------
__global__ void scatter_k(const float* __restrict__ H, const int* __restrict__ dst,
                          float* __restrict__ Mv) {
    long long idx = (long long)blockIdx.x * blockDim.x + threadIdx.x;
    if (idx >= (long long)NBO * DHP) return;
    int b = (int)(idx / DHP);
    int f = (int)(idx - (long long)b * DHP);
    float v = H[idx];
    if (v != 0.f) atomicAdd(&Mv[(size_t)dst[b] * DHP + f], v);
}

__global__ void pool_k(const float* __restrict__ Hv, const int* __restrict__ batch,
                       float* __restrict__ Z) {
    long long idx = (long long)blockIdx.x * blockDim.x + threadIdx.x;
    if (idx >= (long long)NAT * DHP) return;
    int a = (int)(idx / DHP);
    int f = (int)(idx - (long long)a * DHP);
    float v = Hv[idx];
    if (v != 0.f) atomicAdd(&Z[(size_t)batch[a] * DHP + f], v);
}

__global__ void count_k(const int* __restrict__ batch, float* __restrict__ cnt) {
    int a = blockIdx.x * blockDim.x + threadIdx.x;
    if (a < NAT) atomicAdd(&cnt[batch[a]], 1.f);
}

__global__ void div_k(float* __restrict__ Z, const float* __restrict__ cnt) {
    int idx = blockIdx.x * blockDim.x + threadIdx.x;
    if (idx >= NMO * DHP) return;
    int m = idx / DHP;
    Z[idx] = Z[idx] / fmaxf(cnt[m], 1.f);
}

// ---------------- launcher ----------------
extern "C" void kernel_launch(void* const* d_in, const int* in_sizes, int n_in,
                              void* d_out, int out_size) {
    const float* V    = (const float*)d_in[0];
    const float* E    = (const float*)d_in[1];
    const int*   esrc = (const int*)d_in[2];
    const int*   edst = (const int*)d_in[3];
    const int*   rev  = (const int*)d_in[4];
    const int*   batc = (const int*)d_in[5];
    int wi = 6;
    if (n_in >= 15 && in_sizes[6] == 1) wi = 7;   // n_mols scalar present
    const float* W_i = (const float*)d_in[wi + 0];
    const float* W_h = (const float*)d_in[wi + 1];
    const float* W_o = (const float*)d_in[wi + 2];
    const float* b_o = (const float*)d_in[wi + 3];
    const float* W1  = (const float*)d_in[wi + 4];
    const float* b1  = (const float*)d_in[wi + 5];
    const float* W2  = (const float*)d_in[wi + 6];
    const float* b2  = (const float*)d_in[wi + 7];
    float* out = (float*)d_out;

    float *H0, *Ha, *Hb, *Mv, *Hv, *Z, *cnt, *T, *Wi, *Wh, *Wo, *bo, *W1p;
    cudaGetSymbolAddress((void**)&H0,  g_H0);
    cudaGetSymbolAddress((void**)&Ha,  g_Ha);
    cudaGetSymbolAddress((void**)&Hb,  g_Hb);
    cudaGetSymbolAddress((void**)&Mv,  g_Mv);
    cudaGetSymbolAddress((void**)&Hv,  g_Hv);
    cudaGetSymbolAddress((void**)&Z,   g_Z);
    cudaGetSymbolAddress((void**)&cnt, g_cnt);
    cudaGetSymbolAddress((void**)&T,   g_T);
    cudaGetSymbolAddress((void**)&Wi,  g_Wi);
    cudaGetSymbolAddress((void**)&Wh,  g_Wh);
    cudaGetSymbolAddress((void**)&Wo,  g_Wo);
    cudaGetSymbolAddress((void**)&bo,  g_bo);
    cudaGetSymbolAddress((void**)&W1p, g_W1);

    // pad weights to DHP
    pad_k<<<(86  * DHP + 255) / 256, 256>>>(W_i, Wi, 86,  300, 86,  DHP);
    pad_k<<<(DHP * DHP + 255) / 256, 256>>>(W_h, Wh, 300, 300, DHP, DHP);
    pad_k<<<(392 * DHP + 255) / 256, 256>>>(W_o, Wo, 372, 300, 392, DHP);
    pad_k<<<(DHP + 255) / 256, 256>>>(b_o, bo, 1, 300, 1, DHP);
    pad_k<<<(DHP * DEM + 255) / 256, 256>>>(W1, W1p, 300, 256, DHP, DEM);

    const long long bondsElems = (long long)NBO * DHP;
    const long long atomElems  = (long long)NAT * DHP;
    const int SCT = (int)((bondsElems + 255) / 256);
    const int PLT = (int)((atomElems + 255) / 256);

    // 1. H0 = concat(V[src], E) @ W_i ; Ha = relu(H0)
    {
        dim3 g(DHP / 160, NBO / 128);
        gemm_k<1, 3><<<g, 256>>>(V, E, esrc, nullptr, 72, DVV, DEE,
                                 Wi, nullptr, H0, Ha, NBO, DHP, 86);
    }

    // 2. two message-passing iterations (H: Ha -> Hb -> Ha)
    float* Hc = Ha; float* Hn = Hb;
    for (int it = 0; it < 2; it++) {
        cudaMemsetAsync(Mv, 0, (size_t)NAT * DHP * sizeof(float));
        scatter_k<<<SCT, 256>>>(Hc, edst, Mv);
        dim3 g(DHP / 160, NBO / 128);
        gemm_k<2, 2><<<g, 256>>>(Mv, Hc, esrc, rev, 0, DHP, DHP,
                                 Wh, H0, Hn, nullptr, NBO, DHP, DHP);
        float* t = Hc; Hc = Hn; Hn = t;
    }

    // 3. final segment sum
    cudaMemsetAsync(Mv, 0, (size_t)NAT * DHP * sizeof(float));
    scatter_k<<<SCT, 256>>>(Hc, edst, Mv);

    // 4. Hv = relu(concat(V, Mv) @ W_o + b_o)
    {
        dim3 g(DHP / 160, NAT / 128);
        gemm_k<3, 1><<<g, 256>>>(V, Mv, nullptr, nullptr, 72, DVV, DHP,
                                 Wo, bo, Hv, nullptr, NAT, DHP, 392);
    }

    // 5. mean pool
    cudaMemsetAsync(Z, 0, (size_t)NMO * DHP * sizeof(float));
    cudaMemsetAsync(cnt, 0, (size_t)NMO * sizeof(float));
    pool_k<<<PLT, 256>>>(Hv, batc, Z);
    count_k<<<(NAT + 255) / 256, 256>>>(batc, cnt);
    div_k<<<(NMO * DHP + 255) / 256, 256>>>(Z, cnt);

    // 6. T = relu(Z @ W1 + b1)
    {
        dim3 g((DEM + 159) / 160, NMO / 128);
        gemm_k<0, 1><<<g, 256>>>(Z, nullptr, nullptr, nullptr, 0, DHP, 0,
                                 W1p, b1, T, nullptr, NMO, DEM, DHP);
    }
    // 7. out = T @ W2 + b2
    {
        dim3 g((DEM + 159) / 160, NMO / 128);
        gemm_k<0, 4><<<g, 256>>>(T, nullptr, nullptr, nullptr, 0, DEM, 0,
                                 W2, b2, out, nullptr, NMO, DEM, DEM);
    }
}

// round 5
// speedup vs baseline: 2.0379x; 2.0379x over previous
#include <cuda_runtime.h>
#include <cuda_bf16.h>
#include <cstdint>
#include <cstddef>

#define NAT 131072
#define NBO 262144
#define NMO 4096
#define DHP 320
#define DEM 256

// ---------------- scratch (device globals; no allocation) ----------------
__device__ float g_H0[(size_t)NBO * DHP];
__device__ float g_Ha[(size_t)NBO * DHP];
__device__ float g_Hb[(size_t)NBO * DHP];
__device__ float g_Mv[(size_t)NAT * DHP];
__device__ float g_Hv[(size_t)NAT * DHP];
__device__ float g_Z [(size_t)NMO * DHP];
__device__ float g_cnt[NMO];
__device__ float g_T [(size_t)NMO * DEM];
__device__ float g_bo[DHP];
__device__ __align__(16) __nv_bfloat16 g_As[(size_t)NBO * 640];
__device__ __align__(16) __nv_bfloat16 g_Bh0[320 * 256];
__device__ __align__(16) __nv_bfloat16 g_Bh [320 * 640];
__device__ __align__(16) __nv_bfloat16 g_Bo [320 * 768];
__device__ __align__(16) __nv_bfloat16 g_B1 [256 * 640];
__device__ __align__(16) __nv_bfloat16 g_B2 [256 * 512];

// ---------------- PTX helpers (base sm_100 ISA only) ----------------
__device__ __forceinline__ uint32_t smem_u32(const void* p) {
    uint32_t a;
    asm("{ .reg .u64 t; cvta.to.shared.u64 t, %1; cvt.u32.u64 %0, t; }"
        : "=r"(a) : "l"(p));
    return a;
}
__device__ __forceinline__ void cpa16(uint32_t dst, const void* src) {
    asm volatile("cp.async.cg.shared.global [%0], [%1], 16;"
                 :: "r"(dst), "l"(src) : "memory");
}
__device__ __forceinline__ void cp_commit() {
    asm volatile("cp.async.commit_group;" ::: "memory");
}
template<int N>
__device__ __forceinline__ void cp_wait() {
    asm volatile("cp.async.wait_group %0;" :: "n"(N) : "memory");
}
__device__ __forceinline__ void ldsm4(uint32_t* r, uint32_t a) {
    asm volatile("ldmatrix.sync.aligned.m8n8.x4.shared.b16 {%0,%1,%2,%3}, [%4];"
                 : "=r"(r[0]), "=r"(r[1]), "=r"(r[2]), "=r"(r[3]) : "r"(a));
}
__device__ __forceinline__ void ldsm2(uint32_t* r, uint32_t a) {
    asm volatile("ldmatrix.sync.aligned.m8n8.x2.shared.b16 {%0,%1}, [%2];"
                 : "=r"(r[0]), "=r"(r[1]) : "r"(a));
}
__device__ __forceinline__ void mma16816(float* c, const uint32_t* a, const uint32_t* b) {
    asm volatile(
        "mma.sync.aligned.m16n8k16.row.col.f32.bf16.bf16.f32 "
        "{%0,%1,%2,%3}, {%4,%5,%6,%7}, {%8,%9}, {%0,%1,%2,%3};"
        : "+f"(c[0]), "+f"(c[1]), "+f"(c[2]), "+f"(c[3])
        : "r"(a[0]), "r"(a[1]), "r"(a[2]), "r"(a[3]), "r"(b[0]), "r"(b[1]));
}

// ---------------- split helpers ----------------
__device__ __forceinline__ void wsplit(__nv_bfloat16* out, size_t base, int KP,
                                       int kp, float a, float b) {
    __nv_bfloat16 ha = __float2bfloat16(a), hb = __float2bfloat16(b);
    __nv_bfloat162 hp; hp.x = ha; hp.y = hb;
    *(uint32_t*)(out + base + kp) = *(uint32_t*)&hp;
    __nv_bfloat162 lp = __floats2bfloat162_rn(a - __bfloat162float(ha),
                                              b - __bfloat162float(hb));
    *(uint32_t*)(out + base + KP + kp) = *(uint32_t*)&lp;
}

// ---------------- prep kernels ----------------
__global__ void prep_bt_k(const float* __restrict__ W, __nv_bfloat16* __restrict__ out,
                          int Ksrc, int Nsrc, int KP, int Nrows) {
    int idx = blockIdx.x * 256 + threadIdx.x;
    if (idx >= Nrows * KP) return;
    int n = idx / KP, k = idx - n * KP;
    float v = (k < Ksrc && n < Nsrc) ? W[(size_t)k * Nsrc + n] : 0.f;
    __nv_bfloat16 hi = __float2bfloat16(v);
    size_t base = (size_t)n * (2 * KP);
    out[base + k] = hi;
    out[base + KP + k] = __float2bfloat16(v - __bfloat162float(hi));
}

__global__ void prep_h0a_k(const float* __restrict__ V, const float* __restrict__ E,
                           const int* __restrict__ esrc, __nv_bfloat16* __restrict__ out) {
    int idx = blockIdx.x * 256 + threadIdx.x;
    if (idx >= NBO * 64) return;
    int r = idx >> 6, kp = (idx & 63) << 1;
    int s = esrc[r];
    int k1 = kp + 1;
    float v0 = (kp < 72) ? V[(size_t)s * 72 + kp]
                         : (kp < 86 ? E[(size_t)r * 14 + kp - 72] : 0.f);
    float v1 = (k1 < 72) ? V[(size_t)s * 72 + k1]
                         : (k1 < 86 ? E[(size_t)r * 14 + k1 - 72] : 0.f);
    wsplit(out, (size_t)r * 256, 128, kp, v0, v1);
}

__global__ void prep_msga_k(const float* __restrict__ Mv, const float* __restrict__ H,
                            const int* __restrict__ esrc, const int* __restrict__ rev,
                            __nv_bfloat16* __restrict__ out) {
    long long idx = (long long)blockIdx.x * 256 + threadIdx.x;
    if (idx >= (long long)NBO * 160) return;
    int r = (int)(idx / 160);
    int kp = ((int)(idx - (long long)r * 160)) << 1;
    int s = esrc[r], rv = rev[r];
    float2 m = *(const float2*)(Mv + (size_t)s  * DHP + kp);
    float2 h = *(const float2*)(H  + (size_t)rv * DHP + kp);
    wsplit(out, (size_t)r * 640, 320, kp, m.x - h.x, m.y - h.y);
}

__global__ void prep_woa_k(const float* __restrict__ V, const float* __restrict__ Mv,
                           __nv_bfloat16* __restrict__ out) {
    long long idx = (long long)blockIdx.x * 256 + threadIdx.x;
    if (idx >= (long long)NAT * 192) return;
    int a = (int)(idx / 192);
    int kp = ((int)(idx - (long long)a * 192)) << 1;
    int k1 = kp + 1;
    float v0 = (kp < 72) ? V[(size_t)a * 72 + kp]
                         : (kp < 372 ? Mv[(size_t)a * DHP + kp - 72] : 0.f);
    float v1 = (k1 < 72) ? V[(size_t)a * 72 + k1]
                         : (k1 < 372 ? Mv[(size_t)a * DHP + k1 - 72] : 0.f);
    wsplit(out, (size_t)a * 768, 384, kp, v0, v1);
}

__global__ void prep_pa_k(const float* __restrict__ X, __nv_bfloat16* __restrict__ out,
                          int rows, int KP) {
    int hk = KP >> 1;
    int idx = blockIdx.x * 256 + threadIdx.x;
    if (idx >= rows * hk) return;
    int r = idx / hk, kp = (idx - r * hk) << 1;
    float2 v = *(const float2*)(X + (size_t)r * KP + kp);
    wsplit(out, (size_t)r * (2 * KP), KP, kp, v.x, v.y);
}

__global__ void pad_k(const float* __restrict__ in, float* __restrict__ out,
                      int IR, int IC, int OR, int OC) {
    int idx = blockIdx.x * blockDim.x + threadIdx.x;
    if (idx >= OR * OC) return;
    int r = idx / OC, c = idx - r * OC;
    out[idx] = (r < IR && c < IC) ? in[r * IC + c] : 0.f;
}

// ---------------- warp-MMA GEMM (split-bf16 triple-K) ----------------
// C[M,N] = A @ Bt^T. A: [M][2*KP] (hi|lo), Bt: [N][2*KP] (hi|lo).
// BM=128, BK=32, 8 warps (2x4), warp tile 64 x (BN/4).
// EPI: 1 relu(acc+aux[c]) ; 2 relu(acc+aux[r*N+c]) ; 3 C=acc,C2=relu(acc) ; 4 acc+aux[c]
template<int EPI, int BN>
__global__ void __launch_bounds__(256, 1)
gemm_mma(const __nv_bfloat16* __restrict__ A, int lda, int KP,
         const __nv_bfloat16* __restrict__ Bt, int ldb,
         const float* __restrict__ aux,
         float* __restrict__ C, float* __restrict__ C2, int N) {
    constexpr int NT = BN / 32;        // n-tiles (8 cols) per warp
    constexpr int RS = 80;             // padded smem row stride in bytes
    constexpr int ASTG = 128 * RS;
    constexpr int BSTG = BN * RS;
    constexpr int STG = ASTG + BSTG;
    extern __shared__ __align__(16) char sm[];
    const uint32_t sbase = smem_u32(sm);

    const int tid = threadIdx.x;
    const int wid = tid >> 5, lane = tid & 31;
    const int wm = wid & 1, wn = wid >> 1;
    const long long bm = (long long)blockIdx.y * 128;
    const int bn = blockIdx.x * BN;

    const int segC = KP >> 5;
    const int nC = 3 * segC;

    float acc[4][NT][4];
#pragma unroll
    for (int i = 0; i < 4; i++)
#pragma unroll
        for (int j = 0; j < NT; j++)
#pragma unroll
            for (int t = 0; t < 4; t++) acc[i][j][t] = 0.f;

    // ldmatrix lane address components
    const int aRow = (lane & 7) + ((lane >> 3) & 1) * 8;
    const int aK   = (lane >> 4) * 8;
    const int bRow = lane & 7;
    const int bK   = ((lane >> 3) & 1) * 8;

    auto load_chunk = [&](int c) {
        const int buf = c & 1;
        const int seg = c / segC, w = c - seg * segC;
        const int aoff = (seg == 1 ? KP : 0) + w * 32;   // A: [hi|lo|hi]
        const int boff = (seg == 2 ? KP : 0) + w * 32;   // B: [hi|hi|lo]
        const uint32_t as = sbase + buf * STG;
        const uint32_t bs = as + ASTG;
#pragma unroll
        for (int it = 0; it < 2; ++it) {
            int idx = tid + it * 256;
            int row = idx >> 2, sg = idx & 3;
            cpa16(as + row * RS + sg * 16,
                  A + (bm + row) * (long long)lda + aoff + sg * 8);
        }
        for (int idx = tid; idx < BN * 4; idx += 256) {
            int row = idx >> 2, sg = idx & 3;
            cpa16(bs + row * RS + sg * 16,
                  Bt + (long long)(bn + row) * ldb + boff + sg * 8);
        }
        cp_commit();
    };

    load_chunk(0);
    for (int c = 0; c < nC; ++c) {
        if (c + 1 < nC) { load_chunk(c + 1); cp_wait<1>(); }
        else            { cp_wait<0>(); }
        __syncthreads();
        const uint32_t as = sbase + (c & 1) * STG;
        const uint32_t bs = as + ASTG;
#pragma unroll
        for (int ks = 0; ks < 32; ks += 16) {
            uint32_t af[4][4], bf[NT][2];
#pragma unroll
            for (int mt = 0; mt < 4; ++mt)
                ldsm4(af[mt], as + (wm * 64 + mt * 16 + aRow) * RS + (ks + aK) * 2);
#pragma unroll
            for (int nt = 0; nt < NT; ++nt)
                ldsm2(bf[nt], bs + (wn * NT * 8 + nt * 8 + bRow) * RS + (ks + bK) * 2);
#pragma unroll
            for (int mt = 0; mt < 4; ++mt)
#pragma unroll
                for (int nt = 0; nt < NT; ++nt)
                    mma16816(acc[mt][nt], af[mt], bf[nt]);
        }
        __syncthreads();
    }

    // ---- epilogue ----
    const int gid = lane >> 2, tig = lane & 3;
#pragma unroll
    for (int mt = 0; mt < 4; ++mt) {
        const long long r0 = bm + wm * 64 + mt * 16 + gid;
        const long long r1 = r0 + 8;
#pragma unroll
        for (int nt = 0; nt < NT; ++nt) {
            const int c0 = bn + wn * NT * 8 + nt * 8 + tig * 2;
            float v00 = acc[mt][nt][0], v01 = acc[mt][nt][1];
            float v10 = acc[mt][nt][2], v11 = acc[mt][nt][3];
            if (EPI == 1 || EPI == 4) {
                float2 ax = *(const float2*)(aux + c0);
                v00 += ax.x; v01 += ax.y; v10 += ax.x; v11 += ax.y;
                if (EPI == 1) {
                    v00 = fmaxf(v00, 0.f); v01 = fmaxf(v01, 0.f);
                    v10 = fmaxf(v10, 0.f); v11 = fmaxf(v11, 0.f);
                }
            } else if (EPI == 2) {
                float2 a0 = *(const float2*)(aux + r0 * N + c0);
                float2 a1 = *(const float2*)(aux + r1 * N + c0);
                v00 = fmaxf(v00 + a0.x, 0.f); v01 = fmaxf(v01 + a0.y, 0.f);
                v10 = fmaxf(v10 + a1.x, 0.f); v11 = fmaxf(v11 + a1.y, 0.f);
            } else if (EPI == 3) {
                *(float2*)(C2 + r0 * N + c0) =
                    make_float2(fmaxf(v00, 0.f), fmaxf(v01, 0.f));
                *(float2*)(C2 + r1 * N + c0) =
                    make_float2(fmaxf(v10, 0.f), fmaxf(v11, 0.f));
            }
            *(float2*)(C + r0 * N + c0) = make_float2(v00, v01);
            *(float2*)(C + r1 * N + c0) = make_float2(v10, v11);
        }
    }
}

// ---------------- scatter / pool / misc (fp32) ----------------
__global__ void scatter_k(const float* __restrict__ H, const int* __restrict__ dst,
                          float* __restrict__ Mv) {
    long long idx = (long long)blockIdx.x * blockDim.x + threadIdx.x;
    if (idx >= (long long)NBO * DHP) return;
    int b = (int)(idx / DHP);
    int f = (int)(idx - (long long)b * DHP);
    float v = H[idx];
    if (v != 0.f) atomicAdd(&Mv[(size_t)dst[b] * DHP + f], v);
}
__global__ void pool_k(const float* __restrict__ Hv, const int* __restrict__ batch,
                       float* __restrict__ Z) {
    long long idx = (long long)blockIdx.x * blockDim.x + threadIdx.x;
    if (idx >= (long long)NAT * DHP) return;
    int a = (int)(idx / DHP);
    int f = (int)(idx - (long long)a * DHP);
    float v = Hv[idx];
    if (v != 0.f) atomicAdd(&Z[(size_t)batch[a] * DHP + f], v);
}
__global__ void count_k(const int* __restrict__ batch, float* __restrict__ cnt) {
    int a = blockIdx.x * blockDim.x + threadIdx.x;
    if (a < NAT) atomicAdd(&cnt[batch[a]], 1.f);
}
__global__ void div_k(float* __restrict__ Z, const float* __restrict__ cnt) {
    int idx = blockIdx.x * blockDim.x + threadIdx.x;
    if (idx >= NMO * DHP) return;
    int m = idx / DHP;
    Z[idx] = Z[idx] / fmaxf(cnt[m], 1.f);
}

// ---------------- launcher ----------------
extern "C" void kernel_launch(void* const* d_in, const int* in_sizes, int n_in,
                              void* d_out, int out_size) {
    const float* V    = (const float*)d_in[0];
    const float* E    = (const float*)d_in[1];
    const int*   esrc = (const int*)d_in[2];
    const int*   edst = (const int*)d_in[3];
    const int*   rev  = (const int*)d_in[4];
    const int*   batc = (const int*)d_in[5];
    int wi = 6;
    if (n_in >= 15 && in_sizes[6] == 1) wi = 7;
    const float* W_i = (const float*)d_in[wi + 0];
    const float* W_h = (const float*)d_in[wi + 1];
    const float* W_o = (const float*)d_in[wi + 2];
    const float* b_o = (const float*)d_in[wi + 3];
    const float* W1  = (const float*)d_in[wi + 4];
    const float* b1  = (const float*)d_in[wi + 5];
    const float* W2  = (const float*)d_in[wi + 6];
    const float* b2  = (const float*)d_in[wi + 7];
    float* out = (float*)d_out;

    float *H0, *Ha, *Hb, *Mv, *Hv, *Z, *cnt, *T, *bo;
    __nv_bfloat16 *As, *Bh0, *Bh, *Bo, *B1, *B2;
    cudaGetSymbolAddress((void**)&H0,  g_H0);
    cudaGetSymbolAddress((void**)&Ha,  g_Ha);
    cudaGetSymbolAddress((void**)&Hb,  g_Hb);
    cudaGetSymbolAddress((void**)&Mv,  g_Mv);
    cudaGetSymbolAddress((void**)&Hv,  g_Hv);
    cudaGetSymbolAddress((void**)&Z,   g_Z);
    cudaGetSymbolAddress((void**)&cnt, g_cnt);
    cudaGetSymbolAddress((void**)&T,   g_T);
    cudaGetSymbolAddress((void**)&bo,  g_bo);
    cudaGetSymbolAddress((void**)&As,  g_As);
    cudaGetSymbolAddress((void**)&Bh0, g_Bh0);
    cudaGetSymbolAddress((void**)&Bh,  g_Bh);
    cudaGetSymbolAddress((void**)&Bo,  g_Bo);
    cudaGetSymbolAddress((void**)&B1,  g_B1);
    cudaGetSymbolAddress((void**)&B2,  g_B2);

    const int SM160 = 2 * (128 * 80 + 160 * 80);   // 46080
    const int SM128 = 2 * (128 * 80 + 128 * 80);   // 40960

    // ---- weight prep (transpose + bf16 split) ----
    prep_bt_k<<<(320 * 128 + 255) / 256, 256>>>(W_i, Bh0, 86,  300, 128, 320);
    prep_bt_k<<<(320 * 320 + 255) / 256, 256>>>(W_h, Bh,  300, 300, 320, 320);
    prep_bt_k<<<(320 * 384 + 255) / 256, 256>>>(W_o, Bo,  372, 300, 384, 320);
    prep_bt_k<<<(256 * 320 + 255) / 256, 256>>>(W1,  B1,  300, 256, 320, 256);
    prep_bt_k<<<(256 * 256 + 255) / 256, 256>>>(W2,  B2,  256, 256, 256, 256);
    pad_k<<<(DHP + 255) / 256, 256>>>(b_o, bo, 1, 300, 1, DHP);

    const long long bondsElems = (long long)NBO * DHP;
    const long long atomElems  = (long long)NAT * DHP;
    const int SCT = (int)((bondsElems + 255) / 256);
    const int PLT = (int)((atomElems + 255) / 256);

    // 1. H0 = concat(V[src], E) @ W_i ; Ha = relu(H0)
    prep_h0a_k<<<NBO * 64 / 256, 256>>>(V, E, esrc, As);
    gemm_mma<3, 160><<<dim3(2, NBO / 128), 256, SM160>>>(
        As, 256, 128, Bh0, 256, nullptr, H0, Ha, DHP);

    // 2. two message-passing iterations
    float* Hc = Ha; float* Hn = Hb;
    for (int it = 0; it < 2; it++) {
        cudaMemsetAsync(Mv, 0, (size_t)NAT * DHP * sizeof(float));
        scatter_k<<<SCT, 256>>>(Hc, edst, Mv);
        prep_msga_k<<<(int)((long long)NBO * 160 / 256), 256>>>(Mv, Hc, esrc, rev, As);
        gemm_mma<2, 160><<<dim3(2, NBO / 128), 256, SM160>>>(
            As, 640, 320, Bh, 640, H0, Hn, nullptr, DHP);
        float* t = Hc; Hc = Hn; Hn = t;
    }

    // 3. final segment sum
    cudaMemsetAsync(Mv, 0, (size_t)NAT * DHP * sizeof(float));
    scatter_k<<<SCT, 256>>>(Hc, edst, Mv);

    // 4. Hv = relu(concat(V, Mv) @ W_o + b_o)
    prep_woa_k<<<(int)((long long)NAT * 192 / 256), 256>>>(V, Mv, As);
    gemm_mma<1, 160><<<dim3(2, NAT / 128), 256, SM160>>>(
        As, 768, 384, Bo, 768, bo, Hv, nullptr, DHP);

    // 5. mean pool
    cudaMemsetAsync(Z, 0, (size_t)NMO * DHP * sizeof(float));
    cudaMemsetAsync(cnt, 0, (size_t)NMO * sizeof(float));
    pool_k<<<PLT, 256>>>(Hv, batc, Z);
    count_k<<<(NAT + 255) / 256, 256>>>(batc, cnt);
    div_k<<<(NMO * DHP + 255) / 256, 256>>>(Z, cnt);

    // 6. T = relu(Z @ W1 + b1)
    prep_pa_k<<<(NMO * 160 + 255) / 256, 256>>>(Z, As, NMO, 320);
    gemm_mma<1, 128><<<dim3(2, NMO / 128), 256, SM128>>>(
        As, 640, 320, B1, 640, b1, T, nullptr, DEM);

    // 7. out = T @ W2 + b2
    prep_pa_k<<<(NMO * 128 + 255) / 256, 256>>>(T, As, NMO, 256);
    gemm_mma<4, 128><<<dim3(2, NMO / 128), 256, SM128>>>(
        As, 512, 256, B2, 512, b2, out, nullptr, DEM);
}

// round 7
// speedup vs baseline: 2.7537x; 1.3513x over previous
#include <cuda_runtime.h>
#include <cuda_bf16.h>
#include <cstdint>
#include <cstddef>

#define NAT 131072
#define NBO 262144
#define NMO 4096
#define DHP 320
#define DEM 256

// ---------------- scratch (device globals; no allocation) ----------------
__device__ float g_H0[(size_t)NBO * DHP];
__device__ float g_Ha[(size_t)NBO * DHP];
__device__ float g_Hb[(size_t)NBO * DHP];
__device__ float g_Mv1[(size_t)NAT * DHP];
__device__ float g_Mv2[(size_t)NAT * DHP];
__device__ float g_Z [(size_t)NMO * DHP];
__device__ float g_cnt[NMO];
__device__ float g_T [(size_t)NMO * DEM];
__device__ float g_bo[DHP];
__device__ __align__(16) __nv_bfloat16 g_Bh0[320 * 256];
__device__ __align__(16) __nv_bfloat16 g_Bh [320 * 640];
__device__ __align__(16) __nv_bfloat16 g_Bo [320 * 768];
__device__ __align__(16) __nv_bfloat16 g_B1 [256 * 640];
__device__ __align__(16) __nv_bfloat16 g_B2 [256 * 512];

// ---------------- PTX helpers ----------------
__device__ __forceinline__ uint32_t smem_u32(const void* p) {
    uint32_t a;
    asm("{ .reg .u64 t; cvta.to.shared.u64 t, %1; cvt.u32.u64 %0, t; }"
        : "=r"(a) : "l"(p));
    return a;
}
__device__ __forceinline__ void cpa16(uint32_t dst, const void* src) {
    asm volatile("cp.async.cg.shared.global [%0], [%1], 16;"
                 :: "r"(dst), "l"(src) : "memory");
}
__device__ __forceinline__ void cp_commit() {
    asm volatile("cp.async.commit_group;" ::: "memory");
}
template<int N>
__device__ __forceinline__ void cp_wait() {
    asm volatile("cp.async.wait_group %0;" :: "n"(N) : "memory");
}
__device__ __forceinline__ void ldsm4(uint32_t* r, uint32_t a) {
    asm volatile("ldmatrix.sync.aligned.m8n8.x4.shared.b16 {%0,%1,%2,%3}, [%4];"
                 : "=r"(r[0]), "=r"(r[1]), "=r"(r[2]), "=r"(r[3]) : "r"(a));
}
__device__ __forceinline__ void ldsm2(uint32_t* r, uint32_t a) {
    asm volatile("ldmatrix.sync.aligned.m8n8.x2.shared.b16 {%0,%1}, [%2];"
                 : "=r"(r[0]), "=r"(r[1]) : "r"(a));
}
__device__ __forceinline__ void mma16816(float* c, const uint32_t* a, const uint32_t* b) {
    asm volatile(
        "mma.sync.aligned.m16n8k16.row.col.f32.bf16.bf16.f32 "
        "{%0,%1,%2,%3}, {%4,%5,%6,%7}, {%8,%9}, {%0,%1,%2,%3};"
        : "+f"(c[0]), "+f"(c[1]), "+f"(c[2]), "+f"(c[3])
        : "r"(a[0]), "r"(a[1]), "r"(a[2]), "r"(a[3]), "r"(b[0]), "r"(b[1]));
}
__device__ __forceinline__ void sts16(uint32_t a, uint32_t x, uint32_t y,
                                      uint32_t z, uint32_t w) {
    asm volatile("st.shared.v4.b32 [%0], {%1,%2,%3,%4};"
                 :: "r"(a), "r"(x), "r"(y), "r"(z), "r"(w) : "memory");
}

// ---------------- weight prep ----------------
__global__ void prep_bt_k(const float* __restrict__ W, __nv_bfloat16* __restrict__ out,
                          int Ksrc, int Nsrc, int KP, int Nrows) {
    int idx = blockIdx.x * 256 + threadIdx.x;
    if (idx >= Nrows * KP) return;
    int n = idx / KP, k = idx - n * KP;
    float v = (k < Ksrc && n < Nsrc) ? W[(size_t)k * Nsrc + n] : 0.f;
    __nv_bfloat16 hi = __float2bfloat16(v);
    size_t base = (size_t)n * (2 * KP);
    out[base + k] = hi;
    out[base + KP + k] = __float2bfloat16(v - __bfloat162float(hi));
}

__global__ void pad_k(const float* __restrict__ in, float* __restrict__ out,
                      int IC, int OC) {
    int idx = blockIdx.x * blockDim.x + threadIdx.x;
    if (idx >= OC) return;
    out[idx] = (idx < IC) ? in[idx] : 0.f;
}

// ---------------- fused GEMM ----------------
// AMODE: 0 plain A1[r*KP+k]
//        1 h0 concat-gather: k<72 ? V[g[r]*72+k] : (k<86 ? E[r*14+k-72] : 0)
//        2 message: Mv[g[r]*320+k] - H[(r^1)*320+k]
//        3 wo concat: k<72 ? V[r*72+k] : (k<372 ? Mv[r*320+k-72] : 0)
// EPI:   0 C=acc+aux[c]                         (MLP out)
//        1 C=relu(acc+aux[c])                   (MLP hidden)
//        2 v=relu(acc+aux[r*N+c]); C=v; scatter (msg iter w/ store)
//        3 v=relu(acc); C=acc; C2=v; scatter    (H0)
//        4 v=relu(acc+aux[r*N+c]); scatter only (msg last iter)
//        5 v=relu(acc+aux[c]); scatter only     (Wo -> pool)
// scatter: atomicAdd(S[sidx[r]*DHP + c], v)
template<int AMODE>
__device__ __forceinline__ void loadA16(const float* __restrict__ A1,
                                        const float* __restrict__ A2,
                                        long long row, int s, int k0, int KP,
                                        float* va) {
    if (AMODE == 0) {
        const float4* p = (const float4*)(A1 + row * KP + k0);
#pragma unroll
        for (int i = 0; i < 4; i++) {
            float4 v = p[i];
            va[4*i] = v.x; va[4*i+1] = v.y; va[4*i+2] = v.z; va[4*i+3] = v.w;
        }
    } else if (AMODE == 2) {
        const float4* pm = (const float4*)(A1 + (size_t)s * DHP + k0);
        const float4* ph = (const float4*)(A2 + (size_t)(row ^ 1) * DHP + k0);
#pragma unroll
        for (int i = 0; i < 4; i++) {
            float4 m = pm[i], h = ph[i];
            va[4*i]   = m.x - h.x; va[4*i+1] = m.y - h.y;
            va[4*i+2] = m.z - h.z; va[4*i+3] = m.w - h.w;
        }
    } else if (AMODE == 1) {
#pragma unroll
        for (int j = 0; j < 16; j++) {
            int k = k0 + j;
            va[j] = (k < 72) ? A1[(size_t)s * 72 + k]
                             : (k < 86 ? A2[row * 14 + (k - 72)] : 0.f);
        }
    } else {
#pragma unroll
        for (int j = 0; j < 16; j++) {
            int k = k0 + j;
            va[j] = (k < 72) ? A1[row * 72 + k]
                             : (k < 372 ? A2[row * DHP + (k - 72)] : 0.f);
        }
    }
}

__device__ __forceinline__ void storeA16(uint32_t ahi, uint32_t alo, const float* va) {
    uint32_t h[8], l[8];
#pragma unroll
    for (int j = 0; j < 8; j++) {
        float a = va[2*j], b = va[2*j+1];
        __nv_bfloat16 ha = __float2bfloat16(a), hb = __float2bfloat16(b);
        __nv_bfloat162 hp; hp.x = ha; hp.y = hb;
        h[j] = *(uint32_t*)&hp;
        __nv_bfloat162 lp = __floats2bfloat162_rn(a - __bfloat162float(ha),
                                                  b - __bfloat162float(hb));
        l[j] = *(uint32_t*)&lp;
    }
    sts16(ahi,      h[0], h[1], h[2], h[3]);
    sts16(ahi + 16, h[4], h[5], h[6], h[7]);
    sts16(alo,      l[0], l[1], l[2], l[3]);
    sts16(alo + 16, l[4], l[5], l[6], l[7]);
}

template<int AMODE, int EPI, int BN>
__global__ void __launch_bounds__(256, 1)
gemm_f(const float* __restrict__ A1, const float* __restrict__ A2,
       const int* __restrict__ gidx,
       const __nv_bfloat16* __restrict__ Bt, int KP,
       const float* __restrict__ aux,
       const int* __restrict__ sidx, float* __restrict__ S,
       float* __restrict__ C, float* __restrict__ C2, int N) {
    constexpr int NT = BN / 32;
    constexpr int RS = 80;
    constexpr int ABUF = 128 * RS;              // one A matrix (hi or lo)
    constexpr int BBUF = BN * RS;
    constexpr int STG = 2 * ABUF + 2 * BBUF;    // [Ahi][Alo][Bhi][Blo]
    extern __shared__ __align__(16) char sm[];
    const uint32_t sbase = smem_u32(sm);

    const int tid = threadIdx.x;
    const int wid = tid >> 5, lane = tid & 31;
    const int wm = wid & 1, wn = wid >> 1;
    const long long bm = (long long)blockIdx.y * 128;
    const int bn = blockIdx.x * BN;
    const int nW = KP >> 5;
    const int ldb = 2 * KP;

    const int arow = tid >> 1;
    const int kh = (tid & 1) * 16;
    const long long grow = bm + arow;
    const int s = (AMODE == 1 || AMODE == 2) ? gidx[grow] : 0;

    float acc[4][NT][4];
#pragma unroll
    for (int i = 0; i < 4; i++)
#pragma unroll
        for (int j = 0; j < NT; j++)
#pragma unroll
            for (int t = 0; t < 4; t++) acc[i][j][t] = 0.f;

    const int aRow = (lane & 7) + ((lane >> 3) & 1) * 8;
    const int aK   = (lane >> 4) * 8;
    const int bRow = lane & 7;
    const int bK   = ((lane >> 3) & 1) * 8;

    auto loadB = [&](int w, int buf) {
        const uint32_t bhi = sbase + buf * STG + 2 * ABUF;
        for (int idx = tid; idx < BN * 4; idx += 256) {
            int row = idx >> 2, sg = idx & 3;
            cpa16(bhi + row * RS + sg * 16,
                  Bt + (size_t)(bn + row) * ldb + w * 32 + sg * 8);
        }
        for (int idx = tid; idx < BN * 4; idx += 256) {
            int row = idx >> 2, sg = idx & 3;
            cpa16(bhi + BBUF + row * RS + sg * 16,
                  Bt + (size_t)(bn + row) * ldb + KP + w * 32 + sg * 8);
        }
    };

    // prologue: window 0
    {
        float va[16];
        loadA16<AMODE>(A1, A2, grow, s, kh, KP, va);
        uint32_t ah = sbase + arow * RS + kh * 2;
        storeA16(ah, ah + ABUF, va);
        loadB(0, 0);
        cp_commit();
    }

    for (int w = 0; w < nW; ++w) {
        const int buf = w & 1;
        const bool more = (w + 1 < nW);
        float va[16];
        if (more) {
            loadA16<AMODE>(A1, A2, grow, s, (w + 1) * 32 + kh, KP, va);
            loadB(w + 1, buf ^ 1);
            cp_commit();
        }
        if (more) cp_wait<1>(); else cp_wait<0>();
        __syncthreads();
        if (more) {
            uint32_t ah = sbase + (buf ^ 1) * STG + arow * RS + kh * 2;
            storeA16(ah, ah + ABUF, va);
        }
        const uint32_t as = sbase + buf * STG;
        const uint32_t bs = as + 2 * ABUF;
#pragma unroll
        for (int ks = 0; ks < 32; ks += 16) {
            uint32_t afh[4][4], afl[4][4], bfh[NT][2], bfl[NT][2];
#pragma unroll
            for (int mt = 0; mt < 4; ++mt) {
                uint32_t ar = as + (wm * 64 + mt * 16 + aRow) * RS + (ks + aK) * 2;
                ldsm4(afh[mt], ar);
                ldsm4(afl[mt], ar + ABUF);
            }
#pragma unroll
            for (int nt = 0; nt < NT; ++nt) {
                uint32_t br = bs + (wn * NT * 8 + nt * 8 + bRow) * RS + (ks + bK) * 2;
                ldsm2(bfh[nt], br);
                ldsm2(bfl[nt], br + BBUF);
            }
#pragma unroll
            for (int mt = 0; mt < 4; ++mt)
#pragma unroll
                for (int nt = 0; nt < NT; ++nt) {
                    mma16816(acc[mt][nt], afh[mt], bfh[nt]);
                    mma16816(acc[mt][nt], afl[mt], bfh[nt]);
                    mma16816(acc[mt][nt], afh[mt], bfl[nt]);
                }
        }
        __syncthreads();
    }

    // ---- epilogue ----
    const int gid = lane >> 2, tig = lane & 3;
#pragma unroll
    for (int mt = 0; mt < 4; ++mt) {
        const long long r0 = bm + wm * 64 + mt * 16 + gid;
        const long long r1 = r0 + 8;
        int si0 = 0, si1 = 0;
        if (EPI >= 2) { si0 = sidx[r0]; si1 = sidx[r1]; }
#pragma unroll
        for (int nt = 0; nt < NT; ++nt) {
            const int c0 = bn + wn * NT * 8 + nt * 8 + tig * 2;
            float v00 = acc[mt][nt][0], v01 = acc[mt][nt][1];
            float v10 = acc[mt][nt][2], v11 = acc[mt][nt][3];
            float r00, r01, r10, r11;
            if (EPI == 0 || EPI == 1 || EPI == 5) {
                float2 ax = *(const float2*)(aux + c0);
                r00 = v00 + ax.x; r01 = v01 + ax.y;
                r10 = v10 + ax.x; r11 = v11 + ax.y;
            } else if (EPI == 2 || EPI == 4) {
                float2 a0 = *(const float2*)(aux + r0 * N + c0);
                float2 a1 = *(const float2*)(aux + r1 * N + c0);
                r00 = v00 + a0.x; r01 = v01 + a0.y;
                r10 = v10 + a1.x; r11 = v11 + a1.y;
            } else { // EPI==3
                r00 = v00; r01 = v01; r10 = v10; r11 = v11;
            }
            if (EPI != 0) {
                r00 = fmaxf(r00, 0.f); r01 = fmaxf(r01, 0.f);
                r10 = fmaxf(r10, 0.f); r11 = fmaxf(r11, 0.f);
            }
            // stores
            if (EPI == 0 || EPI == 1 || EPI == 2) {
                *(float2*)(C + r0 * N + c0) = make_float2(r00, r01);
                *(float2*)(C + r1 * N + c0) = make_float2(r10, r11);
            } else if (EPI == 3) {
                *(float2*)(C + r0 * N + c0) = make_float2(v00, v01);
                *(float2*)(C + r1 * N + c0) = make_float2(v10, v11);
                *(float2*)(C2 + r0 * N + c0) = make_float2(r00, r01);
                *(float2*)(C2 + r1 * N + c0) = make_float2(r10, r11);
            }
            // scatter
            if (EPI >= 2) {
                float* s0 = S + (size_t)si0 * DHP + c0;
                float* s1 = S + (size_t)si1 * DHP + c0;
                if (r00 != 0.f) atomicAdd(s0,     r00);
                if (r01 != 0.f) atomicAdd(s0 + 1, r01);
                if (r10 != 0.f) atomicAdd(s1,     r10);
                if (r11 != 0.f) atomicAdd(s1 + 1, r11);
            }
        }
    }
}

// ---------------- misc ----------------
__global__ void count_k(const int* __restrict__ batch, float* __restrict__ cnt) {
    int a = blockIdx.x * blockDim.x + threadIdx.x;
    if (a < NAT) atomicAdd(&cnt[batch[a]], 1.f);
}
__global__ void div_k(float* __restrict__ Z, const float* __restrict__ cnt) {
    int idx = blockIdx.x * blockDim.x + threadIdx.x;
    if (idx >= NMO * DHP) return;
    int m = idx / DHP;
    Z[idx] = Z[idx] / fmaxf(cnt[m], 1.f);
}

// ---------------- launcher ----------------
extern "C" void kernel_launch(void* const* d_in, const int* in_sizes, int n_in,
                              void* d_out, int out_size) {
    const float* V    = (const float*)d_in[0];
    const float* E    = (const float*)d_in[1];
    const int*   esrc = (const int*)d_in[2];
    const int*   edst = (const int*)d_in[3];
    const int*   batc = (const int*)d_in[5];
    int wi = 6;
    if (n_in >= 15 && in_sizes[6] == 1) wi = 7;
    const float* W_i = (const float*)d_in[wi + 0];
    const float* W_h = (const float*)d_in[wi + 1];
    const float* W_o = (const float*)d_in[wi + 2];
    const float* b_o = (const float*)d_in[wi + 3];
    const float* W1  = (const float*)d_in[wi + 4];
    const float* b1  = (const float*)d_in[wi + 5];
    const float* W2  = (const float*)d_in[wi + 6];
    const float* b2  = (const float*)d_in[wi + 7];
    float* out = (float*)d_out;

    float *H0, *Ha, *Hb, *Mv1, *Mv2, *Z, *cnt, *T, *bo;
    __nv_bfloat16 *Bh0, *Bh, *Bo, *B1, *B2;
    cudaGetSymbolAddress((void**)&H0,  g_H0);
    cudaGetSymbolAddress((void**)&Ha,  g_Ha);
    cudaGetSymbolAddress((void**)&Hb,  g_Hb);
    cudaGetSymbolAddress((void**)&Mv1, g_Mv1);
    cudaGetSymbolAddress((void**)&Mv2, g_Mv2);
    cudaGetSymbolAddress((void**)&Z,   g_Z);
    cudaGetSymbolAddress((void**)&cnt, g_cnt);
    cudaGetSymbolAddress((void**)&T,   g_T);
    cudaGetSymbolAddress((void**)&bo,  g_bo);
    cudaGetSymbolAddress((void**)&Bh0, g_Bh0);
    cudaGetSymbolAddress((void**)&Bh,  g_Bh);
    cudaGetSymbolAddress((void**)&Bo,  g_Bo);
    cudaGetSymbolAddress((void**)&B1,  g_B1);
    cudaGetSymbolAddress((void**)&B2,  g_B2);

    const int SMF160 = 2 * (2 * 128 * 80 + 2 * 160 * 80);  // 92160
    const int SMF128 = 2 * (2 * 128 * 80 + 2 * 128 * 80);  // 81920
    cudaFuncSetAttribute(gemm_f<1,3,160>, cudaFuncAttributeMaxDynamicSharedMemorySize, SMF160);
    cudaFuncSetAttribute(gemm_f<2,2,160>, cudaFuncAttributeMaxDynamicSharedMemorySize, SMF160);
    cudaFuncSetAttribute(gemm_f<2,4,160>, cudaFuncAttributeMaxDynamicSharedMemorySize, SMF160);
    cudaFuncSetAttribute(gemm_f<3,5,160>, cudaFuncAttributeMaxDynamicSharedMemorySize, SMF160);
    cudaFuncSetAttribute(gemm_f<0,1,128>, cudaFuncAttributeMaxDynamicSharedMemorySize, SMF128);
    cudaFuncSetAttribute(gemm_f<0,0,128>, cudaFuncAttributeMaxDynamicSharedMemorySize, SMF128);

    // weight prep (transpose + split)
    prep_bt_k<<<(320 * 128 + 255) / 256, 256>>>(W_i, Bh0, 86,  300, 128, 320);
    prep_bt_k<<<(320 * 320 + 255) / 256, 256>>>(W_h, Bh,  300, 300, 320, 320);
    prep_bt_k<<<(320 * 384 + 255) / 256, 256>>>(W_o, Bo,  372, 300, 384, 320);
    prep_bt_k<<<(256 * 320 + 255) / 256, 256>>>(W1,  B1,  300, 256, 320, 256);
    prep_bt_k<<<(256 * 256 + 255) / 256, 256>>>(W2,  B2,  256, 256, 256, 256);
    pad_k<<<2, 256>>>(b_o, bo, 300, DHP);

    const size_t MVB = (size_t)NAT * DHP * sizeof(float);

    // 1. H0 = concat(V[src],E)@W_i ; Ha = relu ; scatter relu -> Mv1
    cudaMemsetAsync(Mv1, 0, MVB);
    gemm_f<1,3,160><<<dim3(2, NBO / 128), 256, SMF160>>>(
        V, E, esrc, Bh0, 128, nullptr, edst, Mv1, H0, Ha, DHP);

    // 2. iter1: Hb = relu(H0 + (Mv1[src]-Ha[rev])@Wh) ; scatter -> Mv2
    cudaMemsetAsync(Mv2, 0, MVB);
    gemm_f<2,2,160><<<dim3(2, NBO / 128), 256, SMF160>>>(
        Mv1, Ha, esrc, Bh, 320, H0, edst, Mv2, Hb, nullptr, DHP);

    // 3. iter2: relu(H0 + (Mv2[src]-Hb[rev])@Wh) scattered -> Mv1 (no store)
    cudaMemsetAsync(Mv1, 0, MVB);
    gemm_f<2,4,160><<<dim3(2, NBO / 128), 256, SMF160>>>(
        Mv2, Hb, esrc, Bh, 320, H0, edst, Mv1, nullptr, nullptr, DHP);

    // 4. Hv = relu(concat(V,Mv1)@Wo + bo) pooled -> Z (no store)
    cudaMemsetAsync(Z, 0, (size_t)NMO * DHP * sizeof(float));
    cudaMemsetAsync(cnt, 0, (size_t)NMO * sizeof(float));
    gemm_f<3,5,160><<<dim3(2, NAT / 128), 256, SMF160>>>(
        V, Mv1, nullptr, Bo, 384, bo, batc, Z, nullptr, nullptr, DHP);

    // 5. mean
    count_k<<<(NAT + 255) / 256, 256>>>(batc, cnt);
    div_k<<<(NMO * DHP + 255) / 256, 256>>>(Z, cnt);

    // 6. T = relu(Z@W1+b1)
    gemm_f<0,1,128><<<dim3(2, NMO / 128), 256, SMF128>>>(
        Z, nullptr, nullptr, B1, 320, b1, nullptr, nullptr, T, nullptr, DEM);

    // 7. out = T@W2+b2
    gemm_f<0,0,128><<<dim3(2, NMO / 128), 256, SMF128>>>(
        T, nullptr, nullptr, B2, 256, b2, nullptr, nullptr, out, nullptr, DEM);
}

// round 8
// speedup vs baseline: 3.0525x; 1.1085x over previous
#include <cuda_runtime.h>
#include <cuda_bf16.h>
#include <cstdint>
#include <cstddef>

#define NAT 131072
#define NBO 262144
#define NMO 4096
#define DHP 320
#define DEM 256

// ---------------- scratch (device globals; no allocation) ----------------
__device__ float g_H0[(size_t)NBO * DHP];
__device__ float g_Ha[(size_t)NBO * DHP];
__device__ float g_Hb[(size_t)NBO * DHP];
__device__ float g_Mv1[(size_t)NAT * DHP];
__device__ float g_Mv2[(size_t)NAT * DHP];
__device__ float g_Z [(size_t)NMO * DHP];
__device__ float g_cnt[NMO];
__device__ float g_T [(size_t)NMO * DEM];
__device__ float g_bo[DHP];
__device__ __align__(16) __nv_bfloat16 g_Bh0[320 * 192];
__device__ __align__(16) __nv_bfloat16 g_Bh [320 * 640];
__device__ __align__(16) __nv_bfloat16 g_Bo [320 * 768];
__device__ __align__(16) __nv_bfloat16 g_B1 [256 * 640];
__device__ __align__(16) __nv_bfloat16 g_B2 [256 * 512];

// ---------------- PTX helpers ----------------
__device__ __forceinline__ uint32_t smem_u32(const void* p) {
    uint32_t a;
    asm("{ .reg .u64 t; cvta.to.shared.u64 t, %1; cvt.u32.u64 %0, t; }"
        : "=r"(a) : "l"(p));
    return a;
}
__device__ __forceinline__ void cpa16(uint32_t dst, const void* src) {
    asm volatile("cp.async.cg.shared.global [%0], [%1], 16;"
                 :: "r"(dst), "l"(src) : "memory");
}
__device__ __forceinline__ void cp_commit() {
    asm volatile("cp.async.commit_group;" ::: "memory");
}
template<int N>
__device__ __forceinline__ void cp_wait() {
    asm volatile("cp.async.wait_group %0;" :: "n"(N) : "memory");
}
__device__ __forceinline__ void ldsm4(uint32_t* r, uint32_t a) {
    asm volatile("ldmatrix.sync.aligned.m8n8.x4.shared.b16 {%0,%1,%2,%3}, [%4];"
                 : "=r"(r[0]), "=r"(r[1]), "=r"(r[2]), "=r"(r[3]) : "r"(a));
}
__device__ __forceinline__ void ldsm2(uint32_t* r, uint32_t a) {
    asm volatile("ldmatrix.sync.aligned.m8n8.x2.shared.b16 {%0,%1}, [%2];"
                 : "=r"(r[0]), "=r"(r[1]) : "r"(a));
}
__device__ __forceinline__ void mma16816(float* c, const uint32_t* a, const uint32_t* b) {
    asm volatile(
        "mma.sync.aligned.m16n8k16.row.col.f32.bf16.bf16.f32 "
        "{%0,%1,%2,%3}, {%4,%5,%6,%7}, {%8,%9}, {%0,%1,%2,%3};"
        : "+f"(c[0]), "+f"(c[1]), "+f"(c[2]), "+f"(c[3])
        : "r"(a[0]), "r"(a[1]), "r"(a[2]), "r"(a[3]), "r"(b[0]), "r"(b[1]));
}
__device__ __forceinline__ void sts16(uint32_t a, uint32_t x, uint32_t y,
                                      uint32_t z, uint32_t w) {
    asm volatile("st.shared.v4.b32 [%0], {%1,%2,%3,%4};"
                 :: "r"(a), "r"(x), "r"(y), "r"(z), "r"(w) : "memory");
}
__device__ __forceinline__ void red2(float* addr, float x, float y) {
    asm volatile("red.global.add.v2.f32 [%0], {%1,%2};"
                 :: "l"(addr), "f"(x), "f"(y) : "memory");
}

// ---------------- weight prep ----------------
__global__ void prep_bt_k(const float* __restrict__ W, __nv_bfloat16* __restrict__ out,
                          int Ksrc, int Nsrc, int KP, int Nrows) {
    int idx = blockIdx.x * 256 + threadIdx.x;
    if (idx >= Nrows * KP) return;
    int n = idx / KP, k = idx - n * KP;
    float v = (k < Ksrc && n < Nsrc) ? W[(size_t)k * Nsrc + n] : 0.f;
    __nv_bfloat16 hi = __float2bfloat16(v);
    size_t base = (size_t)n * (2 * KP);
    out[base + k] = hi;
    out[base + KP + k] = __float2bfloat16(v - __bfloat162float(hi));
}

__global__ void pad_k(const float* __restrict__ in, float* __restrict__ out,
                      int IC, int OC) {
    int idx = blockIdx.x * blockDim.x + threadIdx.x;
    if (idx >= OC) return;
    out[idx] = (idx < IC) ? in[idx] : 0.f;
}

// ---------------- fused GEMM ----------------
// AMODE: 0 plain A1[r*KP+k]
//        1 h0 concat-gather: k<72 ? V[g[r]*72+k] : (k<86 ? E[r*14+k-72] : 0)
//        2 message: Mv[g[r]*320+k] - H[(r^1)*320+k]
//        3 wo concat: k<72 ? V[r*72+k] : (k<372 ? Mv[r*320+k-72] : 0)
// EPI:   0 C=acc+aux[c] ; 1 C=relu(acc+aux[c]) ;
//        2 v=relu(acc+aux[r*N+c]); C=v; scatter ; 3 v=relu(acc); C=acc; C2=v; scatter ;
//        4 relu(acc+aux[r*N+c]) scatter only ; 5 relu(acc+aux[c]) scatter only
template<int AMODE>
__device__ __forceinline__ void loadA16(const float* __restrict__ A1,
                                        const float* __restrict__ A2,
                                        long long row, int s, int k0, int KP,
                                        float* va) {
    if (AMODE == 0) {
        const float4* p = (const float4*)(A1 + row * KP + k0);
#pragma unroll
        for (int i = 0; i < 4; i++) {
            float4 v = p[i];
            va[4*i] = v.x; va[4*i+1] = v.y; va[4*i+2] = v.z; va[4*i+3] = v.w;
        }
    } else if (AMODE == 2) {
        const float4* pm = (const float4*)(A1 + (size_t)s * DHP + k0);
        const float4* ph = (const float4*)(A2 + (size_t)(row ^ 1) * DHP + k0);
#pragma unroll
        for (int i = 0; i < 4; i++) {
            float4 m = pm[i], h = ph[i];
            va[4*i]   = m.x - h.x; va[4*i+1] = m.y - h.y;
            va[4*i+2] = m.z - h.z; va[4*i+3] = m.w - h.w;
        }
    } else if (AMODE == 1) {
#pragma unroll
        for (int j = 0; j < 16; j++) {
            int k = k0 + j;
            va[j] = (k < 72) ? A1[(size_t)s * 72 + k]
                             : (k < 86 ? A2[row * 14 + (k - 72)] : 0.f);
        }
    } else {
#pragma unroll
        for (int j = 0; j < 16; j++) {
            int k = k0 + j;
            va[j] = (k < 72) ? A1[row * 72 + k]
                             : (k < 372 ? A2[row * DHP + (k - 72)] : 0.f);
        }
    }
}

__device__ __forceinline__ void storeA16(uint32_t ahi, uint32_t alo, const float* va) {
    uint32_t h[8], l[8];
#pragma unroll
    for (int j = 0; j < 8; j++) {
        float a = va[2*j], b = va[2*j+1];
        __nv_bfloat16 ha = __float2bfloat16(a), hb = __float2bfloat16(b);
        __nv_bfloat162 hp; hp.x = ha; hp.y = hb;
        h[j] = *(uint32_t*)&hp;
        __nv_bfloat162 lp = __floats2bfloat162_rn(a - __bfloat162float(ha),
                                                  b - __bfloat162float(hb));
        l[j] = *(uint32_t*)&lp;
    }
    sts16(ahi,      h[0], h[1], h[2], h[3]);
    sts16(ahi + 16, h[4], h[5], h[6], h[7]);
    sts16(alo,      l[0], l[1], l[2], l[3]);
    sts16(alo + 16, l[4], l[5], l[6], l[7]);
}

template<int AMODE, int EPI, int BN>
__global__ void __launch_bounds__(256, 1)
gemm_f(const float* __restrict__ A1, const float* __restrict__ A2,
       const int* __restrict__ gidx,
       const __nv_bfloat16* __restrict__ Bt, int KP,
       const float* __restrict__ aux,
       const int* __restrict__ sidx, float* __restrict__ S,
       float* __restrict__ C, float* __restrict__ C2, int N) {
    constexpr int NT = BN / 32;
    constexpr int RS = 80;
    constexpr int ABUF = 128 * RS;
    constexpr int BBUF = BN * RS;
    constexpr int STG = 2 * ABUF + 2 * BBUF;    // [Ahi][Alo][Bhi][Blo]
    extern __shared__ __align__(16) char sm[];
    const uint32_t sbase = smem_u32(sm);

    const int tid = threadIdx.x;
    const int wid = tid >> 5, lane = tid & 31;
    const int wm = wid & 1, wn = wid >> 1;
    const long long bm = (long long)blockIdx.y * 128;
    const int bn = blockIdx.x * BN;
    const int nW = KP >> 5;
    const int ldb = 2 * KP;

    const int arow = tid >> 1;
    const int kh = (tid & 1) * 16;
    const long long grow = bm + arow;
    const int s = (AMODE == 1 || AMODE == 2) ? gidx[grow] : 0;

    float acc[4][NT][4];
#pragma unroll
    for (int i = 0; i < 4; i++)
#pragma unroll
        for (int j = 0; j < NT; j++)
#pragma unroll
            for (int t = 0; t < 4; t++) acc[i][j][t] = 0.f;

    const int aRow = (lane & 7) + ((lane >> 3) & 1) * 8;
    const int aK   = (lane >> 4) * 8;
    const int bRow = lane & 7;
    const int bK   = ((lane >> 3) & 1) * 8;

    auto loadB = [&](int w, int buf) {
        const uint32_t bhi = sbase + buf * STG + 2 * ABUF;
        for (int idx = tid; idx < BN * 4; idx += 256) {
            int row = idx >> 2, sg = idx & 3;
            cpa16(bhi + row * RS + sg * 16,
                  Bt + (size_t)(bn + row) * ldb + w * 32 + sg * 8);
        }
        for (int idx = tid; idx < BN * 4; idx += 256) {
            int row = idx >> 2, sg = idx & 3;
            cpa16(bhi + BBUF + row * RS + sg * 16,
                  Bt + (size_t)(bn + row) * ldb + KP + w * 32 + sg * 8);
        }
    };

    // prologue: window 0
    {
        float va[16];
        loadA16<AMODE>(A1, A2, grow, s, kh, KP, va);
        uint32_t ah = sbase + arow * RS + kh * 2;
        storeA16(ah, ah + ABUF, va);
        loadB(0, 0);
        cp_commit();
    }

    for (int w = 0; w < nW; ++w) {
        const int buf = w & 1;
        const bool more = (w + 1 < nW);
        float va[16];
        if (more) {
            // issue gather LDGs for next window; consumed AFTER the MMA body
            loadA16<AMODE>(A1, A2, grow, s, (w + 1) * 32 + kh, KP, va);
            loadB(w + 1, buf ^ 1);
            cp_commit();
        }
        if (more) cp_wait<1>(); else cp_wait<0>();
        __syncthreads();
        const uint32_t as = sbase + buf * STG;
        const uint32_t bs = as + 2 * ABUF;
#pragma unroll
        for (int ks = 0; ks < 32; ks += 16) {
            uint32_t afh[4][4], afl[4][4], bfh[NT][2], bfl[NT][2];
#pragma unroll
            for (int mt = 0; mt < 4; ++mt) {
                uint32_t ar = as + (wm * 64 + mt * 16 + aRow) * RS + (ks + aK) * 2;
                ldsm4(afh[mt], ar);
                ldsm4(afl[mt], ar + ABUF);
            }
#pragma unroll
            for (int nt = 0; nt < NT; ++nt) {
                uint32_t br = bs + (wn * NT * 8 + nt * 8 + bRow) * RS + (ks + bK) * 2;
                ldsm2(bfh[nt], br);
                ldsm2(bfl[nt], br + BBUF);
            }
#pragma unroll
            for (int mt = 0; mt < 4; ++mt)
#pragma unroll
                for (int nt = 0; nt < NT; ++nt) {
                    mma16816(acc[mt][nt], afh[mt], bfh[nt]);
                    mma16816(acc[mt][nt], afl[mt], bfh[nt]);
                    mma16816(acc[mt][nt], afh[mt], bfl[nt]);
                }
        }
        // split+store next window's A after the MMA body (LDG latency hidden)
        if (more) {
            uint32_t ah = sbase + (buf ^ 1) * STG + arow * RS + kh * 2;
            storeA16(ah, ah + ABUF, va);
        }
        __syncthreads();
    }

    // ---- epilogue ----
    const int gid = lane >> 2, tig = lane & 3;
#pragma unroll
    for (int mt = 0; mt < 4; ++mt) {
        const long long r0 = bm + wm * 64 + mt * 16 + gid;
        const long long r1 = r0 + 8;
        int si0 = 0, si1 = 0;
        if (EPI >= 2) { si0 = sidx[r0]; si1 = sidx[r1]; }
#pragma unroll
        for (int nt = 0; nt < NT; ++nt) {
            const int c0 = bn + wn * NT * 8 + nt * 8 + tig * 2;
            float v00 = acc[mt][nt][0], v01 = acc[mt][nt][1];
            float v10 = acc[mt][nt][2], v11 = acc[mt][nt][3];
            float r00, r01, r10, r11;
            if (EPI == 0 || EPI == 1 || EPI == 5) {
                float2 ax = *(const float2*)(aux + c0);
                r00 = v00 + ax.x; r01 = v01 + ax.y;
                r10 = v10 + ax.x; r11 = v11 + ax.y;
            } else if (EPI == 2 || EPI == 4) {
                float2 a0 = *(const float2*)(aux + r0 * N + c0);
                float2 a1 = *(const float2*)(aux + r1 * N + c0);
                r00 = v00 + a0.x; r01 = v01 + a0.y;
                r10 = v10 + a1.x; r11 = v11 + a1.y;
            } else { // EPI==3
                r00 = v00; r01 = v01; r10 = v10; r11 = v11;
            }
            if (EPI != 0) {
                r00 = fmaxf(r00, 0.f); r01 = fmaxf(r01, 0.f);
                r10 = fmaxf(r10, 0.f); r11 = fmaxf(r11, 0.f);
            }
            if (EPI == 0 || EPI == 1 || EPI == 2) {
                *(float2*)(C + r0 * N + c0) = make_float2(r00, r01);
                *(float2*)(C + r1 * N + c0) = make_float2(r10, r11);
            } else if (EPI == 3) {
                *(float2*)(C + r0 * N + c0) = make_float2(v00, v01);
                *(float2*)(C + r1 * N + c0) = make_float2(v10, v11);
                *(float2*)(C2 + r0 * N + c0) = make_float2(r00, r01);
                *(float2*)(C2 + r1 * N + c0) = make_float2(r10, r11);
            }
            if (EPI >= 2) {
                float* s0 = S + (size_t)si0 * DHP + c0;
                float* s1 = S + (size_t)si1 * DHP + c0;
                if (r00 != 0.f || r01 != 0.f) red2(s0, r00, r01);
                if (r10 != 0.f || r11 != 0.f) red2(s1, r10, r11);
            }
        }
    }
}

// ---------------- misc ----------------
__global__ void count_k(const int* __restrict__ batch, float* __restrict__ cnt) {
    int a = blockIdx.x * blockDim.x + threadIdx.x;
    if (a < NAT) atomicAdd(&cnt[batch[a]], 1.f);
}
__global__ void div_k(float* __restrict__ Z, const float* __restrict__ cnt) {
    int idx = blockIdx.x * blockDim.x + threadIdx.x;
    if (idx >= NMO * DHP) return;
    int m = idx / DHP;
    Z[idx] = Z[idx] / fmaxf(cnt[m], 1.f);
}

// ---------------- launcher ----------------
extern "C" void kernel_launch(void* const* d_in, const int* in_sizes, int n_in,
                              void* d_out, int out_size) {
    const float* V    = (const float*)d_in[0];
    const float* E    = (const float*)d_in[1];
    const int*   esrc = (const int*)d_in[2];
    const int*   edst = (const int*)d_in[3];
    const int*   batc = (const int*)d_in[5];
    int wi = 6;
    if (n_in >= 15 && in_sizes[6] == 1) wi = 7;
    const float* W_i = (const float*)d_in[wi + 0];
    const float* W_h = (const float*)d_in[wi + 1];
    const float* W_o = (const float*)d_in[wi + 2];
    const float* b_o = (const float*)d_in[wi + 3];
    const float* W1  = (const float*)d_in[wi + 4];
    const float* b1  = (const float*)d_in[wi + 5];
    const float* W2  = (const float*)d_in[wi + 6];
    const float* b2  = (const float*)d_in[wi + 7];
    float* out = (float*)d_out;

    float *H0, *Ha, *Hb, *Mv1, *Mv2, *Z, *cnt, *T, *bo;
    __nv_bfloat16 *Bh0, *Bh, *Bo, *B1, *B2;
    cudaGetSymbolAddress((void**)&H0,  g_H0);
    cudaGetSymbolAddress((void**)&Ha,  g_Ha);
    cudaGetSymbolAddress((void**)&Hb,  g_Hb);
    cudaGetSymbolAddress((void**)&Mv1, g_Mv1);
    cudaGetSymbolAddress((void**)&Mv2, g_Mv2);
    cudaGetSymbolAddress((void**)&Z,   g_Z);
    cudaGetSymbolAddress((void**)&cnt, g_cnt);
    cudaGetSymbolAddress((void**)&T,   g_T);
    cudaGetSymbolAddress((void**)&bo,  g_bo);
    cudaGetSymbolAddress((void**)&Bh0, g_Bh0);
    cudaGetSymbolAddress((void**)&Bh,  g_Bh);
    cudaGetSymbolAddress((void**)&Bo,  g_Bo);
    cudaGetSymbolAddress((void**)&B1,  g_B1);
    cudaGetSymbolAddress((void**)&B2,  g_B2);

    const int SMF160 = 2 * (2 * 128 * 80 + 2 * 160 * 80);  // 92160
    const int SMF128 = 2 * (2 * 128 * 80 + 2 * 128 * 80);  // 81920
    cudaFuncSetAttribute(gemm_f<1,3,160>, cudaFuncAttributeMaxDynamicSharedMemorySize, SMF160);
    cudaFuncSetAttribute(gemm_f<2,2,160>, cudaFuncAttributeMaxDynamicSharedMemorySize, SMF160);
    cudaFuncSetAttribute(gemm_f<2,4,160>, cudaFuncAttributeMaxDynamicSharedMemorySize, SMF160);
    cudaFuncSetAttribute(gemm_f<3,5,160>, cudaFuncAttributeMaxDynamicSharedMemorySize, SMF160);
    cudaFuncSetAttribute(gemm_f<0,1,128>, cudaFuncAttributeMaxDynamicSharedMemorySize, SMF128);
    cudaFuncSetAttribute(gemm_f<0,0,128>, cudaFuncAttributeMaxDynamicSharedMemorySize, SMF128);

    // weight prep (transpose + split)
    prep_bt_k<<<(320 * 96  + 255) / 256, 256>>>(W_i, Bh0, 86,  300, 96,  320);
    prep_bt_k<<<(320 * 320 + 255) / 256, 256>>>(W_h, Bh,  300, 300, 320, 320);
    prep_bt_k<<<(320 * 384 + 255) / 256, 256>>>(W_o, Bo,  372, 300, 384, 320);
    prep_bt_k<<<(256 * 320 + 255) / 256, 256>>>(W1,  B1,  300, 256, 320, 256);
    prep_bt_k<<<(256 * 256 + 255) / 256, 256>>>(W2,  B2,  256, 256, 256, 256);
    pad_k<<<2, 256>>>(b_o, bo, 300, DHP);

    const size_t MVB = (size_t)NAT * DHP * sizeof(float);

    // 1. H0 = concat(V[src],E)@W_i ; Ha = relu ; scatter relu -> Mv1
    cudaMemsetAsync(Mv1, 0, MVB);
    cudaMemsetAsync(Mv2, 0, MVB);
    cudaMemsetAsync(Z, 0, (size_t)NMO * DHP * sizeof(float));
    cudaMemsetAsync(cnt, 0, (size_t)NMO * sizeof(float));
    gemm_f<1,3,160><<<dim3(2, NBO / 128), 256, SMF160>>>(
        V, E, esrc, Bh0, 96, nullptr, edst, Mv1, H0, Ha, DHP);

    // 2. iter1: Hb = relu(H0 + (Mv1[src]-Ha[rev])@Wh) ; scatter -> Mv2
    gemm_f<2,2,160><<<dim3(2, NBO / 128), 256, SMF160>>>(
        Mv1, Ha, esrc, Bh, 320, H0, edst, Mv2, Hb, nullptr, DHP);

    // 3. iter2: relu(H0 + (Mv2[src]-Hb[rev])@Wh) scattered -> Mv1 (no store)
    cudaMemsetAsync(Mv1, 0, MVB);
    gemm_f<2,4,160><<<dim3(2, NBO / 128), 256, SMF160>>>(
        Mv2, Hb, esrc, Bh, 320, H0, edst, Mv1, nullptr, nullptr, DHP);

    // 4. Hv = relu(concat(V,Mv1)@Wo + bo) pooled -> Z (no store)
    gemm_f<3,5,160><<<dim3(2, NAT / 128), 256, SMF160>>>(
        V, Mv1, nullptr, Bo, 384, bo, batc, Z, nullptr, nullptr, DHP);

    // 5. mean
    count_k<<<(NAT + 255) / 256, 256>>>(batc, cnt);
    div_k<<<(NMO * DHP + 255) / 256, 256>>>(Z, cnt);

    // 6. T = relu(Z@W1+b1)
    gemm_f<0,1,128><<<dim3(2, NMO / 128), 256, SMF128>>>(
        Z, nullptr, nullptr, B1, 320, b1, nullptr, nullptr, T, nullptr, DEM);

    // 7. out = T@W2+b2
    gemm_f<0,0,128><<<dim3(2, NMO / 128), 256, SMF128>>>(
        T, nullptr, nullptr, B2, 256, b2, nullptr, nullptr, out, nullptr, DEM);
}

// round 9
// speedup vs baseline: 3.1833x; 1.0429x over previous
#include <cuda_runtime.h>
#include <cuda_bf16.h>
#include <cstdint>
#include <cstddef>

#define NAT 131072
#define NBO 262144
#define NMO 4096
#define DHP 320
#define DEM 256

// ---------------- scratch (device globals; no allocation) ----------------
__device__ float g_H0[(size_t)NBO * DHP];
__device__ float g_Hb[(size_t)NBO * DHP];
__device__ float g_Mv1[(size_t)NAT * DHP];
__device__ float g_Mv2[(size_t)NAT * DHP];
__device__ float g_Z [(size_t)NMO * DHP];
__device__ float g_cnt[NMO];
__device__ float g_T [(size_t)NMO * DEM];
__device__ float g_bo[DHP];
__device__ __align__(16) __nv_bfloat16 g_Bh0[320 * 192];
__device__ __align__(16) __nv_bfloat16 g_Bh [320 * 640];
__device__ __align__(16) __nv_bfloat16 g_Bo [320 * 768];
__device__ __align__(16) __nv_bfloat16 g_B1 [256 * 640];
__device__ __align__(16) __nv_bfloat16 g_B2 [256 * 512];

// ---------------- PTX helpers ----------------
__device__ __forceinline__ uint32_t smem_u32(const void* p) {
    uint32_t a;
    asm("{ .reg .u64 t; cvta.to.shared.u64 t, %1; cvt.u32.u64 %0, t; }"
        : "=r"(a) : "l"(p));
    return a;
}
__device__ __forceinline__ void cpa16(uint32_t dst, const void* src) {
    asm volatile("cp.async.cg.shared.global [%0], [%1], 16;"
                 :: "r"(dst), "l"(src) : "memory");
}
__device__ __forceinline__ void cp_commit() {
    asm volatile("cp.async.commit_group;" ::: "memory");
}
template<int N>
__device__ __forceinline__ void cp_wait() {
    asm volatile("cp.async.wait_group %0;" :: "n"(N) : "memory");
}
__device__ __forceinline__ void ldsm4(uint32_t* r, uint32_t a) {
    asm volatile("ldmatrix.sync.aligned.m8n8.x4.shared.b16 {%0,%1,%2,%3}, [%4];"
                 : "=r"(r[0]), "=r"(r[1]), "=r"(r[2]), "=r"(r[3]) : "r"(a));
}
__device__ __forceinline__ void mma16816(float* c, const uint32_t* a, const uint32_t* b) {
    asm volatile(
        "mma.sync.aligned.m16n8k16.row.col.f32.bf16.bf16.f32 "
        "{%0,%1,%2,%3}, {%4,%5,%6,%7}, {%8,%9}, {%0,%1,%2,%3};"
        : "+f"(c[0]), "+f"(c[1]), "+f"(c[2]), "+f"(c[3])
        : "r"(a[0]), "r"(a[1]), "r"(a[2]), "r"(a[3]), "r"(b[0]), "r"(b[1]));
}
__device__ __forceinline__ void sts16(uint32_t a, uint32_t x, uint32_t y,
                                      uint32_t z, uint32_t w) {
    asm volatile("st.shared.v4.b32 [%0], {%1,%2,%3,%4};"
                 :: "r"(a), "r"(x), "r"(y), "r"(z), "r"(w) : "memory");
}
__device__ __forceinline__ void red2(float* addr, float x, float y) {
    asm volatile("red.global.add.v2.f32 [%0], {%1,%2};"
                 :: "l"(addr), "f"(x), "f"(y) : "memory");
}

// ---------------- weight prep ----------------
__global__ void prep_bt_k(const float* __restrict__ W, __nv_bfloat16* __restrict__ out,
                          int Ksrc, int Nsrc, int KP, int Nrows) {
    int idx = blockIdx.x * 256 + threadIdx.x;
    if (idx >= Nrows * KP) return;
    int n = idx / KP, k = idx - n * KP;
    float v = (k < Ksrc && n < Nsrc) ? W[(size_t)k * Nsrc + n] : 0.f;
    __nv_bfloat16 hi = __float2bfloat16(v);
    size_t base = (size_t)n * (2 * KP);
    out[base + k] = hi;
    out[base + KP + k] = __float2bfloat16(v - __bfloat162float(hi));
}

__global__ void pad_k(const float* __restrict__ in, float* __restrict__ out,
                      int IC, int OC) {
    int idx = blockIdx.x * blockDim.x + threadIdx.x;
    if (idx >= OC) return;
    out[idx] = (idx < IC) ? in[idx] : 0.f;
}

__global__ void count_k(const int* __restrict__ batch, float* __restrict__ cnt) {
    int a = blockIdx.x * blockDim.x + threadIdx.x;
    if (a < NAT) atomicAdd(&cnt[batch[a]], 1.f);
}

// ---------------- fused GEMM (BM=64, BN=N) ----------------
// AMODE: 0 plain A1[r*KP+k]
//        1 h0 concat-gather: k<72 ? V[g[r]*72+k] : (k<86 ? E[r*14+k-72] : 0)
//        2 message:       Mv[g[r]*320+k] -      H[(r^1)*320+k]
//        5 message+relu:  Mv[g[r]*320+k] - relu(H[(r^1)*320+k])
//        3 wo concat: k<72 ? V[r*72+k] : (k<372 ? Mv[r*320+k-72] : 0)
// EPI:   0 C=acc+aux[c] ; 1 C=relu(acc+aux[c]) ;
//        2 v=relu(acc+aux[r*N+c]); C=v; scatter v ;
//        3 C=acc; scatter relu(acc) ;
//        4 v=relu(acc+aux[r*N+c]); scatter only ;
//        5 v=relu(acc+aux[c])/cnt[sidx[r]]; scatter only (cnt passed via C2)
template<int AMODE>
__device__ __forceinline__ void loadA8(const float* __restrict__ A1,
                                       const float* __restrict__ A2,
                                       long long row, int s, int k0,
                                       int KP, float* va) {
    if (AMODE == 0) {
        const float4* p = (const float4*)(A1 + row * KP + k0);
        float4 a = p[0], b = p[1];
        va[0]=a.x; va[1]=a.y; va[2]=a.z; va[3]=a.w;
        va[4]=b.x; va[5]=b.y; va[6]=b.z; va[7]=b.w;
    } else if (AMODE == 2 || AMODE == 5) {
        const float4* pm = (const float4*)(A1 + (size_t)s * DHP + k0);
        const float4* ph = (const float4*)(A2 + (size_t)(row ^ 1) * DHP + k0);
#pragma unroll
        for (int i = 0; i < 2; i++) {
            float4 m = pm[i], h = ph[i];
            if (AMODE == 5) {
                h.x = fmaxf(h.x, 0.f); h.y = fmaxf(h.y, 0.f);
                h.z = fmaxf(h.z, 0.f); h.w = fmaxf(h.w, 0.f);
            }
            va[4*i]   = m.x - h.x; va[4*i+1] = m.y - h.y;
            va[4*i+2] = m.z - h.z; va[4*i+3] = m.w - h.w;
        }
    } else if (AMODE == 1) {
#pragma unroll
        for (int j = 0; j < 8; j++) {
            int k = k0 + j;
            va[j] = (k < 72) ? A1[(size_t)s * 72 + k]
                             : (k < 86 ? A2[row * 14 + (k - 72)] : 0.f);
        }
    } else { // AMODE 3
#pragma unroll
        for (int j = 0; j < 8; j++) {
            int k = k0 + j;
            va[j] = (k < 72) ? A1[row * 72 + k]
                             : (k < 372 ? A2[row * DHP + (k - 72)] : 0.f);
        }
    }
}

__device__ __forceinline__ void storeA8(uint32_t ahi, uint32_t alo, const float* va) {
    uint32_t h[4], l[4];
#pragma unroll
    for (int j = 0; j < 4; j++) {
        float a = va[2*j], b = va[2*j+1];
        __nv_bfloat16 ha = __float2bfloat16(a), hb = __float2bfloat16(b);
        __nv_bfloat162 hp; hp.x = ha; hp.y = hb;
        h[j] = *(uint32_t*)&hp;
        __nv_bfloat162 lp = __floats2bfloat162_rn(a - __bfloat162float(ha),
                                                  b - __bfloat162float(hb));
        l[j] = *(uint32_t*)&lp;
    }
    sts16(ahi, h[0], h[1], h[2], h[3]);
    sts16(alo, l[0], l[1], l[2], l[3]);
}

template<int AMODE, int EPI, int BN>
__global__ void __launch_bounds__(256, 1)
gemm_f(const float* __restrict__ A1, const float* __restrict__ A2,
       const int* __restrict__ gidx,
       const __nv_bfloat16* __restrict__ Bt, int KP,
       const float* __restrict__ aux,
       const int* __restrict__ sidx, float* __restrict__ S,
       float* __restrict__ C, float* __restrict__ C2, int N) {
    constexpr int NT = BN / 32;                 // n-tiles (8 cols) per warp
    constexpr int RS = 80;
    constexpr int ABUF = 64 * RS;
    constexpr int BBUF = BN * RS;
    constexpr int STG = 2 * ABUF + 2 * BBUF;    // [Ahi][Alo][Bhi][Blo]
    extern __shared__ __align__(16) char sm[];
    const uint32_t sbase = smem_u32(sm);

    const int tid = threadIdx.x;
    const int wid = tid >> 5, lane = tid & 31;
    const int wm = wid & 1, wn = wid >> 1;
    const long long bm = (long long)blockIdx.y * 64;
    const int nW = KP >> 5;
    const int ldb = 2 * KP;

    const int arow = tid >> 2;                  // 0..63
    const int kh = (tid & 3) * 8;               // 0,8,16,24
    const long long grow = bm + arow;
    const int s = (AMODE == 1 || AMODE == 2 || AMODE == 5) ? gidx[grow] : 0;

    float acc[2][NT][4];
#pragma unroll
    for (int i = 0; i < 2; i++)
#pragma unroll
        for (int j = 0; j < NT; j++)
#pragma unroll
            for (int t = 0; t < 4; t++) acc[i][j][t] = 0.f;

    const int aRow = (lane & 7) + ((lane >> 3) & 1) * 8;
    const int aK   = (lane >> 4) * 8;
    const int bRow4 = (lane & 7) + ((lane >> 4) << 3);
    const int bK4   = ((lane >> 3) & 1) * 8;

    auto loadB = [&](int w, int buf) {
        const uint32_t bhi = sbase + buf * STG + 2 * ABUF;
        for (int idx = tid; idx < BN * 4; idx += 256) {
            int row = idx >> 2, sg = idx & 3;
            cpa16(bhi + row * RS + sg * 16,
                  Bt + (size_t)row * ldb + w * 32 + sg * 8);
        }
        for (int idx = tid; idx < BN * 4; idx += 256) {
            int row = idx >> 2, sg = idx & 3;
            cpa16(bhi + BBUF + row * RS + sg * 16,
                  Bt + (size_t)row * ldb + KP + w * 32 + sg * 8);
        }
    };

    // prologue: window 0
    {
        float va[8];
        loadA8<AMODE>(A1, A2, grow, s, kh, KP, va);
        uint32_t ah = sbase + arow * RS + kh * 2;
        storeA8(ah, ah + ABUF, va);
        loadB(0, 0);
        cp_commit();
    }

    for (int w = 0; w < nW; ++w) {
        const int buf = w & 1;
        const bool more = (w + 1 < nW);
        float va[8];
        if (more) {
            loadA8<AMODE>(A1, A2, grow, s, (w + 1) * 32 + kh, KP, va);
            loadB(w + 1, buf ^ 1);
            cp_commit();
        }
        if (more) cp_wait<1>(); else cp_wait<0>();
        __syncthreads();
        const uint32_t as = sbase + buf * STG;
        const uint32_t bs = as + 2 * ABUF;
#pragma unroll
        for (int ks = 0; ks < 32; ks += 16) {
            uint32_t afh[2][4], afl[2][4];
#pragma unroll
            for (int mt = 0; mt < 2; ++mt) {
                uint32_t ar = as + (wm * 32 + mt * 16 + aRow) * RS + (ks + aK) * 2;
                ldsm4(afh[mt], ar);
                ldsm4(afl[mt], ar + ABUF);
            }
#pragma unroll
            for (int ntp = 0; ntp < NT / 2; ++ntp) {
                uint32_t bh4[4], bl4[4];
                uint32_t br = bs + (wn * NT * 8 + ntp * 16 + bRow4) * RS + (ks + bK4) * 2;
                ldsm4(bh4, br);
                ldsm4(bl4, br + BBUF);
#pragma unroll
                for (int mt = 0; mt < 2; ++mt)
#pragma unroll
                    for (int h = 0; h < 2; ++h) {
                        mma16816(acc[mt][ntp*2 + h], afh[mt], bh4 + h*2);
                        mma16816(acc[mt][ntp*2 + h], afl[mt], bh4 + h*2);
                        mma16816(acc[mt][ntp*2 + h], afh[mt], bl4 + h*2);
                    }
            }
        }
        if (more) {
            uint32_t ah = sbase + (buf ^ 1) * STG + arow * RS + kh * 2;
            storeA8(ah, ah + ABUF, va);
        }
        __syncthreads();
    }

    // ---- epilogue ----
    const int gid = lane >> 2, tig = lane & 3;
#pragma unroll
    for (int mt = 0; mt < 2; ++mt) {
        const long long r0 = bm + wm * 32 + mt * 16 + gid;
        const long long r1 = r0 + 8;
        int si0 = 0, si1 = 0;
        float inv0 = 1.f, inv1 = 1.f;
        if (EPI >= 2) { si0 = sidx[r0]; si1 = sidx[r1]; }
        if (EPI == 5) {
            inv0 = 1.f / fmaxf(C2[si0], 1.f);
            inv1 = 1.f / fmaxf(C2[si1], 1.f);
        }
#pragma unroll
        for (int nt = 0; nt < NT; ++nt) {
            const int c0 = wn * NT * 8 + nt * 8 + tig * 2;
            float v00 = acc[mt][nt][0], v01 = acc[mt][nt][1];
            float v10 = acc[mt][nt][2], v11 = acc[mt][nt][3];
            float r00, r01, r10, r11;
            if (EPI == 0 || EPI == 1 || EPI == 5) {
                float2 ax = *(const float2*)(aux + c0);
                r00 = v00 + ax.x; r01 = v01 + ax.y;
                r10 = v10 + ax.x; r11 = v11 + ax.y;
            } else if (EPI == 2 || EPI == 4) {
                float2 a0 = *(const float2*)(aux + r0 * N + c0);
                float2 a1 = *(const float2*)(aux + r1 * N + c0);
                r00 = v00 + a0.x; r01 = v01 + a0.y;
                r10 = v10 + a1.x; r11 = v11 + a1.y;
            } else { // EPI==3
                r00 = v00; r01 = v01; r10 = v10; r11 = v11;
            }
            if (EPI != 0) {
                r00 = fmaxf(r00, 0.f); r01 = fmaxf(r01, 0.f);
                r10 = fmaxf(r10, 0.f); r11 = fmaxf(r11, 0.f);
            }
            if (EPI == 5) {
                r00 *= inv0; r01 *= inv0; r10 *= inv1; r11 *= inv1;
            }
            if (EPI == 0 || EPI == 1 || EPI == 2) {
                *(float2*)(C + r0 * N + c0) = make_float2(r00, r01);
                *(float2*)(C + r1 * N + c0) = make_float2(r10, r11);
            } else if (EPI == 3) {
                *(float2*)(C + r0 * N + c0) = make_float2(v00, v01);
                *(float2*)(C + r1 * N + c0) = make_float2(v10, v11);
            }
            if (EPI >= 2) {
                float* s0 = S + (size_t)si0 * DHP + c0;
                float* s1 = S + (size_t)si1 * DHP + c0;
                if (r00 != 0.f || r01 != 0.f) red2(s0, r00, r01);
                if (r10 != 0.f || r11 != 0.f) red2(s1, r10, r11);
            }
        }
    }
}

// ---------------- launcher ----------------
extern "C" void kernel_launch(void* const* d_in, const int* in_sizes, int n_in,
                              void* d_out, int out_size) {
    const float* V    = (const float*)d_in[0];
    const float* E    = (const float*)d_in[1];
    const int*   esrc = (const int*)d_in[2];
    const int*   edst = (const int*)d_in[3];
    const int*   batc = (const int*)d_in[5];
    int wi = 6;
    if (n_in >= 15 && in_sizes[6] == 1) wi = 7;
    const float* W_i = (const float*)d_in[wi + 0];
    const float* W_h = (const float*)d_in[wi + 1];
    const float* W_o = (const float*)d_in[wi + 2];
    const float* b_o = (const float*)d_in[wi + 3];
    const float* W1  = (const float*)d_in[wi + 4];
    const float* b1  = (const float*)d_in[wi + 5];
    const float* W2  = (const float*)d_in[wi + 6];
    const float* b2  = (const float*)d_in[wi + 7];
    float* out = (float*)d_out;

    float *H0, *Hb, *Mv1, *Mv2, *Z, *cnt, *T, *bo;
    __nv_bfloat16 *Bh0, *Bh, *Bo, *B1, *B2;
    cudaGetSymbolAddress((void**)&H0,  g_H0);
    cudaGetSymbolAddress((void**)&Hb,  g_Hb);
    cudaGetSymbolAddress((void**)&Mv1, g_Mv1);
    cudaGetSymbolAddress((void**)&Mv2, g_Mv2);
    cudaGetSymbolAddress((void**)&Z,   g_Z);
    cudaGetSymbolAddress((void**)&cnt, g_cnt);
    cudaGetSymbolAddress((void**)&T,   g_T);
    cudaGetSymbolAddress((void**)&bo,  g_bo);
    cudaGetSymbolAddress((void**)&Bh0, g_Bh0);
    cudaGetSymbolAddress((void**)&Bh,  g_Bh);
    cudaGetSymbolAddress((void**)&Bo,  g_Bo);
    cudaGetSymbolAddress((void**)&B1,  g_B1);
    cudaGetSymbolAddress((void**)&B2,  g_B2);

    const int SMF320 = 2 * (2 * 64 * 80 + 2 * 320 * 80);  // 122880
    const int SMF256 = 2 * (2 * 64 * 80 + 2 * 256 * 80);  // 102400
    cudaFuncSetAttribute(gemm_f<1,3,320>, cudaFuncAttributeMaxDynamicSharedMemorySize, SMF320);
    cudaFuncSetAttribute(gemm_f<5,2,320>, cudaFuncAttributeMaxDynamicSharedMemorySize, SMF320);
    cudaFuncSetAttribute(gemm_f<2,4,320>, cudaFuncAttributeMaxDynamicSharedMemorySize, SMF320);
    cudaFuncSetAttribute(gemm_f<3,5,320>, cudaFuncAttributeMaxDynamicSharedMemorySize, SMF320);
    cudaFuncSetAttribute(gemm_f<0,1,256>, cudaFuncAttributeMaxDynamicSharedMemorySize, SMF256);
    cudaFuncSetAttribute(gemm_f<0,0,256>, cudaFuncAttributeMaxDynamicSharedMemorySize, SMF256);

    // weight prep (transpose + split)
    prep_bt_k<<<(320 * 96  + 255) / 256, 256>>>(W_i, Bh0, 86,  300, 96,  320);
    prep_bt_k<<<(320 * 320 + 255) / 256, 256>>>(W_h, Bh,  300, 300, 320, 320);
    prep_bt_k<<<(320 * 384 + 255) / 256, 256>>>(W_o, Bo,  372, 300, 384, 320);
    prep_bt_k<<<(256 * 320 + 255) / 256, 256>>>(W1,  B1,  300, 256, 320, 256);
    prep_bt_k<<<(256 * 256 + 255) / 256, 256>>>(W2,  B2,  256, 256, 256, 256);
    pad_k<<<2, 256>>>(b_o, bo, 300, DHP);

    const size_t MVB = (size_t)NAT * DHP * sizeof(float);
    cudaMemsetAsync(cnt, 0, (size_t)NMO * sizeof(float));
    count_k<<<(NAT + 255) / 256, 256>>>(batc, cnt);
    cudaMemsetAsync(Mv1, 0, MVB);
    cudaMemsetAsync(Mv2, 0, MVB);
    cudaMemsetAsync(Z, 0, (size_t)NMO * DHP * sizeof(float));

    // 1. H0 = concat(V[src],E)@W_i (store pre-relu) ; scatter relu -> Mv1
    gemm_f<1,3,320><<<dim3(1, NBO / 64), 256, SMF320>>>(
        V, E, esrc, Bh0, 96, nullptr, edst, Mv1, H0, nullptr, DHP);

    // 2. iter1: Hb = relu(H0 + (Mv1[src]-relu(H0)[rev])@Wh) ; scatter -> Mv2
    gemm_f<5,2,320><<<dim3(1, NBO / 64), 256, SMF320>>>(
        Mv1, H0, esrc, Bh, 320, H0, edst, Mv2, Hb, nullptr, DHP);

    // 3. iter2: relu(H0 + (Mv2[src]-Hb[rev])@Wh) scattered -> Mv1 (no store)
    cudaMemsetAsync(Mv1, 0, MVB);
    gemm_f<2,4,320><<<dim3(1, NBO / 64), 256, SMF320>>>(
        Mv2, Hb, esrc, Bh, 320, H0, edst, Mv1, nullptr, nullptr, DHP);

    // 4. relu(concat(V,Mv1)@Wo + bo) / cnt pooled -> Z (mean fused)
    gemm_f<3,5,320><<<dim3(1, NAT / 64), 256, SMF320>>>(
        V, Mv1, nullptr, Bo, 384, bo, batc, Z, nullptr, cnt, DHP);

    // 5. T = relu(Z@W1+b1)
    gemm_f<0,1,256><<<dim3(1, NMO / 64), 256, SMF256>>>(
        Z, nullptr, nullptr, B1, 320, b1, nullptr, nullptr, T, nullptr, DEM);

    // 6. out = T@W2+b2
    gemm_f<0,0,256><<<dim3(1, NMO / 64), 256, SMF256>>>(
        T, nullptr, nullptr, B2, 256, b2, nullptr, nullptr, out, nullptr, DEM);
}

// round 10
// speedup vs baseline: 3.9837x; 1.2514x over previous
#include <cuda_runtime.h>
#include <cuda_fp16.h>
#include <cstdint>
#include <cstddef>

#define NAT 131072
#define NBO 262144
#define NMO 4096
#define DHP 320
#define DEM 256

// ---------------- scratch (device globals; no allocation) ----------------
__device__ float g_H0[(size_t)NBO * DHP];
__device__ float g_Hb[(size_t)NBO * DHP];
__device__ float g_Mv1[(size_t)NAT * DHP];
__device__ float g_Mv2[(size_t)NAT * DHP];
__device__ float g_Z [(size_t)NMO * DHP];
__device__ float g_cnt[NMO];
__device__ float g_T [(size_t)NMO * DEM];
__device__ float g_bo[DHP];
__device__ __align__(16) __half g_Bh0[320 * 96];
__device__ __align__(16) __half g_Bh [320 * 320];
__device__ __align__(16) __half g_Bo [320 * 384];
__device__ __align__(16) __half g_B1 [256 * 320];
__device__ __align__(16) __half g_B2 [256 * 256];

// ---------------- PTX helpers ----------------
__device__ __forceinline__ uint32_t smem_u32(const void* p) {
    uint32_t a;
    asm("{ .reg .u64 t; cvta.to.shared.u64 t, %1; cvt.u32.u64 %0, t; }"
        : "=r"(a) : "l"(p));
    return a;
}
__device__ __forceinline__ void cpa16(uint32_t dst, const void* src) {
    asm volatile("cp.async.cg.shared.global [%0], [%1], 16;"
                 :: "r"(dst), "l"(src) : "memory");
}
__device__ __forceinline__ void cp_commit() {
    asm volatile("cp.async.commit_group;" ::: "memory");
}
template<int N>
__device__ __forceinline__ void cp_wait() {
    asm volatile("cp.async.wait_group %0;" :: "n"(N) : "memory");
}
__device__ __forceinline__ void ldsm4(uint32_t* r, uint32_t a) {
    asm volatile("ldmatrix.sync.aligned.m8n8.x4.shared.b16 {%0,%1,%2,%3}, [%4];"
                 : "=r"(r[0]), "=r"(r[1]), "=r"(r[2]), "=r"(r[3]) : "r"(a));
}
__device__ __forceinline__ void mma16816(float* c, const uint32_t* a, const uint32_t* b) {
    asm volatile(
        "mma.sync.aligned.m16n8k16.row.col.f32.f16.f16.f32 "
        "{%0,%1,%2,%3}, {%4,%5,%6,%7}, {%8,%9}, {%0,%1,%2,%3};"
        : "+f"(c[0]), "+f"(c[1]), "+f"(c[2]), "+f"(c[3])
        : "r"(a[0]), "r"(a[1]), "r"(a[2]), "r"(a[3]), "r"(b[0]), "r"(b[1]));
}
__device__ __forceinline__ void sts16(uint32_t a, uint32_t x, uint32_t y,
                                      uint32_t z, uint32_t w) {
    asm volatile("st.shared.v4.b32 [%0], {%1,%2,%3,%4};"
                 :: "r"(a), "r"(x), "r"(y), "r"(z), "r"(w) : "memory");
}
__device__ __forceinline__ void red2(float* addr, float x, float y) {
    asm volatile("red.global.add.v2.f32 [%0], {%1,%2};"
                 :: "l"(addr), "f"(x), "f"(y) : "memory");
}

// ---------------- weight prep (transpose + fp16 round) ----------------
__global__ void prep_bt_k(const float* __restrict__ W, __half* __restrict__ out,
                          int Ksrc, int Nsrc, int KP, int Nrows) {
    int idx = blockIdx.x * 256 + threadIdx.x;
    if (idx >= Nrows * KP) return;
    int n = idx / KP, k = idx - n * KP;
    float v = (k < Ksrc && n < Nsrc) ? W[(size_t)k * Nsrc + n] : 0.f;
    out[(size_t)n * KP + k] = __float2half_rn(v);
}

__global__ void pad_k(const float* __restrict__ in, float* __restrict__ out,
                      int IC, int OC) {
    int idx = blockIdx.x * blockDim.x + threadIdx.x;
    if (idx >= OC) return;
    out[idx] = (idx < IC) ? in[idx] : 0.f;
}

__global__ void count_k(const int* __restrict__ batch, float* __restrict__ cnt) {
    int a = blockIdx.x * blockDim.x + threadIdx.x;
    if (a < NAT) atomicAdd(&cnt[batch[a]], 1.f);
}

// ---------------- fused GEMM (BM=64, BN=N, fp16 2-pass split) ----------------
// AMODE: 0 plain ; 1 h0 concat-gather ; 2 message ; 5 message+relu ; 3 wo concat
// EPI:   0 C=acc+aux[c] ; 1 C=relu(acc+aux[c]) ;
//        2 v=relu(acc+aux[r*N+c]); C=v; scatter v ;
//        3 C=acc; scatter relu(acc) ;
//        4 v=relu(acc+aux[r*N+c]); scatter only ;
//        5 v=relu(acc+aux[c])/cnt[sidx[r]]; scatter only (cnt via C2)
template<int AMODE>
__device__ __forceinline__ void loadA8(const float* __restrict__ A1,
                                       const float* __restrict__ A2,
                                       long long row, int s, int k0,
                                       int KP, float* va) {
    if (AMODE == 0) {
        const float4* p = (const float4*)(A1 + row * KP + k0);
        float4 a = p[0], b = p[1];
        va[0]=a.x; va[1]=a.y; va[2]=a.z; va[3]=a.w;
        va[4]=b.x; va[5]=b.y; va[6]=b.z; va[7]=b.w;
    } else if (AMODE == 2 || AMODE == 5) {
        const float4* pm = (const float4*)(A1 + (size_t)s * DHP + k0);
        const float4* ph = (const float4*)(A2 + (size_t)(row ^ 1) * DHP + k0);
#pragma unroll
        for (int i = 0; i < 2; i++) {
            float4 m = pm[i], h = ph[i];
            if (AMODE == 5) {
                h.x = fmaxf(h.x, 0.f); h.y = fmaxf(h.y, 0.f);
                h.z = fmaxf(h.z, 0.f); h.w = fmaxf(h.w, 0.f);
            }
            va[4*i]   = m.x - h.x; va[4*i+1] = m.y - h.y;
            va[4*i+2] = m.z - h.z; va[4*i+3] = m.w - h.w;
        }
    } else if (AMODE == 1) {
#pragma unroll
        for (int j = 0; j < 8; j++) {
            int k = k0 + j;
            va[j] = (k < 72) ? A1[(size_t)s * 72 + k]
                             : (k < 86 ? A2[row * 14 + (k - 72)] : 0.f);
        }
    } else { // AMODE 3
#pragma unroll
        for (int j = 0; j < 8; j++) {
            int k = k0 + j;
            va[j] = (k < 72) ? A1[row * 72 + k]
                             : (k < 372 ? A2[row * DHP + (k - 72)] : 0.f);
        }
    }
}

__device__ __forceinline__ void storeA8(uint32_t ahi, uint32_t alo, const float* va) {
    uint32_t h[4], l[4];
#pragma unroll
    for (int j = 0; j < 4; j++) {
        float a = va[2*j], b = va[2*j+1];
        __half ha = __float2half_rn(a), hb = __float2half_rn(b);
        __half2 hp; hp.x = ha; hp.y = hb;
        h[j] = *(uint32_t*)&hp;
        __half la = __float2half_rn(a - __half2float(ha));
        __half lb = __float2half_rn(b - __half2float(hb));
        __half2 lp; lp.x = la; lp.y = lb;
        l[j] = *(uint32_t*)&lp;
    }
    sts16(ahi, h[0], h[1], h[2], h[3]);
    sts16(alo, l[0], l[1], l[2], l[3]);
}

template<int AMODE, int EPI, int BN>
__global__ void __launch_bounds__(256, 1)
gemm_f(const float* __restrict__ A1, const float* __restrict__ A2,
       const int* __restrict__ gidx,
       const __half* __restrict__ Bt, int KP,
       const float* __restrict__ aux,
       const int* __restrict__ sidx, float* __restrict__ S,
       float* __restrict__ C, float* __restrict__ C2, int N) {
    constexpr int NT = BN / 32;                 // n-tiles (8 cols) per warp
    constexpr int RS = 80;
    constexpr int ABUF = 64 * RS;
    constexpr int BBUF = BN * RS;
    constexpr int STG = 2 * ABUF + BBUF;        // [Ahi][Alo][Bhi]
    extern __shared__ __align__(16) char sm[];
    const uint32_t sbase = smem_u32(sm);

    const int tid = threadIdx.x;
    const int wid = tid >> 5, lane = tid & 31;
    const int wm = wid & 1, wn = wid >> 1;
    const long long bm = (long long)blockIdx.y * 64;
    const int nW = KP >> 5;

    const int arow = tid >> 2;                  // 0..63
    const int kh = (tid & 3) * 8;               // 0,8,16,24
    const long long grow = bm + arow;
    const int s = (AMODE == 1 || AMODE == 2 || AMODE == 5) ? gidx[grow] : 0;

    float acc[2][NT][4];
#pragma unroll
    for (int i = 0; i < 2; i++)
#pragma unroll
        for (int j = 0; j < NT; j++)
#pragma unroll
            for (int t = 0; t < 4; t++) acc[i][j][t] = 0.f;

    const int aRow = (lane & 7) + ((lane >> 3) & 1) * 8;
    const int aK   = (lane >> 4) * 8;
    const int bRow4 = (lane & 7) + ((lane >> 4) << 3);
    const int bK4   = ((lane >> 3) & 1) * 8;

    auto loadB = [&](int w, int buf) {
        const uint32_t bhi = sbase + buf * STG + 2 * ABUF;
        for (int idx = tid; idx < BN * 4; idx += 256) {
            int row = idx >> 2, sg = idx & 3;
            cpa16(bhi + row * RS + sg * 16,
                  Bt + (size_t)row * KP + w * 32 + sg * 8);
        }
    };

    // prologue: window 0
    {
        float va[8];
        loadA8<AMODE>(A1, A2, grow, s, kh, KP, va);
        uint32_t ah = sbase + arow * RS + kh * 2;
        storeA8(ah, ah + ABUF, va);
        loadB(0, 0);
        cp_commit();
    }

    for (int w = 0; w < nW; ++w) {
        const int buf = w & 1;
        const bool more = (w + 1 < nW);
        float va[8];
        if (more) {
            loadA8<AMODE>(A1, A2, grow, s, (w + 1) * 32 + kh, KP, va);
            loadB(w + 1, buf ^ 1);
            cp_commit();
        }
        if (more) cp_wait<1>(); else cp_wait<0>();
        __syncthreads();
        const uint32_t as = sbase + buf * STG;
        const uint32_t bs = as + 2 * ABUF;
#pragma unroll
        for (int ks = 0; ks < 32; ks += 16) {
            uint32_t afh[2][4], afl[2][4];
#pragma unroll
            for (int mt = 0; mt < 2; ++mt) {
                uint32_t ar = as + (wm * 32 + mt * 16 + aRow) * RS + (ks + aK) * 2;
                ldsm4(afh[mt], ar);
                ldsm4(afl[mt], ar + ABUF);
            }
#pragma unroll
            for (int ntp = 0; ntp < NT / 2; ++ntp) {
                uint32_t bh4[4];
                uint32_t br = bs + (wn * NT * 8 + ntp * 16 + bRow4) * RS + (ks + bK4) * 2;
                ldsm4(bh4, br);
#pragma unroll
                for (int mt = 0; mt < 2; ++mt)
#pragma unroll
                    for (int h = 0; h < 2; ++h) {
                        mma16816(acc[mt][ntp*2 + h], afh[mt], bh4 + h*2);
                        mma16816(acc[mt][ntp*2 + h], afl[mt], bh4 + h*2);
                    }
            }
        }
        if (more) {
            uint32_t ah = sbase + (buf ^ 1) * STG + arow * RS + kh * 2;
            storeA8(ah, ah + ABUF, va);
        }
        __syncthreads();
    }

    // ---- epilogue ----
    const int gid = lane >> 2, tig = lane & 3;
#pragma unroll
    for (int mt = 0; mt < 2; ++mt) {
        const long long r0 = bm + wm * 32 + mt * 16 + gid;
        const long long r1 = r0 + 8;
        int si0 = 0, si1 = 0;
        float inv0 = 1.f, inv1 = 1.f;
        if (EPI >= 2) { si0 = sidx[r0]; si1 = sidx[r1]; }
        if (EPI == 5) {
            inv0 = 1.f / fmaxf(C2[si0], 1.f);
            inv1 = 1.f / fmaxf(C2[si1], 1.f);
        }
#pragma unroll
        for (int nt = 0; nt < NT; ++nt) {
            const int c0 = wn * NT * 8 + nt * 8 + tig * 2;
            float v00 = acc[mt][nt][0], v01 = acc[mt][nt][1];
            float v10 = acc[mt][nt][2], v11 = acc[mt][nt][3];
            float r00, r01, r10, r11;
            if (EPI == 0 || EPI == 1 || EPI == 5) {
                float2 ax = *(const float2*)(aux + c0);
                r00 = v00 + ax.x; r01 = v01 + ax.y;
                r10 = v10 + ax.x; r11 = v11 + ax.y;
            } else if (EPI == 2 || EPI == 4) {
                float2 a0 = *(const float2*)(aux + r0 * N + c0);
                float2 a1 = *(const float2*)(aux + r1 * N + c0);
                r00 = v00 + a0.x; r01 = v01 + a0.y;
                r10 = v10 + a1.x; r11 = v11 + a1.y;
            } else { // EPI==3
                r00 = v00; r01 = v01; r10 = v10; r11 = v11;
            }
            if (EPI != 0) {
                r00 = fmaxf(r00, 0.f); r01 = fmaxf(r01, 0.f);
                r10 = fmaxf(r10, 0.f); r11 = fmaxf(r11, 0.f);
            }
            if (EPI == 5) {
                r00 *= inv0; r01 *= inv0; r10 *= inv1; r11 *= inv1;
            }
            if (EPI == 0 || EPI == 1 || EPI == 2) {
                *(float2*)(C + r0 * N + c0) = make_float2(r00, r01);
                *(float2*)(C + r1 * N + c0) = make_float2(r10, r11);
            } else if (EPI == 3) {
                *(float2*)(C + r0 * N + c0) = make_float2(v00, v01);
                *(float2*)(C + r1 * N + c0) = make_float2(v10, v11);
            }
            if (EPI >= 2) {
                float* s0 = S + (size_t)si0 * DHP + c0;
                float* s1 = S + (size_t)si1 * DHP + c0;
                if (r00 != 0.f || r01 != 0.f) red2(s0, r00, r01);
                if (r10 != 0.f || r11 != 0.f) red2(s1, r10, r11);
            }
        }
    }
}

// ---------------- launcher ----------------
extern "C" void kernel_launch(void* const* d_in, const int* in_sizes, int n_in,
                              void* d_out, int out_size) {
    const float* V    = (const float*)d_in[0];
    const float* E    = (const float*)d_in[1];
    const int*   esrc = (const int*)d_in[2];
    const int*   edst = (const int*)d_in[3];
    const int*   batc = (const int*)d_in[5];
    int wi = 6;
    if (n_in >= 15 && in_sizes[6] == 1) wi = 7;
    const float* W_i = (const float*)d_in[wi + 0];
    const float* W_h = (const float*)d_in[wi + 1];
    const float* W_o = (const float*)d_in[wi + 2];
    const float* b_o = (const float*)d_in[wi + 3];
    const float* W1  = (const float*)d_in[wi + 4];
    const float* b1  = (const float*)d_in[wi + 5];
    const float* W2  = (const float*)d_in[wi + 6];
    const float* b2  = (const float*)d_in[wi + 7];
    float* out = (float*)d_out;

    float *H0, *Hb, *Mv1, *Mv2, *Z, *cnt, *T, *bo;
    __half *Bh0, *Bh, *Bo, *B1, *B2;
    cudaGetSymbolAddress((void**)&H0,  g_H0);
    cudaGetSymbolAddress((void**)&Hb,  g_Hb);
    cudaGetSymbolAddress((void**)&Mv1, g_Mv1);
    cudaGetSymbolAddress((void**)&Mv2, g_Mv2);
    cudaGetSymbolAddress((void**)&Z,   g_Z);
    cudaGetSymbolAddress((void**)&cnt, g_cnt);
    cudaGetSymbolAddress((void**)&T,   g_T);
    cudaGetSymbolAddress((void**)&bo,  g_bo);
    cudaGetSymbolAddress((void**)&Bh0, g_Bh0);
    cudaGetSymbolAddress((void**)&Bh,  g_Bh);
    cudaGetSymbolAddress((void**)&Bo,  g_Bo);
    cudaGetSymbolAddress((void**)&B1,  g_B1);
    cudaGetSymbolAddress((void**)&B2,  g_B2);

    const int SMF320 = 2 * (2 * 64 * 80 + 320 * 80);  // 71680
    const int SMF256 = 2 * (2 * 64 * 80 + 256 * 80);  // 61440
    cudaFuncSetAttribute(gemm_f<1,3,320>, cudaFuncAttributeMaxDynamicSharedMemorySize, SMF320);
    cudaFuncSetAttribute(gemm_f<5,2,320>, cudaFuncAttributeMaxDynamicSharedMemorySize, SMF320);
    cudaFuncSetAttribute(gemm_f<2,4,320>, cudaFuncAttributeMaxDynamicSharedMemorySize, SMF320);
    cudaFuncSetAttribute(gemm_f<3,5,320>, cudaFuncAttributeMaxDynamicSharedMemorySize, SMF320);
    cudaFuncSetAttribute(gemm_f<0,1,256>, cudaFuncAttributeMaxDynamicSharedMemorySize, SMF256);
    cudaFuncSetAttribute(gemm_f<0,0,256>, cudaFuncAttributeMaxDynamicSharedMemorySize, SMF256);

    // weight prep (transpose + fp16)
    prep_bt_k<<<(320 * 96  + 255) / 256, 256>>>(W_i, Bh0, 86,  300, 96,  320);
    prep_bt_k<<<(320 * 320 + 255) / 256, 256>>>(W_h, Bh,  300, 300, 320, 320);
    prep_bt_k<<<(320 * 384 + 255) / 256, 256>>>(W_o, Bo,  372, 300, 384, 320);
    prep_bt_k<<<(256 * 320 + 255) / 256, 256>>>(W1,  B1,  300, 256, 320, 256);
    prep_bt_k<<<(256 * 256 + 255) / 256, 256>>>(W2,  B2,  256, 256, 256, 256);
    pad_k<<<2, 256>>>(b_o, bo, 300, DHP);

    const size_t MVB = (size_t)NAT * DHP * sizeof(float);
    cudaMemsetAsync(cnt, 0, (size_t)NMO * sizeof(float));
    count_k<<<(NAT + 255) / 256, 256>>>(batc, cnt);
    cudaMemsetAsync(Mv1, 0, MVB);
    cudaMemsetAsync(Mv2, 0, MVB);
    cudaMemsetAsync(Z, 0, (size_t)NMO * DHP * sizeof(float));

    // 1. H0 = concat(V[src],E)@W_i (store pre-relu) ; scatter relu -> Mv1
    gemm_f<1,3,320><<<dim3(1, NBO / 64), 256, SMF320>>>(
        V, E, esrc, Bh0, 96, nullptr, edst, Mv1, H0, nullptr, DHP);

    // 2. iter1: Hb = relu(H0 + (Mv1[src]-relu(H0)[rev])@Wh) ; scatter -> Mv2
    gemm_f<5,2,320><<<dim3(1, NBO / 64), 256, SMF320>>>(
        Mv1, H0, esrc, Bh, 320, H0, edst, Mv2, Hb, nullptr, DHP);

    // 3. iter2: relu(H0 + (Mv2[src]-Hb[rev])@Wh) scattered -> Mv1 (no store)
    cudaMemsetAsync(Mv1, 0, MVB);
    gemm_f<2,4,320><<<dim3(1, NBO / 64), 256, SMF320>>>(
        Mv2, Hb, esrc, Bh, 320, H0, edst, Mv1, nullptr, nullptr, DHP);

    // 4. relu(concat(V,Mv1)@Wo + bo) / cnt pooled -> Z (mean fused)
    gemm_f<3,5,320><<<dim3(1, NAT / 64), 256, SMF320>>>(
        V, Mv1, nullptr, Bo, 384, bo, batc, Z, nullptr, cnt, DHP);

    // 5. T = relu(Z@W1+b1)
    gemm_f<0,1,256><<<dim3(1, NMO / 64), 256, SMF256>>>(
        Z, nullptr, nullptr, B1, 320, b1, nullptr, nullptr, T, nullptr, DEM);

    // 6. out = T@W2+b2
    gemm_f<0,0,256><<<dim3(1, NMO / 64), 256, SMF256>>>(
        T, nullptr, nullptr, B2, 256, b2, nullptr, nullptr, out, nullptr, DEM);
}

// round 11
// speedup vs baseline: 5.4529x; 1.3688x over previous
#include <cuda_runtime.h>
#include <cuda_fp16.h>
#include <cstdint>
#include <cstddef>

#define NAT 131072
#define NBO 262144
#define NMO 4096
#define DHP 320
#define DEM 256

// ---------------- scratch (device globals; no allocation) ----------------
__device__ float g_H0[(size_t)NBO * DHP];
__device__ float g_Hb[(size_t)NBO * DHP];
__device__ float g_Mv1[(size_t)NAT * DHP];
__device__ float g_Mv2[(size_t)NAT * DHP];
__device__ float g_Z [(size_t)NMO * DHP];
__device__ float g_cnt[NMO];
__device__ float g_T [(size_t)NMO * DEM];
__device__ float g_bo[DHP];
__device__ __align__(16) __half g_Bh0[320 * 96];
__device__ __align__(16) __half g_Bh [320 * 320];
__device__ __align__(16) __half g_Bo [320 * 384];
__device__ __align__(16) __half g_B1 [256 * 320];
__device__ __align__(16) __half g_B2 [256 * 256];

// ---------------- PTX helpers ----------------
__device__ __forceinline__ uint32_t smem_u32(const void* p) {
    uint32_t a;
    asm("{ .reg .u64 t; cvta.to.shared.u64 t, %1; cvt.u32.u64 %0, t; }"
        : "=r"(a) : "l"(p));
    return a;
}
__device__ __forceinline__ void cpa16(uint32_t dst, const void* src) {
    asm volatile("cp.async.cg.shared.global [%0], [%1], 16;"
                 :: "r"(dst), "l"(src) : "memory");
}
__device__ __forceinline__ void cp_commit() {
    asm volatile("cp.async.commit_group;" ::: "memory");
}
template<int N>
__device__ __forceinline__ void cp_wait() {
    asm volatile("cp.async.wait_group %0;" :: "n"(N) : "memory");
}
__device__ __forceinline__ void ldsm4(uint32_t* r, uint32_t a) {
    asm volatile("ldmatrix.sync.aligned.m8n8.x4.shared.b16 {%0,%1,%2,%3}, [%4];"
                 : "=r"(r[0]), "=r"(r[1]), "=r"(r[2]), "=r"(r[3]) : "r"(a));
}
__device__ __forceinline__ void mma16816(float* c, const uint32_t* a, const uint32_t* b) {
    asm volatile(
        "mma.sync.aligned.m16n8k16.row.col.f32.f16.f16.f32 "
        "{%0,%1,%2,%3}, {%4,%5,%6,%7}, {%8,%9}, {%0,%1,%2,%3};"
        : "+f"(c[0]), "+f"(c[1]), "+f"(c[2]), "+f"(c[3])
        : "r"(a[0]), "r"(a[1]), "r"(a[2]), "r"(a[3]), "r"(b[0]), "r"(b[1]));
}
__device__ __forceinline__ void sts16(uint32_t a, uint32_t x, uint32_t y,
                                      uint32_t z, uint32_t w) {
    asm volatile("st.shared.v4.b32 [%0], {%1,%2,%3,%4};"
                 :: "r"(a), "r"(x), "r"(y), "r"(z), "r"(w) : "memory");
}
__device__ __forceinline__ void red2(float* addr, float x, float y) {
    asm volatile("red.global.add.v2.f32 [%0], {%1,%2};"
                 :: "l"(addr), "f"(x), "f"(y) : "memory");
}

// ---------------- weight prep (transpose + fp16 round) ----------------
__global__ void prep_bt_k(const float* __restrict__ W, __half* __restrict__ out,
                          int Ksrc, int Nsrc, int KP, int Nrows) {
    int idx = blockIdx.x * 256 + threadIdx.x;
    if (idx >= Nrows * KP) return;
    int n = idx / KP, k = idx - n * KP;
    float v = (k < Ksrc && n < Nsrc) ? W[(size_t)k * Nsrc + n] : 0.f;
    out[(size_t)n * KP + k] = __float2half_rn(v);
}

__global__ void pad_k(const float* __restrict__ in, float* __restrict__ out,
                      int IC, int OC) {
    int idx = blockIdx.x * blockDim.x + threadIdx.x;
    if (idx >= OC) return;
    out[idx] = (idx < IC) ? in[idx] : 0.f;
}

__global__ void count_k(const int* __restrict__ batch, float* __restrict__ cnt) {
    int a = blockIdx.x * blockDim.x + threadIdx.x;
    if (a < NAT) atomicAdd(&cnt[batch[a]], 1.f);
}

// ---------------- fused GEMM (BM=64, BN=N, fp16 2-pass split) ----------------
// AMODE: 0 plain ; 1 h0 concat-gather ; 2 message ; 5 message+relu ; 3 wo concat
// EPI:   0 C=acc+aux[c] ; 1 C=relu(acc+aux[c]) ;
//        2 v=relu(acc+aux[r*N+c]); C=v; scatter v ;
//        3 C=acc; scatter relu(acc) ;
//        4 v=relu(acc+aux[r*N+c]); scatter only ;
//        5 v=relu(acc+aux[c])/cnt[sidx[r]]; scatter only (cnt via C2)
template<int AMODE>
__device__ __forceinline__ void loadA8(const float* __restrict__ A1,
                                       const float* __restrict__ A2,
                                       long long row, int s, int k0,
                                       int KP, float* va) {
    if (AMODE == 0) {
        const float4* p = (const float4*)(A1 + row * KP + k0);
        float4 a = p[0], b = p[1];
        va[0]=a.x; va[1]=a.y; va[2]=a.z; va[3]=a.w;
        va[4]=b.x; va[5]=b.y; va[6]=b.z; va[7]=b.w;
    } else if (AMODE == 2 || AMODE == 5) {
        const float4* pm = (const float4*)(A1 + (size_t)s * DHP + k0);
        const float4* ph = (const float4*)(A2 + (size_t)(row ^ 1) * DHP + k0);
#pragma unroll
        for (int i = 0; i < 2; i++) {
            float4 m = pm[i], h = ph[i];
            if (AMODE == 5) {
                h.x = fmaxf(h.x, 0.f); h.y = fmaxf(h.y, 0.f);
                h.z = fmaxf(h.z, 0.f); h.w = fmaxf(h.w, 0.f);
            }
            va[4*i]   = m.x - h.x; va[4*i+1] = m.y - h.y;
            va[4*i+2] = m.z - h.z; va[4*i+3] = m.w - h.w;
        }
    } else if (AMODE == 1) {
#pragma unroll
        for (int j = 0; j < 8; j++) {
            int k = k0 + j;
            va[j] = (k < 72) ? A1[(size_t)s * 72 + k]
                             : (k < 86 ? A2[row * 14 + (k - 72)] : 0.f);
        }
    } else { // AMODE 3
#pragma unroll
        for (int j = 0; j < 8; j++) {
            int k = k0 + j;
            va[j] = (k < 72) ? A1[row * 72 + k]
                             : (k < 372 ? A2[row * DHP + (k - 72)] : 0.f);
        }
    }
}

__device__ __forceinline__ void storeA8(uint32_t ahi, uint32_t alo, const float* va) {
    uint32_t h[4], l[4];
#pragma unroll
    for (int j = 0; j < 4; j++) {
        float a = va[2*j], b = va[2*j+1];
        __half ha = __float2half_rn(a), hb = __float2half_rn(b);
        __half2 hp; hp.x = ha; hp.y = hb;
        h[j] = *(uint32_t*)&hp;
        __half la = __float2half_rn(a - __half2float(ha));
        __half lb = __float2half_rn(b - __half2float(hb));
        __half2 lp; lp.x = la; lp.y = lb;
        l[j] = *(uint32_t*)&lp;
    }
    sts16(ahi, h[0], h[1], h[2], h[3]);
    sts16(alo, l[0], l[1], l[2], l[3]);
}

template<int AMODE, int EPI, int BN>
__global__ void __launch_bounds__(256, 2)
gemm_f(const float* __restrict__ A1, const float* __restrict__ A2,
       const int* __restrict__ gidx,
       const __half* __restrict__ Bt, int KP,
       const float* __restrict__ aux,
       const int* __restrict__ sidx, float* __restrict__ S,
       float* __restrict__ C, float* __restrict__ C2, int N) {
    constexpr int NT = BN / 32;                 // n-tiles (8 cols) per warp
    constexpr int RS = 80;
    constexpr int ABUF = 64 * RS;
    constexpr int BBUF = BN * RS;
    constexpr int STG = 2 * ABUF + BBUF;        // [Ahi][Alo][Bhi]
    extern __shared__ __align__(16) char sm[];
    const uint32_t sbase = smem_u32(sm);

    const int tid = threadIdx.x;
    const int wid = tid >> 5, lane = tid & 31;
    const int wm = wid & 1, wn = wid >> 1;
    const long long bm = (long long)blockIdx.y * 64;
    const int nW = KP >> 5;

    const int arow = tid >> 2;                  // 0..63
    const int kh = (tid & 3) * 8;               // 0,8,16,24
    const long long grow = bm + arow;
    const int s = (AMODE == 1 || AMODE == 2 || AMODE == 5) ? gidx[grow] : 0;

    float acc[2][NT][4];
#pragma unroll
    for (int i = 0; i < 2; i++)
#pragma unroll
        for (int j = 0; j < NT; j++)
#pragma unroll
            for (int t = 0; t < 4; t++) acc[i][j][t] = 0.f;

    const int aRow = (lane & 7) + ((lane >> 3) & 1) * 8;
    const int aK   = (lane >> 4) * 8;
    const int bRow4 = (lane & 7) + ((lane >> 4) << 3);
    const int bK4   = ((lane >> 3) & 1) * 8;

    auto loadB = [&](int w, int buf) {
        const uint32_t bhi = sbase + buf * STG + 2 * ABUF;
        for (int idx = tid; idx < BN * 4; idx += 256) {
            int row = idx >> 2, sg = idx & 3;
            cpa16(bhi + row * RS + sg * 16,
                  Bt + (size_t)row * KP + w * 32 + sg * 8);
        }
    };

    // prologue: window 0
    {
        float va[8];
        loadA8<AMODE>(A1, A2, grow, s, kh, KP, va);
        uint32_t ah = sbase + arow * RS + kh * 2;
        storeA8(ah, ah + ABUF, va);
        loadB(0, 0);
        cp_commit();
    }

    for (int w = 0; w < nW; ++w) {
        const int buf = w & 1;
        const bool more = (w + 1 < nW);
        float va[8];
        if (more) {
            loadA8<AMODE>(A1, A2, grow, s, (w + 1) * 32 + kh, KP, va);
            loadB(w + 1, buf ^ 1);
            cp_commit();
        }
        if (more) cp_wait<1>(); else cp_wait<0>();
        __syncthreads();
        const uint32_t as = sbase + buf * STG;
        const uint32_t bs = as + 2 * ABUF;
#pragma unroll
        for (int ks = 0; ks < 32; ks += 16) {
            uint32_t afh[2][4], afl[2][4];
#pragma unroll
            for (int mt = 0; mt < 2; ++mt) {
                uint32_t ar = as + (wm * 32 + mt * 16 + aRow) * RS + (ks + aK) * 2;
                ldsm4(afh[mt], ar);
                ldsm4(afl[mt], ar + ABUF);
            }
#pragma unroll
            for (int ntp = 0; ntp < NT / 2; ++ntp) {
                uint32_t bh4[4];
                uint32_t br = bs + (wn * NT * 8 + ntp * 16 + bRow4) * RS + (ks + bK4) * 2;
                ldsm4(bh4, br);
#pragma unroll
                for (int mt = 0; mt < 2; ++mt)
#pragma unroll
                    for (int h = 0; h < 2; ++h) {
                        mma16816(acc[mt][ntp*2 + h], afh[mt], bh4 + h*2);
                        mma16816(acc[mt][ntp*2 + h], afl[mt], bh4 + h*2);
                    }
            }
        }
        if (more) {
            uint32_t ah = sbase + (buf ^ 1) * STG + arow * RS + kh * 2;
            storeA8(ah, ah + ABUF, va);
        }
        __syncthreads();
    }

    // ---- epilogue ----
    const int gid = lane >> 2, tig = lane & 3;
#pragma unroll
    for (int mt = 0; mt < 2; ++mt) {
        const long long r0 = bm + wm * 32 + mt * 16 + gid;
        const long long r1 = r0 + 8;
        int si0 = 0, si1 = 0;
        float inv0 = 1.f, inv1 = 1.f;
        if (EPI >= 2) { si0 = sidx[r0]; si1 = sidx[r1]; }
        if (EPI == 5) {
            inv0 = 1.f / fmaxf(C2[si0], 1.f);
            inv1 = 1.f / fmaxf(C2[si1], 1.f);
        }
#pragma unroll
        for (int nt = 0; nt < NT; ++nt) {
            const int c0 = wn * NT * 8 + nt * 8 + tig * 2;
            float v00 = acc[mt][nt][0], v01 = acc[mt][nt][1];
            float v10 = acc[mt][nt][2], v11 = acc[mt][nt][3];
            float r00, r01, r10, r11;
            if (EPI == 0 || EPI == 1 || EPI == 5) {
                float2 ax = *(const float2*)(aux + c0);
                r00 = v00 + ax.x; r01 = v01 + ax.y;
                r10 = v10 + ax.x; r11 = v11 + ax.y;
            } else if (EPI == 2 || EPI == 4) {
                float2 a0 = *(const float2*)(aux + r0 * N + c0);
                float2 a1 = *(const float2*)(aux + r1 * N + c0);
                r00 = v00 + a0.x; r01 = v01 + a0.y;
                r10 = v10 + a1.x; r11 = v11 + a1.y;
            } else { // EPI==3
                r00 = v00; r01 = v01; r10 = v10; r11 = v11;
            }
            if (EPI != 0) {
                r00 = fmaxf(r00, 0.f); r01 = fmaxf(r01, 0.f);
                r10 = fmaxf(r10, 0.f); r11 = fmaxf(r11, 0.f);
            }
            if (EPI == 5) {
                r00 *= inv0; r01 *= inv0; r10 *= inv1; r11 *= inv1;
            }
            if (EPI == 0 || EPI == 1 || EPI == 2) {
                *(float2*)(C + r0 * N + c0) = make_float2(r00, r01);
                *(float2*)(C + r1 * N + c0) = make_float2(r10, r11);
            } else if (EPI == 3) {
                *(float2*)(C + r0 * N + c0) = make_float2(v00, v01);
                *(float2*)(C + r1 * N + c0) = make_float2(v10, v11);
            }
            if (EPI >= 2) {
                float* s0 = S + (size_t)si0 * DHP + c0;
                float* s1 = S + (size_t)si1 * DHP + c0;
                if (r00 != 0.f || r01 != 0.f) red2(s0, r00, r01);
                if (r10 != 0.f || r11 != 0.f) red2(s1, r10, r11);
            }
        }
    }
}

// ---------------- launcher ----------------
extern "C" void kernel_launch(void* const* d_in, const int* in_sizes, int n_in,
                              void* d_out, int out_size) {
    const float* V    = (const float*)d_in[0];
    const float* E    = (const float*)d_in[1];
    const int*   esrc = (const int*)d_in[2];
    const int*   edst = (const int*)d_in[3];
    const int*   batc = (const int*)d_in[5];
    int wi = 6;
    if (n_in >= 15 && in_sizes[6] == 1) wi = 7;
    const float* W_i = (const float*)d_in[wi + 0];
    const float* W_h = (const float*)d_in[wi + 1];
    const float* W_o = (const float*)d_in[wi + 2];
    const float* b_o = (const float*)d_in[wi + 3];
    const float* W1  = (const float*)d_in[wi + 4];
    const float* b1  = (const float*)d_in[wi + 5];
    const float* W2  = (const float*)d_in[wi + 6];
    const float* b2  = (const float*)d_in[wi + 7];
    float* out = (float*)d_out;

    float *H0, *Hb, *Mv1, *Mv2, *Z, *cnt, *T, *bo;
    __half *Bh0, *Bh, *Bo, *B1, *B2;
    cudaGetSymbolAddress((void**)&H0,  g_H0);
    cudaGetSymbolAddress((void**)&Hb,  g_Hb);
    cudaGetSymbolAddress((void**)&Mv1, g_Mv1);
    cudaGetSymbolAddress((void**)&Mv2, g_Mv2);
    cudaGetSymbolAddress((void**)&Z,   g_Z);
    cudaGetSymbolAddress((void**)&cnt, g_cnt);
    cudaGetSymbolAddress((void**)&T,   g_T);
    cudaGetSymbolAddress((void**)&bo,  g_bo);
    cudaGetSymbolAddress((void**)&Bh0, g_Bh0);
    cudaGetSymbolAddress((void**)&Bh,  g_Bh);
    cudaGetSymbolAddress((void**)&Bo,  g_Bo);
    cudaGetSymbolAddress((void**)&B1,  g_B1);
    cudaGetSymbolAddress((void**)&B2,  g_B2);

    const int SMF320 = 2 * (2 * 64 * 80 + 320 * 80);  // 71680
    const int SMF256 = 2 * (2 * 64 * 80 + 256 * 80);  // 61440
    cudaFuncSetAttribute(gemm_f<1,3,320>, cudaFuncAttributeMaxDynamicSharedMemorySize, SMF320);
    cudaFuncSetAttribute(gemm_f<5,2,320>, cudaFuncAttributeMaxDynamicSharedMemorySize, SMF320);
    cudaFuncSetAttribute(gemm_f<2,4,320>, cudaFuncAttributeMaxDynamicSharedMemorySize, SMF320);
    cudaFuncSetAttribute(gemm_f<3,5,320>, cudaFuncAttributeMaxDynamicSharedMemorySize, SMF320);
    cudaFuncSetAttribute(gemm_f<0,1,256>, cudaFuncAttributeMaxDynamicSharedMemorySize, SMF256);
    cudaFuncSetAttribute(gemm_f<0,0,256>, cudaFuncAttributeMaxDynamicSharedMemorySize, SMF256);

    // weight prep (transpose + fp16)
    prep_bt_k<<<(320 * 96  + 255) / 256, 256>>>(W_i, Bh0, 86,  300, 96,  320);
    prep_bt_k<<<(320 * 320 + 255) / 256, 256>>>(W_h, Bh,  300, 300, 320, 320);
    prep_bt_k<<<(320 * 384 + 255) / 256, 256>>>(W_o, Bo,  372, 300, 384, 320);
    prep_bt_k<<<(256 * 320 + 255) / 256, 256>>>(W1,  B1,  300, 256, 320, 256);
    prep_bt_k<<<(256 * 256 + 255) / 256, 256>>>(W2,  B2,  256, 256, 256, 256);
    pad_k<<<2, 256>>>(b_o, bo, 300, DHP);

    const size_t MVB = (size_t)NAT * DHP * sizeof(float);
    cudaMemsetAsync(cnt, 0, (size_t)NMO * sizeof(float));
    count_k<<<(NAT + 255) / 256, 256>>>(batc, cnt);
    cudaMemsetAsync(Mv1, 0, MVB);
    cudaMemsetAsync(Mv2, 0, MVB);
    cudaMemsetAsync(Z, 0, (size_t)NMO * DHP * sizeof(float));

    // 1. H0 = concat(V[src],E)@W_i (store pre-relu) ; scatter relu -> Mv1
    gemm_f<1,3,320><<<dim3(1, NBO / 64), 256, SMF320>>>(
        V, E, esrc, Bh0, 96, nullptr, edst, Mv1, H0, nullptr, DHP);

    // 2. iter1: Hb = relu(H0 + (Mv1[src]-relu(H0)[rev])@Wh) ; scatter -> Mv2
    gemm_f<5,2,320><<<dim3(1, NBO / 64), 256, SMF320>>>(
        Mv1, H0, esrc, Bh, 320, H0, edst, Mv2, Hb, nullptr, DHP);

    // 3. iter2: relu(H0 + (Mv2[src]-Hb[rev])@Wh) scattered -> Mv1 (no store)
    cudaMemsetAsync(Mv1, 0, MVB);
    gemm_f<2,4,320><<<dim3(1, NBO / 64), 256, SMF320>>>(
        Mv2, Hb, esrc, Bh, 320, H0, edst, Mv1, nullptr, nullptr, DHP);

    // 4. relu(concat(V,Mv1)@Wo + bo) / cnt pooled -> Z (mean fused)
    gemm_f<3,5,320><<<dim3(1, NAT / 64), 256, SMF320>>>(
        V, Mv1, nullptr, Bo, 384, bo, batc, Z, nullptr, cnt, DHP);

    // 5. T = relu(Z@W1+b1)
    gemm_f<0,1,256><<<dim3(1, NMO / 64), 256, SMF256>>>(
        Z, nullptr, nullptr, B1, 320, b1, nullptr, nullptr, T, nullptr, DEM);

    // 6. out = T@W2+b2
    gemm_f<0,0,256><<<dim3(1, NMO / 64), 256, SMF256>>>(
        T, nullptr, nullptr, B2, 256, b2, nullptr, nullptr, out, nullptr, DEM);
}

// round 12
// speedup vs baseline: 6.4154x; 1.1765x over previous
#include <cuda_runtime.h>
#include <cuda_fp16.h>
#include <cstdint>
#include <cstddef>

#define NAT 131072
#define NBO 262144
#define NMO 4096
#define DHP 320
#define DEM 256

// ---------------- scratch (device globals; no allocation) ----------------
__device__ float g_H0[(size_t)NBO * DHP];
__device__ float g_Hb[(size_t)NBO * DHP];
__device__ float g_Mv1[(size_t)NAT * DHP];
__device__ float g_Mv2[(size_t)NAT * DHP];
__device__ float g_Z [(size_t)NMO * DHP];
__device__ float g_cnt[NMO];
__device__ float g_T [(size_t)NMO * DEM];
__device__ float g_bo[DHP];
__device__ __align__(16) __half g_Bh0[320 * 96];
__device__ __align__(16) __half g_Bh [320 * 320];
__device__ __align__(16) __half g_Bo [320 * 384];
__device__ __align__(16) __half g_B1 [256 * 320];
__device__ __align__(16) __half g_B2 [256 * 256];

// ---------------- PTX helpers ----------------
__device__ __forceinline__ uint32_t smem_u32(const void* p) {
    uint32_t a;
    asm("{ .reg .u64 t; cvta.to.shared.u64 t, %1; cvt.u32.u64 %0, t; }"
        : "=r"(a) : "l"(p));
    return a;
}
__device__ __forceinline__ void cpa16(uint32_t dst, const void* src) {
    asm volatile("cp.async.cg.shared.global [%0], [%1], 16;"
                 :: "r"(dst), "l"(src) : "memory");
}
__device__ __forceinline__ void cp_commit() {
    asm volatile("cp.async.commit_group;" ::: "memory");
}
template<int N>
__device__ __forceinline__ void cp_wait() {
    asm volatile("cp.async.wait_group %0;" :: "n"(N) : "memory");
}
__device__ __forceinline__ void ldsm4(uint32_t* r, uint32_t a) {
    asm volatile("ldmatrix.sync.aligned.m8n8.x4.shared.b16 {%0,%1,%2,%3}, [%4];"
                 : "=r"(r[0]), "=r"(r[1]), "=r"(r[2]), "=r"(r[3]) : "r"(a));
}
__device__ __forceinline__ void mma16816(float* c, const uint32_t* a, const uint32_t* b) {
    asm volatile(
        "mma.sync.aligned.m16n8k16.row.col.f32.f16.f16.f32 "
        "{%0,%1,%2,%3}, {%4,%5,%6,%7}, {%8,%9}, {%0,%1,%2,%3};"
        : "+f"(c[0]), "+f"(c[1]), "+f"(c[2]), "+f"(c[3])
        : "r"(a[0]), "r"(a[1]), "r"(a[2]), "r"(a[3]), "r"(b[0]), "r"(b[1]));
}
__device__ __forceinline__ void sts16(uint32_t a, uint32_t x, uint32_t y,
                                      uint32_t z, uint32_t w) {
    asm volatile("st.shared.v4.b32 [%0], {%1,%2,%3,%4};"
                 :: "r"(a), "r"(x), "r"(y), "r"(z), "r"(w) : "memory");
}
__device__ __forceinline__ void red2(float* addr, float x, float y) {
    asm volatile("red.global.add.v2.f32 [%0], {%1,%2};"
                 :: "l"(addr), "f"(x), "f"(y) : "memory");
}

// ---------------- weight prep (transpose + fp16 round) ----------------
__global__ void prep_bt_k(const float* __restrict__ W, __half* __restrict__ out,
                          int Ksrc, int Nsrc, int KP, int Nrows) {
    int idx = blockIdx.x * 256 + threadIdx.x;
    if (idx >= Nrows * KP) return;
    int n = idx / KP, k = idx - n * KP;
    float v = (k < Ksrc && n < Nsrc) ? W[(size_t)k * Nsrc + n] : 0.f;
    out[(size_t)n * KP + k] = __float2half_rn(v);
}

__global__ void pad_k(const float* __restrict__ in, float* __restrict__ out,
                      int IC, int OC) {
    int idx = blockIdx.x * blockDim.x + threadIdx.x;
    if (idx >= OC) return;
    out[idx] = (idx < IC) ? in[idx] : 0.f;
}

__global__ void count_k(const int* __restrict__ batch, float* __restrict__ cnt) {
    int a = blockIdx.x * blockDim.x + threadIdx.x;
    if (a < NAT) atomicAdd(&cnt[batch[a]], 1.f);
}

// ---------------- fused GEMM (BM=64, BN=N, fp16 1-pass) ----------------
// AMODE: 0 plain ; 1 h0 concat-gather ; 2 message ; 5 message+relu ; 3 wo concat
// EPI:   0 C=acc+aux[c] ; 1 C=relu(acc+aux[c]) ;
//        2 v=relu(acc+aux[r*N+c]); C=v; scatter v ;
//        3 C=acc; scatter relu(acc) ;
//        4 v=relu(acc+aux[r*N+c]); scatter only ;
//        5 v=relu(acc+aux[c])/cnt[sidx[r]]; scatter only (cnt via C2)
template<int AMODE>
__device__ __forceinline__ void loadA8(const float* __restrict__ A1,
                                       const float* __restrict__ A2,
                                       long long row, int s, int k0,
                                       int KP, float* va) {
    if (AMODE == 0) {
        const float4* p = (const float4*)(A1 + row * KP + k0);
        float4 a = p[0], b = p[1];
        va[0]=a.x; va[1]=a.y; va[2]=a.z; va[3]=a.w;
        va[4]=b.x; va[5]=b.y; va[6]=b.z; va[7]=b.w;
    } else if (AMODE == 2 || AMODE == 5) {
        const float4* pm = (const float4*)(A1 + (size_t)s * DHP + k0);
        const float4* ph = (const float4*)(A2 + (size_t)(row ^ 1) * DHP + k0);
#pragma unroll
        for (int i = 0; i < 2; i++) {
            float4 m = pm[i], h = ph[i];
            if (AMODE == 5) {
                h.x = fmaxf(h.x, 0.f); h.y = fmaxf(h.y, 0.f);
                h.z = fmaxf(h.z, 0.f); h.w = fmaxf(h.w, 0.f);
            }
            va[4*i]   = m.x - h.x; va[4*i+1] = m.y - h.y;
            va[4*i+2] = m.z - h.z; va[4*i+3] = m.w - h.w;
        }
    } else if (AMODE == 1) {
#pragma unroll
        for (int j = 0; j < 8; j++) {
            int k = k0 + j;
            va[j] = (k < 72) ? A1[(size_t)s * 72 + k]
                             : (k < 86 ? A2[row * 14 + (k - 72)] : 0.f);
        }
    } else { // AMODE 3
#pragma unroll
        for (int j = 0; j < 8; j++) {
            int k = k0 + j;
            va[j] = (k < 72) ? A1[row * 72 + k]
                             : (k < 372 ? A2[row * DHP + (k - 72)] : 0.f);
        }
    }
}

__device__ __forceinline__ void storeA8(uint32_t ahi, const float* va) {
    uint32_t h[4];
#pragma unroll
    for (int j = 0; j < 4; j++) {
        __half2 hp;
        hp.x = __float2half_rn(va[2*j]);
        hp.y = __float2half_rn(va[2*j+1]);
        h[j] = *(uint32_t*)&hp;
    }
    sts16(ahi, h[0], h[1], h[2], h[3]);
}

template<int AMODE, int EPI, int BN>
__global__ void __launch_bounds__(256, 2)
gemm_f(const float* __restrict__ A1, const float* __restrict__ A2,
       const int* __restrict__ gidx,
       const __half* __restrict__ Bt, int KP,
       const float* __restrict__ aux,
       const int* __restrict__ sidx, float* __restrict__ S,
       float* __restrict__ C, float* __restrict__ C2, int N) {
    constexpr int NT = BN / 32;                 // n-tiles (8 cols) per warp
    constexpr int RS = 80;
    constexpr int ABUF = 64 * RS;
    constexpr int BBUF = BN * RS;
    constexpr int STG = ABUF + BBUF;            // [Ahi][Bhi]
    extern __shared__ __align__(16) char sm[];
    const uint32_t sbase = smem_u32(sm);

    const int tid = threadIdx.x;
    const int wid = tid >> 5, lane = tid & 31;
    const int wm = wid & 1, wn = wid >> 1;
    const long long bm = (long long)blockIdx.y * 64;
    const int nW = KP >> 5;

    const int arow = tid >> 2;                  // 0..63
    const int kh = (tid & 3) * 8;               // 0,8,16,24
    const long long grow = bm + arow;
    const int s = (AMODE == 1 || AMODE == 2 || AMODE == 5) ? gidx[grow] : 0;

    float acc[2][NT][4];
#pragma unroll
    for (int i = 0; i < 2; i++)
#pragma unroll
        for (int j = 0; j < NT; j++)
#pragma unroll
            for (int t = 0; t < 4; t++) acc[i][j][t] = 0.f;

    const int aRow = (lane & 7) + ((lane >> 3) & 1) * 8;
    const int aK   = (lane >> 4) * 8;
    const int bRow4 = (lane & 7) + ((lane >> 4) << 3);
    const int bK4   = ((lane >> 3) & 1) * 8;

    auto loadB = [&](int w, int buf) {
        const uint32_t bhi = sbase + buf * STG + ABUF;
        for (int idx = tid; idx < BN * 4; idx += 256) {
            int row = idx >> 2, sg = idx & 3;
            cpa16(bhi + row * RS + sg * 16,
                  Bt + (size_t)row * KP + w * 32 + sg * 8);
        }
    };

    // prologue: window 0
    {
        float va[8];
        loadA8<AMODE>(A1, A2, grow, s, kh, KP, va);
        storeA8(sbase + arow * RS + kh * 2, va);
        loadB(0, 0);
        cp_commit();
    }

    for (int w = 0; w < nW; ++w) {
        const int buf = w & 1;
        const bool more = (w + 1 < nW);
        float va[8];
        if (more) {
            loadA8<AMODE>(A1, A2, grow, s, (w + 1) * 32 + kh, KP, va);
            loadB(w + 1, buf ^ 1);
            cp_commit();
        }
        if (more) cp_wait<1>(); else cp_wait<0>();
        __syncthreads();
        const uint32_t as = sbase + buf * STG;
        const uint32_t bs = as + ABUF;
#pragma unroll
        for (int ks = 0; ks < 32; ks += 16) {
            uint32_t afh[2][4];
#pragma unroll
            for (int mt = 0; mt < 2; ++mt) {
                uint32_t ar = as + (wm * 32 + mt * 16 + aRow) * RS + (ks + aK) * 2;
                ldsm4(afh[mt], ar);
            }
#pragma unroll
            for (int ntp = 0; ntp < NT / 2; ++ntp) {
                uint32_t bh4[4];
                uint32_t br = bs + (wn * NT * 8 + ntp * 16 + bRow4) * RS + (ks + bK4) * 2;
                ldsm4(bh4, br);
#pragma unroll
                for (int mt = 0; mt < 2; ++mt)
#pragma unroll
                    for (int h = 0; h < 2; ++h)
                        mma16816(acc[mt][ntp*2 + h], afh[mt], bh4 + h*2);
            }
        }
        if (more) {
            storeA8(sbase + (buf ^ 1) * STG + arow * RS + kh * 2, va);
        }
        __syncthreads();
    }

    // ---- epilogue ----
    const int gid = lane >> 2, tig = lane & 3;
#pragma unroll
    for (int mt = 0; mt < 2; ++mt) {
        const long long r0 = bm + wm * 32 + mt * 16 + gid;
        const long long r1 = r0 + 8;
        int si0 = 0, si1 = 0;
        float inv0 = 1.f, inv1 = 1.f;
        if (EPI >= 2) { si0 = sidx[r0]; si1 = sidx[r1]; }
        if (EPI == 5) {
            inv0 = 1.f / fmaxf(C2[si0], 1.f);
            inv1 = 1.f / fmaxf(C2[si1], 1.f);
        }
#pragma unroll
        for (int nt = 0; nt < NT; ++nt) {
            const int c0 = wn * NT * 8 + nt * 8 + tig * 2;
            float v00 = acc[mt][nt][0], v01 = acc[mt][nt][1];
            float v10 = acc[mt][nt][2], v11 = acc[mt][nt][3];
            float r00, r01, r10, r11;
            if (EPI == 0 || EPI == 1 || EPI == 5) {
                float2 ax = *(const float2*)(aux + c0);
                r00 = v00 + ax.x; r01 = v01 + ax.y;
                r10 = v10 + ax.x; r11 = v11 + ax.y;
            } else if (EPI == 2 || EPI == 4) {
                float2 a0 = *(const float2*)(aux + r0 * N + c0);
                float2 a1 = *(const float2*)(aux + r1 * N + c0);
                r00 = v00 + a0.x; r01 = v01 + a0.y;
                r10 = v10 + a1.x; r11 = v11 + a1.y;
            } else { // EPI==3
                r00 = v00; r01 = v01; r10 = v10; r11 = v11;
            }
            if (EPI != 0) {
                r00 = fmaxf(r00, 0.f); r01 = fmaxf(r01, 0.f);
                r10 = fmaxf(r10, 0.f); r11 = fmaxf(r11, 0.f);
            }
            if (EPI == 5) {
                r00 *= inv0; r01 *= inv0; r10 *= inv1; r11 *= inv1;
            }
            if (EPI == 0 || EPI == 1 || EPI == 2) {
                *(float2*)(C + r0 * N + c0) = make_float2(r00, r01);
                *(float2*)(C + r1 * N + c0) = make_float2(r10, r11);
            } else if (EPI == 3) {
                *(float2*)(C + r0 * N + c0) = make_float2(v00, v01);
                *(float2*)(C + r1 * N + c0) = make_float2(v10, v11);
            }
            if (EPI >= 2) {
                float* s0 = S + (size_t)si0 * DHP + c0;
                float* s1 = S + (size_t)si1 * DHP + c0;
                if (r00 != 0.f || r01 != 0.f) red2(s0, r00, r01);
                if (r10 != 0.f || r11 != 0.f) red2(s1, r10, r11);
            }
        }
    }
}

// ---------------- launcher ----------------
extern "C" void kernel_launch(void* const* d_in, const int* in_sizes, int n_in,
                              void* d_out, int out_size) {
    const float* V    = (const float*)d_in[0];
    const float* E    = (const float*)d_in[1];
    const int*   esrc = (const int*)d_in[2];
    const int*   edst = (const int*)d_in[3];
    const int*   batc = (const int*)d_in[5];
    int wi = 6;
    if (n_in >= 15 && in_sizes[6] == 1) wi = 7;
    const float* W_i = (const float*)d_in[wi + 0];
    const float* W_h = (const float*)d_in[wi + 1];
    const float* W_o = (const float*)d_in[wi + 2];
    const float* b_o = (const float*)d_in[wi + 3];
    const float* W1  = (const float*)d_in[wi + 4];
    const float* b1  = (const float*)d_in[wi + 5];
    const float* W2  = (const float*)d_in[wi + 6];
    const float* b2  = (const float*)d_in[wi + 7];
    float* out = (float*)d_out;

    float *H0, *Hb, *Mv1, *Mv2, *Z, *cnt, *T, *bo;
    __half *Bh0, *Bh, *Bo, *B1, *B2;
    cudaGetSymbolAddress((void**)&H0,  g_H0);
    cudaGetSymbolAddress((void**)&Hb,  g_Hb);
    cudaGetSymbolAddress((void**)&Mv1, g_Mv1);
    cudaGetSymbolAddress((void**)&Mv2, g_Mv2);
    cudaGetSymbolAddress((void**)&Z,   g_Z);
    cudaGetSymbolAddress((void**)&cnt, g_cnt);
    cudaGetSymbolAddress((void**)&T,   g_T);
    cudaGetSymbolAddress((void**)&bo,  g_bo);
    cudaGetSymbolAddress((void**)&Bh0, g_Bh0);
    cudaGetSymbolAddress((void**)&Bh,  g_Bh);
    cudaGetSymbolAddress((void**)&Bo,  g_Bo);
    cudaGetSymbolAddress((void**)&B1,  g_B1);
    cudaGetSymbolAddress((void**)&B2,  g_B2);

    const int SMF320 = 2 * (64 * 80 + 320 * 80);  // 61440
    const int SMF256 = 2 * (64 * 80 + 256 * 80);  // 51200
    cudaFuncSetAttribute(gemm_f<1,3,320>, cudaFuncAttributeMaxDynamicSharedMemorySize, SMF320);
    cudaFuncSetAttribute(gemm_f<5,2,320>, cudaFuncAttributeMaxDynamicSharedMemorySize, SMF320);
    cudaFuncSetAttribute(gemm_f<2,4,320>, cudaFuncAttributeMaxDynamicSharedMemorySize, SMF320);
    cudaFuncSetAttribute(gemm_f<3,5,320>, cudaFuncAttributeMaxDynamicSharedMemorySize, SMF320);
    cudaFuncSetAttribute(gemm_f<0,1,256>, cudaFuncAttributeMaxDynamicSharedMemorySize, SMF256);
    cudaFuncSetAttribute(gemm_f<0,0,256>, cudaFuncAttributeMaxDynamicSharedMemorySize, SMF256);

    // weight prep (transpose + fp16)
    prep_bt_k<<<(320 * 96  + 255) / 256, 256>>>(W_i, Bh0, 86,  300, 96,  320);
    prep_bt_k<<<(320 * 320 + 255) / 256, 256>>>(W_h, Bh,  300, 300, 320, 320);
    prep_bt_k<<<(320 * 384 + 255) / 256, 256>>>(W_o, Bo,  372, 300, 384, 320);
    prep_bt_k<<<(256 * 320 + 255) / 256, 256>>>(W1,  B1,  300, 256, 320, 256);
    prep_bt_k<<<(256 * 256 + 255) / 256, 256>>>(W2,  B2,  256, 256, 256, 256);
    pad_k<<<2, 256>>>(b_o, bo, 300, DHP);

    const size_t MVB = (size_t)NAT * DHP * sizeof(float);
    cudaMemsetAsync(cnt, 0, (size_t)NMO * sizeof(float));
    count_k<<<(NAT + 255) / 256, 256>>>(batc, cnt);
    cudaMemsetAsync(Mv1, 0, MVB);
    cudaMemsetAsync(Mv2, 0, MVB);
    cudaMemsetAsync(Z, 0, (size_t)NMO * DHP * sizeof(float));

    // 1. H0 = concat(V[src],E)@W_i (store pre-relu) ; scatter relu -> Mv1
    gemm_f<1,3,320><<<dim3(1, NBO / 64), 256, SMF320>>>(
        V, E, esrc, Bh0, 96, nullptr, edst, Mv1, H0, nullptr, DHP);

    // 2. iter1: Hb = relu(H0 + (Mv1[src]-relu(H0)[rev])@Wh) ; scatter -> Mv2
    gemm_f<5,2,320><<<dim3(1, NBO / 64), 256, SMF320>>>(
        Mv1, H0, esrc, Bh, 320, H0, edst, Mv2, Hb, nullptr, DHP);

    // 3. iter2: relu(H0 + (Mv2[src]-Hb[rev])@Wh) scattered -> Mv1 (no store)
    cudaMemsetAsync(Mv1, 0, MVB);
    gemm_f<2,4,320><<<dim3(1, NBO / 64), 256, SMF320>>>(
        Mv2, Hb, esrc, Bh, 320, H0, edst, Mv1, nullptr, nullptr, DHP);

    // 4. relu(concat(V,Mv1)@Wo + bo) / cnt pooled -> Z (mean fused)
    gemm_f<3,5,320><<<dim3(1, NAT / 64), 256, SMF320>>>(
        V, Mv1, nullptr, Bo, 384, bo, batc, Z, nullptr, cnt, DHP);

    // 5. T = relu(Z@W1+b1)
    gemm_f<0,1,256><<<dim3(1, NMO / 64), 256, SMF256>>>(
        Z, nullptr, nullptr, B1, 320, b1, nullptr, nullptr, T, nullptr, DEM);

    // 6. out = T@W2+b2
    gemm_f<0,0,256><<<dim3(1, NMO / 64), 256, SMF256>>>(
        T, nullptr, nullptr, B2, 256, b2, nullptr, nullptr, out, nullptr, DEM);
}

// round 13
// speedup vs baseline: 6.8423x; 1.0665x over previous
#include <cuda_runtime.h>
#include <cuda_fp16.h>
#include <cstdint>
#include <cstddef>

#define NAT 131072
#define NBO 262144
#define NMO 4096
#define DHP 320
#define DEM 256

// ---------------- scratch (device globals; no allocation) ----------------
__device__ __align__(16) __half g_H0[(size_t)NBO * DHP];
__device__ __align__(16) __half g_Hb[(size_t)NBO * DHP];
__device__ float g_Mv1[(size_t)NAT * DHP];
__device__ float g_Mv2[(size_t)NAT * DHP];
__device__ float g_Z [(size_t)NMO * DHP];
__device__ float g_cnt[NMO];
__device__ float g_T [(size_t)NMO * DEM];
__device__ float g_bo[DHP];
__device__ __align__(16) __half g_Bh0[320 * 96];
__device__ __align__(16) __half g_Bh [320 * 320];
__device__ __align__(16) __half g_Bo [320 * 384];
__device__ __align__(16) __half g_B1 [256 * 320];
__device__ __align__(16) __half g_B2 [256 * 256];

// ---------------- PTX helpers ----------------
__device__ __forceinline__ uint32_t smem_u32(const void* p) {
    uint32_t a;
    asm("{ .reg .u64 t; cvta.to.shared.u64 t, %1; cvt.u32.u64 %0, t; }"
        : "=r"(a) : "l"(p));
    return a;
}
__device__ __forceinline__ void cpa16(uint32_t dst, const void* src) {
    asm volatile("cp.async.cg.shared.global [%0], [%1], 16;"
                 :: "r"(dst), "l"(src) : "memory");
}
__device__ __forceinline__ void cp_commit() {
    asm volatile("cp.async.commit_group;" ::: "memory");
}
template<int N>
__device__ __forceinline__ void cp_wait() {
    asm volatile("cp.async.wait_group %0;" :: "n"(N) : "memory");
}
__device__ __forceinline__ void ldsm4(uint32_t* r, uint32_t a) {
    asm volatile("ldmatrix.sync.aligned.m8n8.x4.shared.b16 {%0,%1,%2,%3}, [%4];"
                 : "=r"(r[0]), "=r"(r[1]), "=r"(r[2]), "=r"(r[3]) : "r"(a));
}
__device__ __forceinline__ void mma16816(float* c, const uint32_t* a, const uint32_t* b) {
    asm volatile(
        "mma.sync.aligned.m16n8k16.row.col.f32.f16.f16.f32 "
        "{%0,%1,%2,%3}, {%4,%5,%6,%7}, {%8,%9}, {%0,%1,%2,%3};"
        : "+f"(c[0]), "+f"(c[1]), "+f"(c[2]), "+f"(c[3])
        : "r"(a[0]), "r"(a[1]), "r"(a[2]), "r"(a[3]), "r"(b[0]), "r"(b[1]));
}
__device__ __forceinline__ void sts16(uint32_t a, uint32_t x, uint32_t y,
                                      uint32_t z, uint32_t w) {
    asm volatile("st.shared.v4.b32 [%0], {%1,%2,%3,%4};"
                 :: "r"(a), "r"(x), "r"(y), "r"(z), "r"(w) : "memory");
}
__device__ __forceinline__ void red2(float* addr, float x, float y) {
    asm volatile("red.global.add.v2.f32 [%0], {%1,%2};"
                 :: "l"(addr), "f"(x), "f"(y) : "memory");
}

// ---------------- weight prep (transpose + fp16 round) ----------------
__global__ void prep_bt_k(const float* __restrict__ W, __half* __restrict__ out,
                          int Ksrc, int Nsrc, int KP, int Nrows) {
    int idx = blockIdx.x * 256 + threadIdx.x;
    if (idx >= Nrows * KP) return;
    int n = idx / KP, k = idx - n * KP;
    float v = (k < Ksrc && n < Nsrc) ? W[(size_t)k * Nsrc + n] : 0.f;
    out[(size_t)n * KP + k] = __float2half_rn(v);
}

__global__ void pad_k(const float* __restrict__ in, float* __restrict__ out,
                      int IC, int OC) {
    int idx = blockIdx.x * blockDim.x + threadIdx.x;
    if (idx >= OC) return;
    out[idx] = (idx < IC) ? in[idx] : 0.f;
}

__global__ void count_k(const int* __restrict__ batch, float* __restrict__ cnt) {
    int a = blockIdx.x * blockDim.x + threadIdx.x;
    if (a < NAT) atomicAdd(&cnt[batch[a]], 1.f);
}

// ---------------- fused GEMM (BM=64, BN=N, fp16 1-pass, fp16 H storage) ----
// AMODE: 0 plain(f32 A1) ; 1 h0 concat-gather(V,E f32) ;
//        2 message: Mv(f32)[g[r]] - Hh(f16)[(r^1)] ;
//        5 message+relu: Mv - relu(Hh[(r^1)]) ;
//        3 wo concat: V(f32) | Mv(f32)
// EPI:   0 C=acc+aux_f[c] (f32 store) ; 1 C=relu(acc+aux_f[c]) (f32 store) ;
//        2 v=relu(acc+aux_h[r*N+c]); C(f16)=v; scatter v ;
//        3 C(f16)=acc; scatter relu(acc) ;
//        4 v=relu(acc+aux_h[r*N+c]); scatter only ;
//        5 v=relu(acc+aux_f[c])/cnt[sidx[r]]; scatter only (cnt via C2)
template<int AMODE>
__device__ __forceinline__ void loadA8(const float* __restrict__ A1,
                                       const void* __restrict__ A2v,
                                       long long row, int s, int k0,
                                       int KP, float* va) {
    if (AMODE == 0) {
        const float4* p = (const float4*)(A1 + row * KP + k0);
        float4 a = p[0], b = p[1];
        va[0]=a.x; va[1]=a.y; va[2]=a.z; va[3]=a.w;
        va[4]=b.x; va[5]=b.y; va[6]=b.z; va[7]=b.w;
    } else if (AMODE == 2 || AMODE == 5) {
        const float4* pm = (const float4*)(A1 + (size_t)s * DHP + k0);
        const uint4 hv = *(const uint4*)((const __half*)A2v +
                                         (size_t)(row ^ 1) * DHP + k0);
        const __half2* hp = (const __half2*)&hv;
#pragma unroll
        for (int i = 0; i < 2; i++) {
            float4 m = pm[i];
            float2 f0 = __half22float2(hp[2*i]);
            float2 f1 = __half22float2(hp[2*i+1]);
            if (AMODE == 5) {
                f0.x = fmaxf(f0.x, 0.f); f0.y = fmaxf(f0.y, 0.f);
                f1.x = fmaxf(f1.x, 0.f); f1.y = fmaxf(f1.y, 0.f);
            }
            va[4*i]   = m.x - f0.x; va[4*i+1] = m.y - f0.y;
            va[4*i+2] = m.z - f1.x; va[4*i+3] = m.w - f1.y;
        }
    } else if (AMODE == 1) {
        const float* A2 = (const float*)A2v;
#pragma unroll
        for (int j = 0; j < 8; j++) {
            int k = k0 + j;
            va[j] = (k < 72) ? A1[(size_t)s * 72 + k]
                             : (k < 86 ? A2[row * 14 + (k - 72)] : 0.f);
        }
    } else { // AMODE 3
        const float* A2 = (const float*)A2v;
#pragma unroll
        for (int j = 0; j < 8; j++) {
            int k = k0 + j;
            va[j] = (k < 72) ? A1[row * 72 + k]
                             : (k < 372 ? A2[row * DHP + (k - 72)] : 0.f);
        }
    }
}

__device__ __forceinline__ void storeA8(uint32_t ahi, const float* va) {
    uint32_t h[4];
#pragma unroll
    for (int j = 0; j < 4; j++) {
        __half2 hp;
        hp.x = __float2half_rn(va[2*j]);
        hp.y = __float2half_rn(va[2*j+1]);
        h[j] = *(uint32_t*)&hp;
    }
    sts16(ahi, h[0], h[1], h[2], h[3]);
}

template<int AMODE, int EPI, int BN>
__global__ void __launch_bounds__(256, 2)
gemm_f(const float* __restrict__ A1, const void* __restrict__ A2v,
       const int* __restrict__ gidx,
       const __half* __restrict__ Bt, int KP,
       const void* __restrict__ auxv,
       const int* __restrict__ sidx, float* __restrict__ S,
       void* __restrict__ Cv, const float* __restrict__ C2, int N) {
    constexpr int NT = BN / 32;                 // n-tiles (8 cols) per warp
    constexpr int RS = 80;
    constexpr int ABUF = 64 * RS;
    constexpr int BBUF = BN * RS;
    constexpr int STG = ABUF + BBUF;            // [Ahi][Bhi]
    extern __shared__ __align__(16) char sm[];
    const uint32_t sbase = smem_u32(sm);

    const int tid = threadIdx.x;
    const int wid = tid >> 5, lane = tid & 31;
    const int wm = wid & 1, wn = wid >> 1;
    const long long bm = (long long)blockIdx.y * 64;
    const int nW = KP >> 5;

    const int arow = tid >> 2;                  // 0..63
    const int kh = (tid & 3) * 8;               // 0,8,16,24
    const long long grow = bm + arow;
    const int s = (AMODE == 1 || AMODE == 2 || AMODE == 5) ? gidx[grow] : 0;

    float acc[2][NT][4];
#pragma unroll
    for (int i = 0; i < 2; i++)
#pragma unroll
        for (int j = 0; j < NT; j++)
#pragma unroll
            for (int t = 0; t < 4; t++) acc[i][j][t] = 0.f;

    const int aRow = (lane & 7) + ((lane >> 3) & 1) * 8;
    const int aK   = (lane >> 4) * 8;
    const int bRow4 = (lane & 7) + ((lane >> 4) << 3);
    const int bK4   = ((lane >> 3) & 1) * 8;

    auto loadB = [&](int w, int buf) {
        const uint32_t bhi = sbase + buf * STG + ABUF;
        for (int idx = tid; idx < BN * 4; idx += 256) {
            int row = idx >> 2, sg = idx & 3;
            cpa16(bhi + row * RS + sg * 16,
                  Bt + (size_t)row * KP + w * 32 + sg * 8);
        }
    };

    // prologue: window 0
    {
        float va[8];
        loadA8<AMODE>(A1, A2v, grow, s, kh, KP, va);
        storeA8(sbase + arow * RS + kh * 2, va);
        loadB(0, 0);
        cp_commit();
    }

    for (int w = 0; w < nW; ++w) {
        const int buf = w & 1;
        const bool more = (w + 1 < nW);
        float va[8];
        if (more) {
            loadA8<AMODE>(A1, A2v, grow, s, (w + 1) * 32 + kh, KP, va);
            loadB(w + 1, buf ^ 1);
            cp_commit();
        }
        if (more) cp_wait<1>(); else cp_wait<0>();
        __syncthreads();
        const uint32_t as = sbase + buf * STG;
        const uint32_t bs = as + ABUF;
#pragma unroll
        for (int ks = 0; ks < 32; ks += 16) {
            uint32_t afh[2][4];
#pragma unroll
            for (int mt = 0; mt < 2; ++mt) {
                uint32_t ar = as + (wm * 32 + mt * 16 + aRow) * RS + (ks + aK) * 2;
                ldsm4(afh[mt], ar);
            }
#pragma unroll
            for (int ntp = 0; ntp < NT / 2; ++ntp) {
                uint32_t bh4[4];
                uint32_t br = bs + (wn * NT * 8 + ntp * 16 + bRow4) * RS + (ks + bK4) * 2;
                ldsm4(bh4, br);
#pragma unroll
                for (int mt = 0; mt < 2; ++mt)
#pragma unroll
                    for (int h = 0; h < 2; ++h)
                        mma16816(acc[mt][ntp*2 + h], afh[mt], bh4 + h*2);
            }
        }
        if (more) {
            storeA8(sbase + (buf ^ 1) * STG + arow * RS + kh * 2, va);
        }
        __syncthreads();
    }

    // ---- epilogue ----
    const __half* auxh = (const __half*)auxv;
    const float*  auxf = (const float*)auxv;
    __half* Ch = (__half*)Cv;
    float*  Cf = (float*)Cv;
    const int gid = lane >> 2, tig = lane & 3;
#pragma unroll
    for (int mt = 0; mt < 2; ++mt) {
        const long long r0 = bm + wm * 32 + mt * 16 + gid;
        const long long r1 = r0 + 8;
        int si0 = 0, si1 = 0;
        float inv0 = 1.f, inv1 = 1.f;
        if (EPI >= 2) { si0 = sidx[r0]; si1 = sidx[r1]; }
        if (EPI == 5) {
            inv0 = 1.f / fmaxf(C2[si0], 1.f);
            inv1 = 1.f / fmaxf(C2[si1], 1.f);
        }
#pragma unroll
        for (int nt = 0; nt < NT; ++nt) {
            const int c0 = wn * NT * 8 + nt * 8 + tig * 2;
            float v00 = acc[mt][nt][0], v01 = acc[mt][nt][1];
            float v10 = acc[mt][nt][2], v11 = acc[mt][nt][3];
            float r00, r01, r10, r11;
            if (EPI == 0 || EPI == 1 || EPI == 5) {
                float2 ax = *(const float2*)(auxf + c0);
                r00 = v00 + ax.x; r01 = v01 + ax.y;
                r10 = v10 + ax.x; r11 = v11 + ax.y;
            } else if (EPI == 2 || EPI == 4) {
                float2 a0 = __half22float2(*(const __half2*)(auxh + r0 * N + c0));
                float2 a1 = __half22float2(*(const __half2*)(auxh + r1 * N + c0));
                r00 = v00 + a0.x; r01 = v01 + a0.y;
                r10 = v10 + a1.x; r11 = v11 + a1.y;
            } else { // EPI==3
                r00 = v00; r01 = v01; r10 = v10; r11 = v11;
            }
            if (EPI != 0) {
                r00 = fmaxf(r00, 0.f); r01 = fmaxf(r01, 0.f);
                r10 = fmaxf(r10, 0.f); r11 = fmaxf(r11, 0.f);
            }
            if (EPI == 5) {
                r00 *= inv0; r01 *= inv0; r10 *= inv1; r11 *= inv1;
            }
            if (EPI == 0 || EPI == 1) {
                *(float2*)(Cf + r0 * N + c0) = make_float2(r00, r01);
                *(float2*)(Cf + r1 * N + c0) = make_float2(r10, r11);
            } else if (EPI == 2) {
                *(__half2*)(Ch + r0 * N + c0) = __floats2half2_rn(r00, r01);
                *(__half2*)(Ch + r1 * N + c0) = __floats2half2_rn(r10, r11);
            } else if (EPI == 3) {
                *(__half2*)(Ch + r0 * N + c0) = __floats2half2_rn(v00, v01);
                *(__half2*)(Ch + r1 * N + c0) = __floats2half2_rn(v10, v11);
            }
            if (EPI >= 2) {
                float* s0 = S + (size_t)si0 * DHP + c0;
                float* s1 = S + (size_t)si1 * DHP + c0;
                if (r00 != 0.f || r01 != 0.f) red2(s0, r00, r01);
                if (r10 != 0.f || r11 != 0.f) red2(s1, r10, r11);
            }
        }
    }
}

// ---------------- launcher ----------------
extern "C" void kernel_launch(void* const* d_in, const int* in_sizes, int n_in,
                              void* d_out, int out_size) {
    const float* V    = (const float*)d_in[0];
    const float* E    = (const float*)d_in[1];
    const int*   esrc = (const int*)d_in[2];
    const int*   edst = (const int*)d_in[3];
    const int*   batc = (const int*)d_in[5];
    int wi = 6;
    if (n_in >= 15 && in_sizes[6] == 1) wi = 7;
    const float* W_i = (const float*)d_in[wi + 0];
    const float* W_h = (const float*)d_in[wi + 1];
    const float* W_o = (const float*)d_in[wi + 2];
    const float* b_o = (const float*)d_in[wi + 3];
    const float* W1  = (const float*)d_in[wi + 4];
    const float* b1  = (const float*)d_in[wi + 5];
    const float* W2  = (const float*)d_in[wi + 6];
    const float* b2  = (const float*)d_in[wi + 7];
    float* out = (float*)d_out;

    float *Mv1, *Mv2, *Z, *cnt, *T, *bo;
    __half *H0, *Hb, *Bh0, *Bh, *Bo, *B1, *B2;
    cudaGetSymbolAddress((void**)&H0,  g_H0);
    cudaGetSymbolAddress((void**)&Hb,  g_Hb);
    cudaGetSymbolAddress((void**)&Mv1, g_Mv1);
    cudaGetSymbolAddress((void**)&Mv2, g_Mv2);
    cudaGetSymbolAddress((void**)&Z,   g_Z);
    cudaGetSymbolAddress((void**)&cnt, g_cnt);
    cudaGetSymbolAddress((void**)&T,   g_T);
    cudaGetSymbolAddress((void**)&bo,  g_bo);
    cudaGetSymbolAddress((void**)&Bh0, g_Bh0);
    cudaGetSymbolAddress((void**)&Bh,  g_Bh);
    cudaGetSymbolAddress((void**)&Bo,  g_Bo);
    cudaGetSymbolAddress((void**)&B1,  g_B1);
    cudaGetSymbolAddress((void**)&B2,  g_B2);

    const int SMF320 = 2 * (64 * 80 + 320 * 80);  // 61440
    const int SMF256 = 2 * (64 * 80 + 256 * 80);  // 51200
    cudaFuncSetAttribute(gemm_f<1,3,320>, cudaFuncAttributeMaxDynamicSharedMemorySize, SMF320);
    cudaFuncSetAttribute(gemm_f<5,2,320>, cudaFuncAttributeMaxDynamicSharedMemorySize, SMF320);
    cudaFuncSetAttribute(gemm_f<2,4,320>, cudaFuncAttributeMaxDynamicSharedMemorySize, SMF320);
    cudaFuncSetAttribute(gemm_f<3,5,320>, cudaFuncAttributeMaxDynamicSharedMemorySize, SMF320);
    cudaFuncSetAttribute(gemm_f<0,1,256>, cudaFuncAttributeMaxDynamicSharedMemorySize, SMF256);
    cudaFuncSetAttribute(gemm_f<0,0,256>, cudaFuncAttributeMaxDynamicSharedMemorySize, SMF256);

    // weight prep (transpose + fp16)
    prep_bt_k<<<(320 * 96  + 255) / 256, 256>>>(W_i, Bh0, 86,  300, 96,  320);
    prep_bt_k<<<(320 * 320 + 255) / 256, 256>>>(W_h, Bh,  300, 300, 320, 320);
    prep_bt_k<<<(320 * 384 + 255) / 256, 256>>>(W_o, Bo,  372, 300, 384, 320);
    prep_bt_k<<<(256 * 320 + 255) / 256, 256>>>(W1,  B1,  300, 256, 320, 256);
    prep_bt_k<<<(256 * 256 + 255) / 256, 256>>>(W2,  B2,  256, 256, 256, 256);
    pad_k<<<2, 256>>>(b_o, bo, 300, DHP);

    const size_t MVB = (size_t)NAT * DHP * sizeof(float);
    cudaMemsetAsync(cnt, 0, (size_t)NMO * sizeof(float));
    count_k<<<(NAT + 255) / 256, 256>>>(batc, cnt);
    cudaMemsetAsync(Mv1, 0, MVB);
    cudaMemsetAsync(Mv2, 0, MVB);
    cudaMemsetAsync(Z, 0, (size_t)NMO * DHP * sizeof(float));

    // 1. H0(f16) = concat(V[src],E)@W_i (pre-relu) ; scatter relu -> Mv1
    gemm_f<1,3,320><<<dim3(1, NBO / 64), 256, SMF320>>>(
        V, E, esrc, Bh0, 96, nullptr, edst, Mv1, H0, nullptr, DHP);

    // 2. iter1: Hb(f16) = relu(H0 + (Mv1[src]-relu(H0)[rev])@Wh) ; scatter -> Mv2
    gemm_f<5,2,320><<<dim3(1, NBO / 64), 256, SMF320>>>(
        Mv1, H0, esrc, Bh, 320, H0, edst, Mv2, Hb, nullptr, DHP);

    // 3. iter2: relu(H0 + (Mv2[src]-Hb[rev])@Wh) scattered -> Mv1 (no store)
    cudaMemsetAsync(Mv1, 0, MVB);
    gemm_f<2,4,320><<<dim3(1, NBO / 64), 256, SMF320>>>(
        Mv2, Hb, esrc, Bh, 320, H0, edst, Mv1, nullptr, nullptr, DHP);

    // 4. relu(concat(V,Mv1)@Wo + bo) / cnt pooled -> Z (mean fused)
    gemm_f<3,5,320><<<dim3(1, NAT / 64), 256, SMF320>>>(
        V, Mv1, nullptr, Bo, 384, bo, batc, Z, nullptr, cnt, DHP);

    // 5. T = relu(Z@W1+b1)
    gemm_f<0,1,256><<<dim3(1, NMO / 64), 256, SMF256>>>(
        Z, nullptr, nullptr, B1, 320, b1, nullptr, nullptr, T, nullptr, DEM);

    // 6. out = T@W2+b2
    gemm_f<0,0,256><<<dim3(1, NMO / 64), 256, SMF256>>>(
        T, nullptr, nullptr, B2, 256, b2, nullptr, nullptr, out, nullptr, DEM);
}

// round 14
// speedup vs baseline: 7.6673x; 1.1206x over previous
#include <cuda_runtime.h>
#include <cuda_fp16.h>
#include <cstdint>
#include <cstddef>

#define NAT 131072
#define NBO 262144
#define NMO 4096
#define DHP 320
#define DEM 256

// ---------------- scratch (device globals; no allocation) ----------------
__device__ __align__(16) __half g_H0[(size_t)NBO * DHP];
__device__ __align__(16) __half g_Hb[(size_t)NBO * DHP];
__device__ __align__(16) __half g_Mv1[(size_t)NAT * DHP];
__device__ __align__(16) __half g_Mv2[(size_t)NAT * DHP];
__device__ float g_Z [(size_t)NMO * DHP];
__device__ float g_cnt[NMO];
__device__ float g_T [(size_t)NMO * DEM];
__device__ float g_bo[DHP];
__device__ __align__(16) __half g_Bh0[320 * 96];
__device__ __align__(16) __half g_Bh [320 * 320];
__device__ __align__(16) __half g_Bo [320 * 384];
__device__ __align__(16) __half g_B1 [256 * 320];
__device__ __align__(16) __half g_B2 [256 * 256];

// ---------------- PTX helpers ----------------
__device__ __forceinline__ uint32_t smem_u32(const void* p) {
    uint32_t a;
    asm("{ .reg .u64 t; cvta.to.shared.u64 t, %1; cvt.u32.u64 %0, t; }"
        : "=r"(a) : "l"(p));
    return a;
}
__device__ __forceinline__ void cpa16(uint32_t dst, const void* src) {
    asm volatile("cp.async.cg.shared.global [%0], [%1], 16;"
                 :: "r"(dst), "l"(src) : "memory");
}
__device__ __forceinline__ void cp_commit() {
    asm volatile("cp.async.commit_group;" ::: "memory");
}
template<int N>
__device__ __forceinline__ void cp_wait() {
    asm volatile("cp.async.wait_group %0;" :: "n"(N) : "memory");
}
__device__ __forceinline__ void ldsm4(uint32_t* r, uint32_t a) {
    asm volatile("ldmatrix.sync.aligned.m8n8.x4.shared.b16 {%0,%1,%2,%3}, [%4];"
                 : "=r"(r[0]), "=r"(r[1]), "=r"(r[2]), "=r"(r[3]) : "r"(a));
}
__device__ __forceinline__ void mma16816(float* c, const uint32_t* a, const uint32_t* b) {
    asm volatile(
        "mma.sync.aligned.m16n8k16.row.col.f32.f16.f16.f32 "
        "{%0,%1,%2,%3}, {%4,%5,%6,%7}, {%8,%9}, {%0,%1,%2,%3};"
        : "+f"(c[0]), "+f"(c[1]), "+f"(c[2]), "+f"(c[3])
        : "r"(a[0]), "r"(a[1]), "r"(a[2]), "r"(a[3]), "r"(b[0]), "r"(b[1]));
}
__device__ __forceinline__ void sts16(uint32_t a, uint32_t x, uint32_t y,
                                      uint32_t z, uint32_t w) {
    asm volatile("st.shared.v4.b32 [%0], {%1,%2,%3,%4};"
                 :: "r"(a), "r"(x), "r"(y), "r"(z), "r"(w) : "memory");
}
__device__ __forceinline__ void red2f(float* addr, float x, float y) {
    asm volatile("red.global.add.v2.f32 [%0], {%1,%2};"
                 :: "l"(addr), "f"(x), "f"(y) : "memory");
}
__device__ __forceinline__ void red2h(__half* addr, float x, float y) {
    __half2 h = __floats2half2_rn(x, y);
    asm volatile("red.global.add.noftz.f16x2 [%0], %1;"
                 :: "l"(addr), "r"(*(uint32_t*)&h) : "memory");
}

// ---------------- weight prep (transpose + fp16 round) ----------------
__global__ void prep_bt_k(const float* __restrict__ W, __half* __restrict__ out,
                          int Ksrc, int Nsrc, int KP, int Nrows) {
    int idx = blockIdx.x * 256 + threadIdx.x;
    if (idx >= Nrows * KP) return;
    int n = idx / KP, k = idx - n * KP;
    float v = (k < Ksrc && n < Nsrc) ? W[(size_t)k * Nsrc + n] : 0.f;
    out[(size_t)n * KP + k] = __float2half_rn(v);
}

__global__ void pad_k(const float* __restrict__ in, float* __restrict__ out,
                      int IC, int OC) {
    int idx = blockIdx.x * blockDim.x + threadIdx.x;
    if (idx >= OC) return;
    out[idx] = (idx < IC) ? in[idx] : 0.f;
}

__global__ void count_k(const int* __restrict__ batch, float* __restrict__ cnt) {
    int a = blockIdx.x * blockDim.x + threadIdx.x;
    if (a < NAT) atomicAdd(&cnt[batch[a]], 1.f);
}

// ---------------- fused GEMM (BM=64, BN=N, fp16 1-pass, fp16 H/Mv) --------
// AMODE: 0 plain(f32) ; 1 h0 concat-gather(V,E f32) ;
//        2 message: Mv(f16)[g[r]] - H(f16)[(r^1)] ;
//        5 message+relu: Mv(f16) - relu(H(f16)[(r^1)]) ;
//        3 wo concat: V(f32) | Mv(f16)
// EPI:   0 C=acc+aux_f[c] (f32) ; 1 C=relu(acc+aux_f[c]) (f32) ;
//        2 v=relu(acc+aux_h[r*N+c]); C(f16)=v; scatter f16 ;
//        3 C(f16)=acc; scatter relu(acc) f16 ;
//        4 v=relu(acc+aux_h[r*N+c]); scatter f16 only ;
//        5 v=relu(acc+aux_f[c])/cnt[sidx[r]]; scatter f32 only (cnt via C2)
template<int AMODE>
__device__ __forceinline__ void loadA8(const void* __restrict__ A1v,
                                       const void* __restrict__ A2v,
                                       long long row, int s, int k0,
                                       int KP, float* va) {
    if (AMODE == 0) {
        const float4* p = (const float4*)((const float*)A1v + row * KP + k0);
        float4 a = p[0], b = p[1];
        va[0]=a.x; va[1]=a.y; va[2]=a.z; va[3]=a.w;
        va[4]=b.x; va[5]=b.y; va[6]=b.z; va[7]=b.w;
    } else if (AMODE == 2 || AMODE == 5) {
        const uint4 mv = *(const uint4*)((const __half*)A1v + (size_t)s * DHP + k0);
        const uint4 hv = *(const uint4*)((const __half*)A2v +
                                         (size_t)(row ^ 1) * DHP + k0);
        const __half2* mp = (const __half2*)&mv;
        const __half2* hp = (const __half2*)&hv;
#pragma unroll
        for (int i = 0; i < 4; i++) {
            float2 m = __half22float2(mp[i]);
            float2 h = __half22float2(hp[i]);
            if (AMODE == 5) { h.x = fmaxf(h.x, 0.f); h.y = fmaxf(h.y, 0.f); }
            va[2*i]   = m.x - h.x;
            va[2*i+1] = m.y - h.y;
        }
    } else if (AMODE == 1) {
        const float* A1 = (const float*)A1v;
        const float* A2 = (const float*)A2v;
#pragma unroll
        for (int j = 0; j < 8; j++) {
            int k = k0 + j;
            va[j] = (k < 72) ? A1[(size_t)s * 72 + k]
                             : (k < 86 ? A2[row * 14 + (k - 72)] : 0.f);
        }
    } else { // AMODE 3
        const float* A1 = (const float*)A1v;
        const __half* A2 = (const __half*)A2v;
#pragma unroll
        for (int j = 0; j < 8; j++) {
            int k = k0 + j;
            va[j] = (k < 72) ? A1[row * 72 + k]
                             : (k < 372 ? __half2float(A2[row * DHP + (k - 72)])
                                        : 0.f);
        }
    }
}

__device__ __forceinline__ void storeA8(uint32_t ahi, const float* va) {
    uint32_t h[4];
#pragma unroll
    for (int j = 0; j < 4; j++) {
        __half2 hp;
        hp.x = __float2half_rn(va[2*j]);
        hp.y = __float2half_rn(va[2*j+1]);
        h[j] = *(uint32_t*)&hp;
    }
    sts16(ahi, h[0], h[1], h[2], h[3]);
}

template<int AMODE, int EPI, int BN>
__global__ void __launch_bounds__(256, 2)
gemm_f(const void* __restrict__ A1v, const void* __restrict__ A2v,
       const int* __restrict__ gidx,
       const __half* __restrict__ Bt, int KP,
       const void* __restrict__ auxv,
       const int* __restrict__ sidx, void* __restrict__ Sv,
       void* __restrict__ Cv, const float* __restrict__ C2, int N) {
    constexpr int NT = BN / 32;                 // n-tiles (8 cols) per warp
    constexpr int RS = 80;
    constexpr int ABUF = 64 * RS;
    constexpr int BBUF = BN * RS;
    constexpr int STG = ABUF + BBUF;            // [Ahi][Bhi]
    extern __shared__ __align__(16) char sm[];
    const uint32_t sbase = smem_u32(sm);

    const int tid = threadIdx.x;
    const int wid = tid >> 5, lane = tid & 31;
    const int wm = wid & 1, wn = wid >> 1;
    const long long bm = (long long)blockIdx.y * 64;
    const int nW = KP >> 5;

    const int arow = tid >> 2;                  // 0..63
    const int kh = (tid & 3) * 8;               // 0,8,16,24
    const long long grow = bm + arow;
    const int s = (AMODE == 1 || AMODE == 2 || AMODE == 5) ? gidx[grow] : 0;

    float acc[2][NT][4];
#pragma unroll
    for (int i = 0; i < 2; i++)
#pragma unroll
        for (int j = 0; j < NT; j++)
#pragma unroll
            for (int t = 0; t < 4; t++) acc[i][j][t] = 0.f;

    const int aRow = (lane & 7) + ((lane >> 3) & 1) * 8;
    const int aK   = (lane >> 4) * 8;
    const int bRow4 = (lane & 7) + ((lane >> 4) << 3);
    const int bK4   = ((lane >> 3) & 1) * 8;

    auto loadB = [&](int w, int buf) {
        const uint32_t bhi = sbase + buf * STG + ABUF;
        for (int idx = tid; idx < BN * 4; idx += 256) {
            int row = idx >> 2, sg = idx & 3;
            cpa16(bhi + row * RS + sg * 16,
                  Bt + (size_t)row * KP + w * 32 + sg * 8);
        }
    };

    // prologue: window 0
    {
        float va[8];
        loadA8<AMODE>(A1v, A2v, grow, s, kh, KP, va);
        storeA8(sbase + arow * RS + kh * 2, va);
        loadB(0, 0);
        cp_commit();
    }

    for (int w = 0; w < nW; ++w) {
        const int buf = w & 1;
        const bool more = (w + 1 < nW);
        float va[8];
        if (more) {
            loadA8<AMODE>(A1v, A2v, grow, s, (w + 1) * 32 + kh, KP, va);
            loadB(w + 1, buf ^ 1);
            cp_commit();
        }
        if (more) cp_wait<1>(); else cp_wait<0>();
        __syncthreads();
        const uint32_t as = sbase + buf * STG;
        const uint32_t bs = as + ABUF;
#pragma unroll
        for (int ks = 0; ks < 32; ks += 16) {
            uint32_t afh[2][4];
#pragma unroll
            for (int mt = 0; mt < 2; ++mt) {
                uint32_t ar = as + (wm * 32 + mt * 16 + aRow) * RS + (ks + aK) * 2;
                ldsm4(afh[mt], ar);
            }
#pragma unroll
            for (int ntp = 0; ntp < NT / 2; ++ntp) {
                uint32_t bh4[4];
                uint32_t br = bs + (wn * NT * 8 + ntp * 16 + bRow4) * RS + (ks + bK4) * 2;
                ldsm4(bh4, br);
#pragma unroll
                for (int mt = 0; mt < 2; ++mt)
#pragma unroll
                    for (int h = 0; h < 2; ++h)
                        mma16816(acc[mt][ntp*2 + h], afh[mt], bh4 + h*2);
            }
        }
        if (more) {
            storeA8(sbase + (buf ^ 1) * STG + arow * RS + kh * 2, va);
        }
        __syncthreads();
    }

    // ---- epilogue ----
    const __half* auxh = (const __half*)auxv;
    const float*  auxf = (const float*)auxv;
    __half* Ch = (__half*)Cv;
    float*  Cf = (float*)Cv;
    __half* Sh = (__half*)Sv;
    float*  Sf = (float*)Sv;
    const int gid = lane >> 2, tig = lane & 3;
#pragma unroll
    for (int mt = 0; mt < 2; ++mt) {
        const long long r0 = bm + wm * 32 + mt * 16 + gid;
        const long long r1 = r0 + 8;
        int si0 = 0, si1 = 0;
        float inv0 = 1.f, inv1 = 1.f;
        if (EPI >= 2) { si0 = sidx[r0]; si1 = sidx[r1]; }
        if (EPI == 5) {
            inv0 = 1.f / fmaxf(C2[si0], 1.f);
            inv1 = 1.f / fmaxf(C2[si1], 1.f);
        }
#pragma unroll
        for (int nt = 0; nt < NT; ++nt) {
            const int c0 = wn * NT * 8 + nt * 8 + tig * 2;
            float v00 = acc[mt][nt][0], v01 = acc[mt][nt][1];
            float v10 = acc[mt][nt][2], v11 = acc[mt][nt][3];
            float r00, r01, r10, r11;
            if (EPI == 0 || EPI == 1 || EPI == 5) {
                float2 ax = *(const float2*)(auxf + c0);
                r00 = v00 + ax.x; r01 = v01 + ax.y;
                r10 = v10 + ax.x; r11 = v11 + ax.y;
            } else if (EPI == 2 || EPI == 4) {
                float2 a0 = __half22float2(*(const __half2*)(auxh + r0 * N + c0));
                float2 a1 = __half22float2(*(const __half2*)(auxh + r1 * N + c0));
                r00 = v00 + a0.x; r01 = v01 + a0.y;
                r10 = v10 + a1.x; r11 = v11 + a1.y;
            } else { // EPI==3
                r00 = v00; r01 = v01; r10 = v10; r11 = v11;
            }
            if (EPI != 0) {
                r00 = fmaxf(r00, 0.f); r01 = fmaxf(r01, 0.f);
                r10 = fmaxf(r10, 0.f); r11 = fmaxf(r11, 0.f);
            }
            if (EPI == 5) {
                r00 *= inv0; r01 *= inv0; r10 *= inv1; r11 *= inv1;
            }
            if (EPI == 0 || EPI == 1) {
                *(float2*)(Cf + r0 * N + c0) = make_float2(r00, r01);
                *(float2*)(Cf + r1 * N + c0) = make_float2(r10, r11);
            } else if (EPI == 2) {
                *(__half2*)(Ch + r0 * N + c0) = __floats2half2_rn(r00, r01);
                *(__half2*)(Ch + r1 * N + c0) = __floats2half2_rn(r10, r11);
            } else if (EPI == 3) {
                *(__half2*)(Ch + r0 * N + c0) = __floats2half2_rn(v00, v01);
                *(__half2*)(Ch + r1 * N + c0) = __floats2half2_rn(v10, v11);
            }
            if (EPI == 5) {
                float* s0 = Sf + (size_t)si0 * DHP + c0;
                float* s1 = Sf + (size_t)si1 * DHP + c0;
                if (r00 != 0.f || r01 != 0.f) red2f(s0, r00, r01);
                if (r10 != 0.f || r11 != 0.f) red2f(s1, r10, r11);
            } else if (EPI >= 2) {
                __half* s0 = Sh + (size_t)si0 * DHP + c0;
                __half* s1 = Sh + (size_t)si1 * DHP + c0;
                if (r00 != 0.f || r01 != 0.f) red2h(s0, r00, r01);
                if (r10 != 0.f || r11 != 0.f) red2h(s1, r10, r11);
            }
        }
    }
}

// ---------------- launcher ----------------
extern "C" void kernel_launch(void* const* d_in, const int* in_sizes, int n_in,
                              void* d_out, int out_size) {
    const float* V    = (const float*)d_in[0];
    const float* E    = (const float*)d_in[1];
    const int*   esrc = (const int*)d_in[2];
    const int*   edst = (const int*)d_in[3];
    const int*   batc = (const int*)d_in[5];
    int wi = 6;
    if (n_in >= 15 && in_sizes[6] == 1) wi = 7;
    const float* W_i = (const float*)d_in[wi + 0];
    const float* W_h = (const float*)d_in[wi + 1];
    const float* W_o = (const float*)d_in[wi + 2];
    const float* b_o = (const float*)d_in[wi + 3];
    const float* W1  = (const float*)d_in[wi + 4];
    const float* b1  = (const float*)d_in[wi + 5];
    const float* W2  = (const float*)d_in[wi + 6];
    const float* b2  = (const float*)d_in[wi + 7];
    float* out = (float*)d_out;

    float *Z, *cnt, *T, *bo;
    __half *H0, *Hb, *Mv1, *Mv2, *Bh0, *Bh, *Bo, *B1, *B2;
    cudaGetSymbolAddress((void**)&H0,  g_H0);
    cudaGetSymbolAddress((void**)&Hb,  g_Hb);
    cudaGetSymbolAddress((void**)&Mv1, g_Mv1);
    cudaGetSymbolAddress((void**)&Mv2, g_Mv2);
    cudaGetSymbolAddress((void**)&Z,   g_Z);
    cudaGetSymbolAddress((void**)&cnt, g_cnt);
    cudaGetSymbolAddress((void**)&T,   g_T);
    cudaGetSymbolAddress((void**)&bo,  g_bo);
    cudaGetSymbolAddress((void**)&Bh0, g_Bh0);
    cudaGetSymbolAddress((void**)&Bh,  g_Bh);
    cudaGetSymbolAddress((void**)&Bo,  g_Bo);
    cudaGetSymbolAddress((void**)&B1,  g_B1);
    cudaGetSymbolAddress((void**)&B2,  g_B2);

    const int SMF320 = 2 * (64 * 80 + 320 * 80);  // 61440
    const int SMF256 = 2 * (64 * 80 + 256 * 80);  // 51200
    cudaFuncSetAttribute(gemm_f<1,3,320>, cudaFuncAttributeMaxDynamicSharedMemorySize, SMF320);
    cudaFuncSetAttribute(gemm_f<5,2,320>, cudaFuncAttributeMaxDynamicSharedMemorySize, SMF320);
    cudaFuncSetAttribute(gemm_f<2,4,320>, cudaFuncAttributeMaxDynamicSharedMemorySize, SMF320);
    cudaFuncSetAttribute(gemm_f<3,5,320>, cudaFuncAttributeMaxDynamicSharedMemorySize, SMF320);
    cudaFuncSetAttribute(gemm_f<0,1,256>, cudaFuncAttributeMaxDynamicSharedMemorySize, SMF256);
    cudaFuncSetAttribute(gemm_f<0,0,256>, cudaFuncAttributeMaxDynamicSharedMemorySize, SMF256);

    // weight prep (transpose + fp16)
    prep_bt_k<<<(320 * 96  + 255) / 256, 256>>>(W_i, Bh0, 86,  300, 96,  320);
    prep_bt_k<<<(320 * 320 + 255) / 256, 256>>>(W_h, Bh,  300, 300, 320, 320);
    prep_bt_k<<<(320 * 384 + 255) / 256, 256>>>(W_o, Bo,  372, 300, 384, 320);
    prep_bt_k<<<(256 * 320 + 255) / 256, 256>>>(W1,  B1,  300, 256, 320, 256);
    prep_bt_k<<<(256 * 256 + 255) / 256, 256>>>(W2,  B2,  256, 256, 256, 256);
    pad_k<<<2, 256>>>(b_o, bo, 300, DHP);

    const size_t MVB = (size_t)NAT * DHP * sizeof(__half);
    cudaMemsetAsync(cnt, 0, (size_t)NMO * sizeof(float));
    count_k<<<(NAT + 255) / 256, 256>>>(batc, cnt);
    cudaMemsetAsync(Mv1, 0, MVB);
    cudaMemsetAsync(Mv2, 0, MVB);
    cudaMemsetAsync(Z, 0, (size_t)NMO * DHP * sizeof(float));

    // 1. H0(f16) = concat(V[src],E)@W_i (pre-relu) ; scatter relu -> Mv1(f16)
    gemm_f<1,3,320><<<dim3(1, NBO / 64), 256, SMF320>>>(
        V, E, esrc, Bh0, 96, nullptr, edst, Mv1, H0, nullptr, DHP);

    // 2. iter1: Hb(f16) = relu(H0 + (Mv1[src]-relu(H0)[rev])@Wh) ; scatter -> Mv2
    gemm_f<5,2,320><<<dim3(1, NBO / 64), 256, SMF320>>>(
        Mv1, H0, esrc, Bh, 320, H0, edst, Mv2, Hb, nullptr, DHP);

    // 3. iter2: relu(H0 + (Mv2[src]-Hb[rev])@Wh) scattered -> Mv1 (no store)
    cudaMemsetAsync(Mv1, 0, MVB);
    gemm_f<2,4,320><<<dim3(1, NBO / 64), 256, SMF320>>>(
        Mv2, Hb, esrc, Bh, 320, H0, edst, Mv1, nullptr, nullptr, DHP);

    // 4. relu(concat(V,Mv1)@Wo + bo) / cnt pooled -> Z(f32) (mean fused)
    gemm_f<3,5,320><<<dim3(1, NAT / 64), 256, SMF320>>>(
        V, Mv1, nullptr, Bo, 384, bo, batc, Z, nullptr, cnt, DHP);

    // 5. T = relu(Z@W1+b1)
    gemm_f<0,1,256><<<dim3(1, NMO / 64), 256, SMF256>>>(
        Z, nullptr, nullptr, B1, 320, b1, nullptr, nullptr, T, nullptr, DEM);

    // 6. out = T@W2+b2
    gemm_f<0,0,256><<<dim3(1, NMO / 64), 256, SMF256>>>(
        T, nullptr, nullptr, B2, 256, b2, nullptr, nullptr, out, nullptr, DEM);
}